// round 1
// baseline (speedup 1.0000x reference)
#include <cuda_runtime.h>
#include <cuda_bf16.h>
#include <math.h>

// ---------------------------------------------------------------------------
// EncoderBlock: B=8, N=1024, D=768, H=8, DH=96
//   x -> LN1 -> qkv GEMM -> attention (flash-style) -> o-proj + bias + resid
//     -> LN2 -> ffn1 (+bias, gelu) -> ffn2 (+bias, gelu, +resid) -> LN3 -> out
// "Faithful reshape": attention output stored contiguously as (B,H,N,DH),
// then reinterpreted flat as (B,N,D) for the o-projection.
// ---------------------------------------------------------------------------

#define TOKENS 8192      // B*N
#define DMODEL 768
#define NSEQ   1024
#define NHEAD  8
#define DHEAD  96

// Scratch buffers (static device allocations are allowed)
__device__ float g_ln [TOKENS * DMODEL];
__device__ float g_qkv[TOKENS * 3 * DMODEL];
__device__ float g_att[TOKENS * DMODEL];
__device__ float g_x1 [TOKENS * DMODEL];
__device__ float g_ffn[TOKENS * 4 * DMODEL];
__device__ float g_x2 [TOKENS * DMODEL];

__device__ __forceinline__ float gelu_f(float x) {
    // exact GELU (approximate=False): 0.5*x*(1+erf(x/sqrt(2)))
    return 0.5f * x * (1.0f + erff(x * 0.70710678118654752f));
}

// ---------------------------------------------------------------------------
// LayerNorm: one block per row of 768
// ---------------------------------------------------------------------------
__global__ __launch_bounds__(256) void ln_kernel(
    const float* __restrict__ x, const float* __restrict__ g,
    const float* __restrict__ b, float* __restrict__ o)
{
    __shared__ float red[32];
    const int t = threadIdx.x;
    const float* xr = x + (size_t)blockIdx.x * DMODEL;

    float v0 = xr[t], v1 = xr[t + 256], v2 = xr[t + 512];
    float s  = v0 + v1 + v2;
    float ss = v0 * v0 + v1 * v1 + v2 * v2;
    #pragma unroll
    for (int o2 = 16; o2 > 0; o2 >>= 1) {
        s  += __shfl_xor_sync(0xffffffffu, s,  o2);
        ss += __shfl_xor_sync(0xffffffffu, ss, o2);
    }
    const int w = t >> 5;
    if ((t & 31) == 0) { red[w] = s; red[16 + w] = ss; }
    __syncthreads();
    if (t == 0) {
        float S = 0.f, SS = 0.f;
        #pragma unroll
        for (int i = 0; i < 8; i++) { S += red[i]; SS += red[16 + i]; }
        red[0] = S; red[16] = SS;
    }
    __syncthreads();
    const float mean = red[0] * (1.0f / DMODEL);
    const float var  = red[16] * (1.0f / DMODEL) - mean * mean;
    const float inv  = rsqrtf(var + 1e-5f);

    float* orow = o + (size_t)blockIdx.x * DMODEL;
    orow[t]       = (v0 - mean) * inv * g[t]       + b[t];
    orow[t + 256] = (v1 - mean) * inv * g[t + 256] + b[t + 256];
    orow[t + 512] = (v2 - mean) * inv * g[t + 512] + b[t + 512];
}

// ---------------------------------------------------------------------------
// SGEMM: C(MxN) = A(MxK) @ B(KxN) + epilogue
// 128x128 tile, BK=8, 256 threads, 8x8 microtile (split 4+4 for float4 frags)
// MODE 0: C = AB
// MODE 1: C = AB + bias + res
// MODE 2: C = gelu(AB + bias)
// MODE 3: C = gelu(AB + bias) + res
// All dims assumed divisible by 128 (N) / 128 (M) / 8 (K). True here.
// ---------------------------------------------------------------------------
template <int MODE>
__global__ __launch_bounds__(256) void sgemm_kernel(
    const float* __restrict__ A, const float* __restrict__ B,
    float* __restrict__ C, int M, int N, int K,
    const float* __restrict__ bias, const float* __restrict__ res)
{
    __shared__ float As[8][132];   // transposed A tile, padded vs bank conflicts
    __shared__ float Bs[8][128];

    const int tid = threadIdx.x;
    const int tx = tid & 15, ty = tid >> 4;
    const int bm = blockIdx.y, bn = blockIdx.x;

    const float* Ab = A + (size_t)bm * 128 * K;
    const float* Bb = B + (size_t)bn * 128;

    const int arow = tid >> 1, ac4 = (tid & 1) * 4;
    const int brow = tid >> 5, bc4 = (tid & 31) * 4;

    float acc[8][8];
    #pragma unroll
    for (int i = 0; i < 8; i++)
        #pragma unroll
        for (int j = 0; j < 8; j++) acc[i][j] = 0.f;

    for (int k0 = 0; k0 < K; k0 += 8) {
        float4 a = *(const float4*)&Ab[(size_t)arow * K + k0 + ac4];
        As[ac4 + 0][arow] = a.x;
        As[ac4 + 1][arow] = a.y;
        As[ac4 + 2][arow] = a.z;
        As[ac4 + 3][arow] = a.w;
        *(float4*)&Bs[brow][bc4] =
            *(const float4*)&Bb[(size_t)(k0 + brow) * N + bc4];
        __syncthreads();

        #pragma unroll
        for (int kk = 0; kk < 8; kk++) {
            float4 a0 = *(const float4*)&As[kk][ty * 4];
            float4 a1 = *(const float4*)&As[kk][64 + ty * 4];
            float4 b0 = *(const float4*)&Bs[kk][tx * 4];
            float4 b1 = *(const float4*)&Bs[kk][64 + tx * 4];
            float ar[8] = {a0.x, a0.y, a0.z, a0.w, a1.x, a1.y, a1.z, a1.w};
            float br[8] = {b0.x, b0.y, b0.z, b0.w, b1.x, b1.y, b1.z, b1.w};
            #pragma unroll
            for (int i = 0; i < 8; i++)
                #pragma unroll
                for (int j = 0; j < 8; j++)
                    acc[i][j] = fmaf(ar[i], br[j], acc[i][j]);
        }
        __syncthreads();
    }

    #pragma unroll
    for (int i = 0; i < 8; i++) {
        const int row = bm * 128 + ((i < 4) ? (ty * 4 + i) : (64 + ty * 4 + i - 4));
        const size_t rbase = (size_t)row * N;
        #pragma unroll
        for (int jh = 0; jh < 2; jh++) {
            const int col = bn * 128 + jh * 64 + tx * 4;
            float v[4] = {acc[i][jh * 4 + 0], acc[i][jh * 4 + 1],
                          acc[i][jh * 4 + 2], acc[i][jh * 4 + 3]};
            if (MODE >= 1) {
                const float4 bb = *(const float4*)&bias[col];
                v[0] += bb.x; v[1] += bb.y; v[2] += bb.z; v[3] += bb.w;
            }
            if (MODE >= 2) {
                v[0] = gelu_f(v[0]); v[1] = gelu_f(v[1]);
                v[2] = gelu_f(v[2]); v[3] = gelu_f(v[3]);
            }
            if (MODE == 1 || MODE == 3) {
                const float4 rr = *(const float4*)&res[rbase + col];
                v[0] += rr.x; v[1] += rr.y; v[2] += rr.z; v[3] += rr.w;
            }
            float4 ov; ov.x = v[0]; ov.y = v[1]; ov.z = v[2]; ov.w = v[3];
            *(float4*)&C[rbase + col] = ov;
        }
    }
}

// ---------------------------------------------------------------------------
// Attention: flash-style. grid = (16 q-tiles, 64 bh). 256 threads.
// Tile: 64 queries x 64 keys, DH=96 fp32.
// Phase A (quad mapping, thread owns 1 q-row, 16 keys): S = QK^T, online
//   softmax, P written to smem.
// Phase B (gemm mapping, thread owns 4 rows x 6 cols): O += P @ V.
// Output written contiguously as (B,H,N,DH)  == faithful reshape (B,N,D).
// ---------------------------------------------------------------------------
#define ATTN_QPAD 100           // 96 cols padded to mult-of-4, !=0 mod 32
#define ATTN_PPAD 68
#define ATTN_SMEM_FLOATS (3 * 64 * ATTN_QPAD + 64 * ATTN_PPAD + 64)
#define ATTN_SMEM_BYTES  (ATTN_SMEM_FLOATS * 4)

__global__ __launch_bounds__(256) void attn_kernel(
    const float* __restrict__ qkv, float* __restrict__ out)
{
    extern __shared__ float sm[];
    float* sQ = sm;                     // [64][100]
    float* sK = sQ + 64 * ATTN_QPAD;    // [64][100]
    float* sV = sK + 64 * ATTN_QPAD;    // [64][100]
    float* sP = sV + 64 * ATTN_QPAD;    // [64][68]
    float* sC = sP + 64 * ATTN_PPAD;    // [64] corr / inv-l

    const int tid = threadIdx.x;
    const int bh = blockIdx.y;                  // 0..63
    const int b  = bh >> 3, h = bh & 7;
    const int q0 = blockIdx.x << 6;

    const float* gQ = qkv + (size_t)b * NSEQ * (3 * DMODEL) + h * DHEAD;
    const float* gK = gQ + DMODEL;
    const float* gV = gQ + 2 * DMODEL;

    // load Q tile (64 x 96) as float4
    for (int idx = tid; idx < 64 * 24; idx += 256) {
        const int r = idx / 24, c = (idx % 24) * 4;
        *(float4*)&sQ[r * ATTN_QPAD + c] =
            *(const float4*)&gQ[(size_t)(q0 + r) * (3 * DMODEL) + c];
    }

    const int qr = tid >> 2, l4 = tid & 3;      // phase-A mapping
    const int rg = tid >> 4, cg = tid & 15;     // phase-B mapping: rows rg*4.., cols cg*6..

    const float scale = 0.10206207261596578f;   // 1/sqrt(96)

    float m = -1e30f, l = 0.f;
    float acc[4][6];
    #pragma unroll
    for (int i = 0; i < 4; i++)
        #pragma unroll
        for (int j = 0; j < 6; j++) acc[i][j] = 0.f;

    for (int kt = 0; kt < NSEQ; kt += 64) {
        __syncthreads();   // protect sK/sV/sP from prior-tile readers (and sQ fill)
        for (int idx = tid; idx < 64 * 24; idx += 256) {
            const int r = idx / 24, c = (idx % 24) * 4;
            *(float4*)&sK[r * ATTN_QPAD + c] =
                *(const float4*)&gK[(size_t)(kt + r) * (3 * DMODEL) + c];
            *(float4*)&sV[r * ATTN_QPAD + c] =
                *(const float4*)&gV[(size_t)(kt + r) * (3 * DMODEL) + c];
        }
        __syncthreads();

        // ---- Phase A: S = q . k, online softmax ----
        float s[16];
        #pragma unroll
        for (int jj = 0; jj < 16; jj++) s[jj] = 0.f;
        for (int d4 = 0; d4 < 24; d4++) {
            const float4 q4 = *(const float4*)&sQ[qr * ATTN_QPAD + d4 * 4];
            #pragma unroll
            for (int jj = 0; jj < 16; jj++) {
                const float4 k4 =
                    *(const float4*)&sK[(l4 + jj * 4) * ATTN_QPAD + d4 * 4];
                s[jj] += q4.x * k4.x + q4.y * k4.y + q4.z * k4.z + q4.w * k4.w;
            }
        }
        #pragma unroll
        for (int jj = 0; jj < 16; jj++) s[jj] *= scale;

        float tmax = s[0];
        #pragma unroll
        for (int jj = 1; jj < 16; jj++) tmax = fmaxf(tmax, s[jj]);
        tmax = fmaxf(tmax, __shfl_xor_sync(0xffffffffu, tmax, 1));
        tmax = fmaxf(tmax, __shfl_xor_sync(0xffffffffu, tmax, 2));

        const float mnew = fmaxf(m, tmax);
        const float corr = __expf(m - mnew);
        float psum = 0.f;
        #pragma unroll
        for (int jj = 0; jj < 16; jj++) {
            const float p = __expf(s[jj] - mnew);
            psum += p;
            sP[qr * ATTN_PPAD + l4 + jj * 4] = p;
        }
        psum += __shfl_xor_sync(0xffffffffu, psum, 1);
        psum += __shfl_xor_sync(0xffffffffu, psum, 2);
        l = l * corr + psum;
        m = mnew;
        if (l4 == 0) sC[qr] = corr;
        __syncthreads();

        // ---- Phase B: O = O*corr + P @ V ----
        #pragma unroll
        for (int i = 0; i < 4; i++) {
            const float cr = sC[rg * 4 + i];
            #pragma unroll
            for (int j = 0; j < 6; j++) acc[i][j] *= cr;
        }
        for (int j = 0; j < 64; j++) {
            const float p0 = sP[(rg * 4 + 0) * ATTN_PPAD + j];
            const float p1 = sP[(rg * 4 + 1) * ATTN_PPAD + j];
            const float p2 = sP[(rg * 4 + 2) * ATTN_PPAD + j];
            const float p3 = sP[(rg * 4 + 3) * ATTN_PPAD + j];
            #pragma unroll
            for (int c = 0; c < 6; c++) {
                const float vv = sV[j * ATTN_QPAD + cg * 6 + c];
                acc[0][c] = fmaf(p0, vv, acc[0][c]);
                acc[1][c] = fmaf(p1, vv, acc[1][c]);
                acc[2][c] = fmaf(p2, vv, acc[2][c]);
                acc[3][c] = fmaf(p3, vv, acc[3][c]);
            }
        }
    }

    __syncthreads();
    if (l4 == 0) sC[qr] = 1.0f / l;
    __syncthreads();

    float* gO = out + (size_t)bh * NSEQ * DHEAD + (size_t)q0 * DHEAD;
    #pragma unroll
    for (int i = 0; i < 4; i++) {
        const int r = rg * 4 + i;
        const float inv = sC[r];
        #pragma unroll
        for (int c = 0; c < 6; c++)
            gO[(size_t)r * DHEAD + cg * 6 + c] = acc[i][c] * inv;
    }
}

// ---------------------------------------------------------------------------
// Launcher
// ---------------------------------------------------------------------------
extern "C" void kernel_launch(void* const* d_in, const int* in_sizes, int n_in,
                              void* d_out, int out_size)
{
    (void)in_sizes; (void)n_in; (void)out_size;
    const float* x     = (const float*)d_in[0];
    const float* w_qkv = (const float*)d_in[1];
    const float* w_o   = (const float*)d_in[2];
    const float* b_o   = (const float*)d_in[3];
    const float* w1    = (const float*)d_in[4];
    const float* b1    = (const float*)d_in[5];
    const float* w2    = (const float*)d_in[6];
    const float* b2    = (const float*)d_in[7];
    const float* g1    = (const float*)d_in[8];
    const float* be1   = (const float*)d_in[9];
    const float* gm    = (const float*)d_in[10];
    const float* bm    = (const float*)d_in[11];
    const float* g3    = (const float*)d_in[12];
    const float* be3   = (const float*)d_in[13];

    float *ln, *qkv, *att, *x1, *ffn, *x2;
    cudaGetSymbolAddress((void**)&ln,  g_ln);
    cudaGetSymbolAddress((void**)&qkv, g_qkv);
    cudaGetSymbolAddress((void**)&att, g_att);
    cudaGetSymbolAddress((void**)&x1,  g_x1);
    cudaGetSymbolAddress((void**)&ffn, g_ffn);
    cudaGetSymbolAddress((void**)&x2,  g_x2);

    cudaFuncSetAttribute(attn_kernel,
                         cudaFuncAttributeMaxDynamicSharedMemorySize,
                         ATTN_SMEM_BYTES);

    // 1. h = LN1(x)
    ln_kernel<<<TOKENS, 256>>>(x, g1, be1, ln);
    // 2. qkv = h @ w_qkv                       (8192 x 2304, K=768)
    sgemm_kernel<0><<<dim3(2304 / 128, TOKENS / 128), 256>>>(
        ln, w_qkv, qkv, TOKENS, 2304, 768, nullptr, nullptr);
    // 3. attention -> (B,H,N,DH) contiguous == (B,N,D) flat
    attn_kernel<<<dim3(NSEQ / 64, 64), 256, ATTN_SMEM_BYTES>>>(qkv, att);
    // 4. x1 = att @ w_o + b_o + x              (8192 x 768, K=768)
    sgemm_kernel<1><<<dim3(768 / 128, TOKENS / 128), 256>>>(
        att, w_o, x1, TOKENS, 768, 768, b_o, x);
    // 5. h = LN2(x1)
    ln_kernel<<<TOKENS, 256>>>(x1, gm, bm, ln);
    // 6. ffn = gelu(h @ w1 + b1)               (8192 x 3072, K=768)
    sgemm_kernel<2><<<dim3(3072 / 128, TOKENS / 128), 256>>>(
        ln, w1, ffn, TOKENS, 3072, 768, b1, nullptr);
    // 7. x2 = gelu(ffn @ w2 + b2) + x1         (8192 x 768, K=3072)
    sgemm_kernel<3><<<dim3(768 / 128, TOKENS / 128), 256>>>(
        ffn, w2, x2, TOKENS, 768, 3072, b2, x1);
    // 8. out = LN3(x2)
    ln_kernel<<<TOKENS, 256>>>(x2, g3, be3, (float*)d_out);
}

// round 3
// speedup vs baseline: 1.9679x; 1.9679x over previous
#include <cuda_runtime.h>
#include <cuda_bf16.h>
#include <math.h>
#include <stdint.h>

// ---------------------------------------------------------------------------
// EncoderBlock: B=8, N=1024, D=768, H=8, DH=96
// Round 3: GEMMs on mma.sync m16n8k8 tf32 (sm_80+ path; tcgen05 unavailable
// because the harness compiles via compute_103 PTX, not 103a).
// LN + attention unchanged from the passing R1 kernel.
// ---------------------------------------------------------------------------

#define TOKENS 8192
#define DMODEL 768
#define NSEQ   1024
#define NHEAD  8
#define DHEAD  96

// ---------------- scratch ---------------------------------------------------
__device__ float g_ln  [TOKENS * DMODEL];
__device__ float g_qkv [TOKENS * 3 * DMODEL];
__device__ float g_att [TOKENS * DMODEL];
__device__ float g_x1  [TOKENS * DMODEL];
__device__ float g_ffn [TOKENS * 4 * DMODEL];
__device__ float g_x2  [TOKENS * DMODEL];
// transposed weights [N][K] (K-major rows)
__device__ float g_wqkvT[3 * DMODEL * DMODEL];
__device__ float g_woT  [DMODEL * DMODEL];
__device__ float g_w1T  [4 * DMODEL * DMODEL];
__device__ float g_w2T  [DMODEL * 4 * DMODEL];

__device__ __forceinline__ float to_tf32(float x) {
    float y; asm("cvt.rna.tf32.f32 %0, %1;" : "=f"(y) : "f"(x)); return y;
}
__device__ __forceinline__ float gelu_f(float x) {
    return 0.5f * x * (1.0f + erff(x * 0.70710678118654752f));
}

// ---------------------------------------------------------------------------
// Weight transpose: out[N][K] = in[K][N]
// ---------------------------------------------------------------------------
__global__ __launch_bounds__(256) void transpose_kernel(
    const float* __restrict__ in, float* __restrict__ out, int R, int C)
{
    __shared__ float t[32][33];
    const int bx = blockIdx.x * 32;
    const int by = blockIdx.y * 32;
    const int tx = threadIdx.x & 31, ty4 = (threadIdx.x >> 5) * 4;
    #pragma unroll
    for (int i = 0; i < 4; i++)
        t[ty4 + i][tx] = in[(size_t)(by + ty4 + i) * C + bx + tx];
    __syncthreads();
    #pragma unroll
    for (int i = 0; i < 4; i++)
        out[(size_t)(bx + ty4 + i) * R + by + tx] = t[tx][ty4 + i];
}

// ---------------------------------------------------------------------------
// LayerNorm: one block per row of 768
// ---------------------------------------------------------------------------
__global__ __launch_bounds__(256) void ln_kernel(
    const float* __restrict__ x, const float* __restrict__ g,
    const float* __restrict__ b, float* __restrict__ o)
{
    __shared__ float red[32];
    const int t = threadIdx.x;
    const float* xr = x + (size_t)blockIdx.x * DMODEL;

    float v0 = xr[t], v1 = xr[t + 256], v2 = xr[t + 512];
    float s  = v0 + v1 + v2;
    float ss = v0 * v0 + v1 * v1 + v2 * v2;
    #pragma unroll
    for (int o2 = 16; o2 > 0; o2 >>= 1) {
        s  += __shfl_xor_sync(0xffffffffu, s,  o2);
        ss += __shfl_xor_sync(0xffffffffu, ss, o2);
    }
    const int w = t >> 5;
    if ((t & 31) == 0) { red[w] = s; red[16 + w] = ss; }
    __syncthreads();
    if (t == 0) {
        float S = 0.f, SS = 0.f;
        #pragma unroll
        for (int i = 0; i < 8; i++) { S += red[i]; SS += red[16 + i]; }
        red[0] = S; red[16] = SS;
    }
    __syncthreads();
    const float mean = red[0] * (1.0f / DMODEL);
    const float var  = red[16] * (1.0f / DMODEL) - mean * mean;
    const float inv  = rsqrtf(var + 1e-5f);

    float* orow = o + (size_t)blockIdx.x * DMODEL;
    orow[t]       = (v0 - mean) * inv * g[t]       + b[t];
    orow[t + 256] = (v1 - mean) * inv * g[t + 256] + b[t + 256];
    orow[t + 512] = (v2 - mean) * inv * g[t + 512] + b[t + 512];
}

// ---------------------------------------------------------------------------
// tf32 mma.sync GEMM: C(MxN) = A(MxK) @ Bt(NxK)^T + epilogue
// CTA tile 128x128, BK=32, 256 threads = 8 warps (2m x 4n), warp tile 64x32.
// Fragments per m16n8k8: A 4regs, B 2regs. Smem rows padded to 36 floats:
// bank(lane) = (4g + t) mod 32 -> conflict-free fragment LDS.
// Register prefetch of next K-chunk overlaps LDG with MMA.
// MODE 0: C = AB ; 1: +bias+res ; 2: gelu(+bias) ; 3: gelu(+bias)+res
// Requires M%128==0, N%128==0, K%32==0 and K>=64. True for all calls.
// ---------------------------------------------------------------------------
#define GBK 32
#define APAD 36

__global__ __launch_bounds__(256) void tc_gemm_impl_marker() {}

template <int MODE>
__global__ __launch_bounds__(256) void tc_gemm(
    const float* __restrict__ A, const float* __restrict__ Bt,
    float* __restrict__ C, int M, int N, int K,
    const float* __restrict__ bias, const float* __restrict__ res)
{
    __shared__ float As[128 * APAD];
    __shared__ float Bs[128 * APAD];

    const int tid = threadIdx.x;
    const int wid = tid >> 5, lane = tid & 31;
    const int g = lane >> 2, t = lane & 3;          // groupID / thread-in-group
    const int wm = wid >> 2, wn = wid & 3;          // warp grid 2 x 4
    const int bn = blockIdx.x, bm = blockIdx.y;

    const float* Ab = A  + (size_t)bm * 128 * K;
    const float* Bb = Bt + (size_t)bn * 128 * K;

    // fill indices: 1024 float4 per (A|B) tile / 256 threads = 4 each
    const int fr = tid >> 1;                         // unused; keep simple below

    float acc[4][4][4];
    #pragma unroll
    for (int mt = 0; mt < 4; mt++)
        #pragma unroll
        for (int nt = 0; nt < 4; nt++)
            #pragma unroll
            for (int q = 0; q < 4; q++) acc[mt][nt][q] = 0.f;

    float4 pa[4], pb[4];
    #pragma unroll
    for (int i = 0; i < 4; i++) {
        const int idx = tid + i * 256;
        const int r = idx >> 3, c4 = (idx & 7) * 4;
        pa[i] = *(const float4*)&Ab[(size_t)r * K + c4];
        pb[i] = *(const float4*)&Bb[(size_t)r * K + c4];
    }

    const int nch = K / GBK;
    for (int ch = 0; ch < nch; ch++) {
        // store prefetched chunk (tf32-rounded)
        #pragma unroll
        for (int i = 0; i < 4; i++) {
            const int idx = tid + i * 256;
            const int r = idx >> 3, c4 = (idx & 7) * 4;
            float4 v = pa[i];
            v.x = to_tf32(v.x); v.y = to_tf32(v.y);
            v.z = to_tf32(v.z); v.w = to_tf32(v.w);
            *(float4*)&As[r * APAD + c4] = v;
            v = pb[i];
            v.x = to_tf32(v.x); v.y = to_tf32(v.y);
            v.z = to_tf32(v.z); v.w = to_tf32(v.w);
            *(float4*)&Bs[r * APAD + c4] = v;
        }
        __syncthreads();

        // prefetch next chunk
        if (ch + 1 < nch) {
            const int k0 = (ch + 1) * GBK;
            #pragma unroll
            for (int i = 0; i < 4; i++) {
                const int idx = tid + i * 256;
                const int r = idx >> 3, c4 = (idx & 7) * 4;
                pa[i] = *(const float4*)&Ab[(size_t)r * K + k0 + c4];
                pb[i] = *(const float4*)&Bb[(size_t)r * K + k0 + c4];
            }
        }

        // 4 x k8 MMA steps over this chunk
        #pragma unroll
        for (int kk = 0; kk < GBK; kk += 8) {
            uint32_t af[4][4];
            #pragma unroll
            for (int mt = 0; mt < 4; mt++) {
                const int rb = wm * 64 + mt * 16 + g;
                af[mt][0] = __float_as_uint(As[rb * APAD + kk + t]);
                af[mt][1] = __float_as_uint(As[(rb + 8) * APAD + kk + t]);
                af[mt][2] = __float_as_uint(As[rb * APAD + kk + t + 4]);
                af[mt][3] = __float_as_uint(As[(rb + 8) * APAD + kk + t + 4]);
            }
            uint32_t bf[4][2];
            #pragma unroll
            for (int nt = 0; nt < 4; nt++) {
                const int nb = wn * 32 + nt * 8 + g;
                bf[nt][0] = __float_as_uint(Bs[nb * APAD + kk + t]);
                bf[nt][1] = __float_as_uint(Bs[nb * APAD + kk + t + 4]);
            }
            #pragma unroll
            for (int mt = 0; mt < 4; mt++)
                #pragma unroll
                for (int nt = 0; nt < 4; nt++) {
                    asm volatile(
                        "mma.sync.aligned.m16n8k8.row.col.f32.tf32.tf32.f32 "
                        "{%0,%1,%2,%3}, {%4,%5,%6,%7}, {%8,%9}, {%0,%1,%2,%3};"
                        : "+f"(acc[mt][nt][0]), "+f"(acc[mt][nt][1]),
                          "+f"(acc[mt][nt][2]), "+f"(acc[mt][nt][3])
                        : "r"(af[mt][0]), "r"(af[mt][1]),
                          "r"(af[mt][2]), "r"(af[mt][3]),
                          "r"(bf[nt][0]), "r"(bf[nt][1]));
                }
        }
        __syncthreads();
    }

    // ---- epilogue ----
    #pragma unroll
    for (int mt = 0; mt < 4; mt++) {
        const int row = bm * 128 + wm * 64 + mt * 16 + g;
        #pragma unroll
        for (int nt = 0; nt < 4; nt++) {
            const int col = bn * 128 + wn * 32 + nt * 8 + 2 * t;
            float v0 = acc[mt][nt][0], v1 = acc[mt][nt][1];
            float v2 = acc[mt][nt][2], v3 = acc[mt][nt][3];
            if (MODE >= 1) {
                const float2 bb = *(const float2*)&bias[col];
                v0 += bb.x; v1 += bb.y; v2 += bb.x; v3 += bb.y;
            }
            if (MODE >= 2) {
                v0 = gelu_f(v0); v1 = gelu_f(v1);
                v2 = gelu_f(v2); v3 = gelu_f(v3);
            }
            const size_t r0 = (size_t)row * N + col;
            const size_t r1 = (size_t)(row + 8) * N + col;
            if (MODE == 1 || MODE == 3) {
                const float2 ra = *(const float2*)&res[r0];
                const float2 rb2 = *(const float2*)&res[r1];
                v0 += ra.x; v1 += ra.y; v2 += rb2.x; v3 += rb2.y;
            }
            float2 o0; o0.x = v0; o0.y = v1;
            float2 o1; o1.x = v2; o1.y = v3;
            *(float2*)&C[r0] = o0;
            *(float2*)&C[r1] = o1;
        }
    }
}

// ---------------------------------------------------------------------------
// Attention (unchanged, known correct): flash-style fp32, 64x64 tiles.
// Output written contiguously as (B,H,N,DH) == faithful reshape (B,N,D).
// ---------------------------------------------------------------------------
#define ATTN_QPAD 100
#define ATTN_PPAD 68
#define ATTN_SMEM_FLOATS (3 * 64 * ATTN_QPAD + 64 * ATTN_PPAD + 64)
#define ATTN_SMEM_BYTES  (ATTN_SMEM_FLOATS * 4)

__global__ __launch_bounds__(256) void attn_kernel(
    const float* __restrict__ qkv, float* __restrict__ out)
{
    extern __shared__ float sm[];
    float* sQ = sm;
    float* sK = sQ + 64 * ATTN_QPAD;
    float* sV = sK + 64 * ATTN_QPAD;
    float* sP = sV + 64 * ATTN_QPAD;
    float* sC = sP + 64 * ATTN_PPAD;

    const int tid = threadIdx.x;
    const int bh = blockIdx.y;
    const int b  = bh >> 3, h = bh & 7;
    const int q0 = blockIdx.x << 6;

    const float* gQ = qkv + (size_t)b * NSEQ * (3 * DMODEL) + h * DHEAD;
    const float* gK = gQ + DMODEL;
    const float* gV = gQ + 2 * DMODEL;

    for (int idx = tid; idx < 64 * 24; idx += 256) {
        const int r = idx / 24, c = (idx % 24) * 4;
        *(float4*)&sQ[r * ATTN_QPAD + c] =
            *(const float4*)&gQ[(size_t)(q0 + r) * (3 * DMODEL) + c];
    }

    const int qr = tid >> 2, l4 = tid & 3;
    const int rg = tid >> 4, cg = tid & 15;
    const float scale = 0.10206207261596578f;

    float m = -1e30f, l = 0.f;
    float acc[4][6];
    #pragma unroll
    for (int i = 0; i < 4; i++)
        #pragma unroll
        for (int j = 0; j < 6; j++) acc[i][j] = 0.f;

    for (int kt = 0; kt < NSEQ; kt += 64) {
        __syncthreads();
        for (int idx = tid; idx < 64 * 24; idx += 256) {
            const int r = idx / 24, c = (idx % 24) * 4;
            *(float4*)&sK[r * ATTN_QPAD + c] =
                *(const float4*)&gK[(size_t)(kt + r) * (3 * DMODEL) + c];
            *(float4*)&sV[r * ATTN_QPAD + c] =
                *(const float4*)&gV[(size_t)(kt + r) * (3 * DMODEL) + c];
        }
        __syncthreads();

        float s[16];
        #pragma unroll
        for (int jj = 0; jj < 16; jj++) s[jj] = 0.f;
        for (int d4 = 0; d4 < 24; d4++) {
            const float4 q4 = *(const float4*)&sQ[qr * ATTN_QPAD + d4 * 4];
            #pragma unroll
            for (int jj = 0; jj < 16; jj++) {
                const float4 k4 =
                    *(const float4*)&sK[(l4 + jj * 4) * ATTN_QPAD + d4 * 4];
                s[jj] += q4.x * k4.x + q4.y * k4.y + q4.z * k4.z + q4.w * k4.w;
            }
        }
        #pragma unroll
        for (int jj = 0; jj < 16; jj++) s[jj] *= scale;

        float tmax = s[0];
        #pragma unroll
        for (int jj = 1; jj < 16; jj++) tmax = fmaxf(tmax, s[jj]);
        tmax = fmaxf(tmax, __shfl_xor_sync(0xffffffffu, tmax, 1));
        tmax = fmaxf(tmax, __shfl_xor_sync(0xffffffffu, tmax, 2));

        const float mnew = fmaxf(m, tmax);
        const float corr = __expf(m - mnew);
        float psum = 0.f;
        #pragma unroll
        for (int jj = 0; jj < 16; jj++) {
            const float p = __expf(s[jj] - mnew);
            psum += p;
            sP[qr * ATTN_PPAD + l4 + jj * 4] = p;
        }
        psum += __shfl_xor_sync(0xffffffffu, psum, 1);
        psum += __shfl_xor_sync(0xffffffffu, psum, 2);
        l = l * corr + psum;
        m = mnew;
        if (l4 == 0) sC[qr] = corr;
        __syncthreads();

        #pragma unroll
        for (int i = 0; i < 4; i++) {
            const float cr = sC[rg * 4 + i];
            #pragma unroll
            for (int j = 0; j < 6; j++) acc[i][j] *= cr;
        }
        for (int j = 0; j < 64; j++) {
            const float p0 = sP[(rg * 4 + 0) * ATTN_PPAD + j];
            const float p1 = sP[(rg * 4 + 1) * ATTN_PPAD + j];
            const float p2 = sP[(rg * 4 + 2) * ATTN_PPAD + j];
            const float p3 = sP[(rg * 4 + 3) * ATTN_PPAD + j];
            #pragma unroll
            for (int c = 0; c < 6; c++) {
                const float vv = sV[j * ATTN_QPAD + cg * 6 + c];
                acc[0][c] = fmaf(p0, vv, acc[0][c]);
                acc[1][c] = fmaf(p1, vv, acc[1][c]);
                acc[2][c] = fmaf(p2, vv, acc[2][c]);
                acc[3][c] = fmaf(p3, vv, acc[3][c]);
            }
        }
    }

    __syncthreads();
    if (l4 == 0) sC[qr] = 1.0f / l;
    __syncthreads();

    float* gO = out + (size_t)bh * NSEQ * DHEAD + (size_t)q0 * DHEAD;
    #pragma unroll
    for (int i = 0; i < 4; i++) {
        const int r = rg * 4 + i;
        const float inv = sC[r];
        #pragma unroll
        for (int c = 0; c < 6; c++)
            gO[(size_t)r * DHEAD + cg * 6 + c] = acc[i][c] * inv;
    }
}

// ---------------------------------------------------------------------------
// Launcher
// ---------------------------------------------------------------------------
extern "C" void kernel_launch(void* const* d_in, const int* in_sizes, int n_in,
                              void* d_out, int out_size)
{
    (void)in_sizes; (void)n_in; (void)out_size;
    const float* x     = (const float*)d_in[0];
    const float* w_qkv = (const float*)d_in[1];
    const float* w_o   = (const float*)d_in[2];
    const float* b_o   = (const float*)d_in[3];
    const float* w1    = (const float*)d_in[4];
    const float* b1    = (const float*)d_in[5];
    const float* w2    = (const float*)d_in[6];
    const float* b2    = (const float*)d_in[7];
    const float* g1    = (const float*)d_in[8];
    const float* be1   = (const float*)d_in[9];
    const float* gm    = (const float*)d_in[10];
    const float* bm    = (const float*)d_in[11];
    const float* g3    = (const float*)d_in[12];
    const float* be3   = (const float*)d_in[13];

    float *ln, *qkv, *att, *x1, *ffn, *x2;
    float *wqkvT, *woT, *w1T, *w2T;
    cudaGetSymbolAddress((void**)&ln,    g_ln);
    cudaGetSymbolAddress((void**)&qkv,   g_qkv);
    cudaGetSymbolAddress((void**)&att,   g_att);
    cudaGetSymbolAddress((void**)&x1,    g_x1);
    cudaGetSymbolAddress((void**)&ffn,   g_ffn);
    cudaGetSymbolAddress((void**)&x2,    g_x2);
    cudaGetSymbolAddress((void**)&wqkvT, g_wqkvT);
    cudaGetSymbolAddress((void**)&woT,   g_woT);
    cudaGetSymbolAddress((void**)&w1T,   g_w1T);
    cudaGetSymbolAddress((void**)&w2T,   g_w2T);

    cudaFuncSetAttribute(attn_kernel,
        cudaFuncAttributeMaxDynamicSharedMemorySize, ATTN_SMEM_BYTES);

    // 0. transpose weights to [N][K]
    transpose_kernel<<<dim3(2304 / 32,  768 / 32), 256>>>(w_qkv, wqkvT,  768, 2304);
    transpose_kernel<<<dim3( 768 / 32,  768 / 32), 256>>>(w_o,   woT,    768,  768);
    transpose_kernel<<<dim3(3072 / 32,  768 / 32), 256>>>(w1,    w1T,    768, 3072);
    transpose_kernel<<<dim3( 768 / 32, 3072 / 32), 256>>>(w2,    w2T,   3072,  768);

    // 1. h = LN1(x)
    ln_kernel<<<TOKENS, 256>>>(x, g1, be1, ln);
    // 2. qkv = h @ w_qkv              (8192 x 2304, K=768)
    tc_gemm<0><<<dim3(2304 / 128, TOKENS / 128), 256>>>(
        ln, wqkvT, qkv, TOKENS, 2304, 768, nullptr, nullptr);
    // 3. attention -> (B,H,N,DH) contiguous == (B,N,D) flat
    attn_kernel<<<dim3(NSEQ / 64, 64), 256, ATTN_SMEM_BYTES>>>(qkv, att);
    // 4. x1 = att @ w_o + b_o + x     (8192 x 768, K=768)
    tc_gemm<1><<<dim3(768 / 128, TOKENS / 128), 256>>>(
        att, woT, x1, TOKENS, 768, 768, b_o, x);
    // 5. h = LN2(x1)
    ln_kernel<<<TOKENS, 256>>>(x1, gm, bm, ln);
    // 6. ffn = gelu(h @ w1 + b1)      (8192 x 3072, K=768)
    tc_gemm<2><<<dim3(3072 / 128, TOKENS / 128), 256>>>(
        ln, w1T, ffn, TOKENS, 3072, 768, b1, nullptr);
    // 7. x2 = gelu(ffn @ w2 + b2) + x1 (8192 x 768, K=3072)
    tc_gemm<3><<<dim3(768 / 128, TOKENS / 128), 256>>>(
        ffn, w2T, x2, TOKENS, 768, 3072, b2, x1);
    // 8. out = LN3(x2)
    ln_kernel<<<TOKENS, 256>>>(x2, g3, be3, (float*)d_out);
}

// round 4
// speedup vs baseline: 3.4293x; 1.7427x over previous
#include <cuda_runtime.h>
#include <cuda_bf16.h>
#include <math.h>
#include <stdint.h>

// ---------------------------------------------------------------------------
// EncoderBlock: B=8, N=1024, D=768, H=8, DH=96
// Round 4: attention moved to mma.sync tf32 (both QK^T and PV phases);
// GEMMs double-buffered. All tensor math on the HMMA tf32 path.
// ---------------------------------------------------------------------------

#define TOKENS 8192
#define DMODEL 768
#define NSEQ   1024
#define NHEAD  8
#define DHEAD  96
#define ATTN_SCALE 0.10206207261596577f   // 1/sqrt(96)

// ---------------- scratch ---------------------------------------------------
__device__ float g_ln  [TOKENS * DMODEL];
__device__ float g_qkv [TOKENS * 3 * DMODEL];
__device__ float g_att [TOKENS * DMODEL];
__device__ float g_x1  [TOKENS * DMODEL];
__device__ float g_ffn [TOKENS * 4 * DMODEL];
__device__ float g_x2  [TOKENS * DMODEL];
__device__ float g_wqkvT[3 * DMODEL * DMODEL];
__device__ float g_woT  [DMODEL * DMODEL];
__device__ float g_w1T  [4 * DMODEL * DMODEL];
__device__ float g_w2T  [DMODEL * 4 * DMODEL];

__device__ __forceinline__ float to_tf32(float x) {
    float y; asm("cvt.rna.tf32.f32 %0, %1;" : "=f"(y) : "f"(x)); return y;
}
__device__ __forceinline__ float gelu_f(float x) {
    return 0.5f * x * (1.0f + erff(x * 0.70710678118654752f));
}

#define MMA_TF32(d, a, b) \
    asm volatile("mma.sync.aligned.m16n8k8.row.col.f32.tf32.tf32.f32 " \
      "{%0,%1,%2,%3}, {%4,%5,%6,%7}, {%8,%9}, {%0,%1,%2,%3};" \
      : "+f"((d)[0]), "+f"((d)[1]), "+f"((d)[2]), "+f"((d)[3]) \
      : "r"((a)[0]), "r"((a)[1]), "r"((a)[2]), "r"((a)[3]), \
        "r"((b)[0]), "r"((b)[1]))

// ---------------------------------------------------------------------------
// Weight transpose: out[N][K] = in[K][N]
// ---------------------------------------------------------------------------
__global__ __launch_bounds__(256) void transpose_kernel(
    const float* __restrict__ in, float* __restrict__ out, int R, int C)
{
    __shared__ float t[32][33];
    const int bx = blockIdx.x * 32;
    const int by = blockIdx.y * 32;
    const int tx = threadIdx.x & 31, ty4 = (threadIdx.x >> 5) * 4;
    #pragma unroll
    for (int i = 0; i < 4; i++)
        t[ty4 + i][tx] = in[(size_t)(by + ty4 + i) * C + bx + tx];
    __syncthreads();
    #pragma unroll
    for (int i = 0; i < 4; i++)
        out[(size_t)(bx + ty4 + i) * R + by + tx] = t[tx][ty4 + i];
}

// ---------------------------------------------------------------------------
// LayerNorm: one block per row of 768
// ---------------------------------------------------------------------------
__global__ __launch_bounds__(256) void ln_kernel(
    const float* __restrict__ x, const float* __restrict__ g,
    const float* __restrict__ b, float* __restrict__ o)
{
    __shared__ float red[32];
    const int t = threadIdx.x;
    const float* xr = x + (size_t)blockIdx.x * DMODEL;

    float v0 = xr[t], v1 = xr[t + 256], v2 = xr[t + 512];
    float s  = v0 + v1 + v2;
    float ss = v0 * v0 + v1 * v1 + v2 * v2;
    #pragma unroll
    for (int o2 = 16; o2 > 0; o2 >>= 1) {
        s  += __shfl_xor_sync(0xffffffffu, s,  o2);
        ss += __shfl_xor_sync(0xffffffffu, ss, o2);
    }
    const int w = t >> 5;
    if ((t & 31) == 0) { red[w] = s; red[16 + w] = ss; }
    __syncthreads();
    if (t == 0) {
        float S = 0.f, SS = 0.f;
        #pragma unroll
        for (int i = 0; i < 8; i++) { S += red[i]; SS += red[16 + i]; }
        red[0] = S; red[16] = SS;
    }
    __syncthreads();
    const float mean = red[0] * (1.0f / DMODEL);
    const float var  = red[16] * (1.0f / DMODEL) - mean * mean;
    const float inv  = rsqrtf(var + 1e-5f);

    float* orow = o + (size_t)blockIdx.x * DMODEL;
    orow[t]       = (v0 - mean) * inv * g[t]       + b[t];
    orow[t + 256] = (v1 - mean) * inv * g[t + 256] + b[t + 256];
    orow[t + 512] = (v2 - mean) * inv * g[t + 512] + b[t + 512];
}

// ---------------------------------------------------------------------------
// tf32 mma.sync GEMM, double-buffered: C(MxN) = A(MxK) @ Bt(NxK)^T + epilogue
// CTA tile 128x128, BK=32, 256 threads = 8 warps (2m x 4n), warp tile 64x32.
// MODE 0: C = AB ; 1: +bias+res ; 2: gelu(+bias) ; 3: gelu(+bias)+res
// ---------------------------------------------------------------------------
#define GBK 32
#define APAD 36
#define GTBUF (128 * APAD)
#define GEMM_SMEM_BYTES (4 * GTBUF * 4)    // As0|As1|Bs0|Bs1 = 73728 B

template <int MODE>
__global__ __launch_bounds__(256) void tc_gemm(
    const float* __restrict__ A, const float* __restrict__ Bt,
    float* __restrict__ C, int M, int N, int K,
    const float* __restrict__ bias, const float* __restrict__ res)
{
    extern __shared__ float gsm[];

    const int tid = threadIdx.x;
    const int wid = tid >> 5, lane = tid & 31;
    const int g = lane >> 2, t = lane & 3;
    const int wm = wid >> 2, wn = wid & 3;
    const int bn = blockIdx.x, bm = blockIdx.y;

    const float* Ab = A  + (size_t)bm * 128 * K;
    const float* Bb = Bt + (size_t)bn * 128 * K;

    float acc[4][4][4];
    #pragma unroll
    for (int mt = 0; mt < 4; mt++)
        #pragma unroll
        for (int nt = 0; nt < 4; nt++)
            #pragma unroll
            for (int q = 0; q < 4; q++) acc[mt][nt][q] = 0.f;

    const int fr = tid >> 3, fc = (tid & 7) * 4;   // fill row / col4

    float4 pa[4], pb[4];
    #pragma unroll
    for (int i = 0; i < 4; i++) {
        const int r = fr + i * 32;
        pa[i] = *(const float4*)&Ab[(size_t)r * K + fc];
        pb[i] = *(const float4*)&Bb[(size_t)r * K + fc];
    }
    // store chunk 0 into buffer 0
    #pragma unroll
    for (int i = 0; i < 4; i++) {
        const int r = fr + i * 32;
        float4 v = pa[i];
        v.x = to_tf32(v.x); v.y = to_tf32(v.y); v.z = to_tf32(v.z); v.w = to_tf32(v.w);
        *(float4*)&gsm[0 * GTBUF + r * APAD + fc] = v;
        v = pb[i];
        v.x = to_tf32(v.x); v.y = to_tf32(v.y); v.z = to_tf32(v.z); v.w = to_tf32(v.w);
        *(float4*)&gsm[2 * GTBUF + r * APAD + fc] = v;
    }
    __syncthreads();

    const int nch = K / GBK;
    for (int ch = 0; ch < nch; ch++) {
        const int cur = ch & 1;
        const float* As = gsm + cur * GTBUF;
        const float* Bs = gsm + (2 + cur) * GTBUF;

        // prefetch next chunk into registers
        if (ch + 1 < nch) {
            const int k0 = (ch + 1) * GBK;
            #pragma unroll
            for (int i = 0; i < 4; i++) {
                const int r = fr + i * 32;
                pa[i] = *(const float4*)&Ab[(size_t)r * K + k0 + fc];
                pb[i] = *(const float4*)&Bb[(size_t)r * K + k0 + fc];
            }
        }

        #pragma unroll
        for (int kk = 0; kk < GBK; kk += 8) {
            uint32_t af[4][4];
            #pragma unroll
            for (int mt = 0; mt < 4; mt++) {
                const int rb = wm * 64 + mt * 16 + g;
                af[mt][0] = __float_as_uint(As[rb * APAD + kk + t]);
                af[mt][1] = __float_as_uint(As[(rb + 8) * APAD + kk + t]);
                af[mt][2] = __float_as_uint(As[rb * APAD + kk + t + 4]);
                af[mt][3] = __float_as_uint(As[(rb + 8) * APAD + kk + t + 4]);
            }
            uint32_t bf[4][2];
            #pragma unroll
            for (int nt = 0; nt < 4; nt++) {
                const int nb = wn * 32 + nt * 8 + g;
                bf[nt][0] = __float_as_uint(Bs[nb * APAD + kk + t]);
                bf[nt][1] = __float_as_uint(Bs[nb * APAD + kk + t + 4]);
            }
            #pragma unroll
            for (int mt = 0; mt < 4; mt++)
                #pragma unroll
                for (int nt = 0; nt < 4; nt++)
                    MMA_TF32(acc[mt][nt], af[mt], bf[nt]);
        }

        // store prefetched chunk into the other buffer
        if (ch + 1 < nch) {
            float* An = gsm + (cur ^ 1) * GTBUF;
            float* Bn = gsm + (2 + (cur ^ 1)) * GTBUF;
            #pragma unroll
            for (int i = 0; i < 4; i++) {
                const int r = fr + i * 32;
                float4 v = pa[i];
                v.x = to_tf32(v.x); v.y = to_tf32(v.y);
                v.z = to_tf32(v.z); v.w = to_tf32(v.w);
                *(float4*)&An[r * APAD + fc] = v;
                v = pb[i];
                v.x = to_tf32(v.x); v.y = to_tf32(v.y);
                v.z = to_tf32(v.z); v.w = to_tf32(v.w);
                *(float4*)&Bn[r * APAD + fc] = v;
            }
        }
        __syncthreads();
    }

    // ---- epilogue ----
    #pragma unroll
    for (int mt = 0; mt < 4; mt++) {
        const int row = bm * 128 + wm * 64 + mt * 16 + g;
        #pragma unroll
        for (int nt = 0; nt < 4; nt++) {
            const int col = bn * 128 + wn * 32 + nt * 8 + 2 * t;
            float v0 = acc[mt][nt][0], v1 = acc[mt][nt][1];
            float v2 = acc[mt][nt][2], v3 = acc[mt][nt][3];
            if (MODE >= 1) {
                const float2 bb = *(const float2*)&bias[col];
                v0 += bb.x; v1 += bb.y; v2 += bb.x; v3 += bb.y;
            }
            if (MODE >= 2) {
                v0 = gelu_f(v0); v1 = gelu_f(v1);
                v2 = gelu_f(v2); v3 = gelu_f(v3);
            }
            const size_t r0 = (size_t)row * N + col;
            const size_t r1 = (size_t)(row + 8) * N + col;
            if (MODE == 1 || MODE == 3) {
                const float2 ra = *(const float2*)&res[r0];
                const float2 rb2 = *(const float2*)&res[r1];
                v0 += ra.x; v1 += ra.y; v2 += rb2.x; v3 += rb2.y;
            }
            float2 o0; o0.x = v0; o0.y = v1;
            float2 o1; o1.x = v2; o1.y = v3;
            *(float2*)&C[r0] = o0;
            *(float2*)&C[r1] = o1;
        }
    }
}

// ---------------------------------------------------------------------------
// Attention on mma.sync tf32. CTA: 128 q-rows x 64 kv-tile, 256 threads.
// Warps: 4 in m (32 rows each) x 2 in n.
//   S phase : warp tile 32q x 32kv  (2 m16 x 4 n8 tiles, 12 k-steps over d=96)
//   PV phase: warp tile 32q x 48d   (2 m16 x 6 n8 tiles,  8 k-steps over kv=64)
// V transposed into smem at load (conflict-free stores & fragment loads).
// Softmax row stats in smem; 2-warp combine via sRmax/sRsum.
// Output contiguous (B,H,N,DH) == faithful reshape (B,N,D).
// ---------------------------------------------------------------------------
#define AQPAD 100
#define AVPAD 68
#define APPAD 68
// float offsets in dynamic smem
#define SQ_OFF   0
#define SK_OFF   (128 * AQPAD)                    // 12800
#define SVT_OFF  (SK_OFF + 64 * AQPAD)            // 19200
#define SP_OFF   (SVT_OFF + 96 * AVPAD)           // 25728
#define SM_OFF   (SP_OFF + 128 * APPAD)           // 34432
#define SL_OFF   (SM_OFF + 128)
#define SCR_OFF  (SL_OFF + 128)
#define RMX_OFF  (SCR_OFF + 128)
#define RSM_OFF  (RMX_OFF + 256)
#define ATTN_SMEM_BYTES ((RSM_OFF + 256) * 4)     // 141312 B

__global__ __launch_bounds__(256) void attn_mma_kernel(
    const float* __restrict__ qkv, float* __restrict__ out)
{
    extern __shared__ float sm[];
    float* sQ   = sm + SQ_OFF;
    float* sK   = sm + SK_OFF;
    float* sVt  = sm + SVT_OFF;
    float* sP   = sm + SP_OFF;
    float* sM   = sm + SM_OFF;
    float* sL   = sm + SL_OFF;
    float* sCr  = sm + SCR_OFF;
    float* sRmx = sm + RMX_OFF;    // [128][2]
    float* sRsm = sm + RSM_OFF;    // [128][2]

    const int tid = threadIdx.x, lane = tid & 31, wid = tid >> 5;
    const int g = lane >> 2, t = lane & 3;
    const int wm = wid & 3, wn = wid >> 2;
    const int bh = blockIdx.y, b = bh >> 3, h = bh & 7;
    const int q0 = blockIdx.x * 128;

    const float* gQ = qkv + (size_t)b * NSEQ * (3 * DMODEL) + h * DHEAD;
    const float* gK = gQ + DMODEL;
    const float* gV = gQ + 2 * DMODEL;

    // Q fill (x SCALE, tf32): 128 rows x 24 float4 / 256 threads = 12 each
    #pragma unroll
    for (int i = 0; i < 12; i++) {
        const int idx = tid + i * 256;
        const int r = idx / 24, c4 = (idx % 24) * 4;
        float4 v = *(const float4*)&gQ[(size_t)(q0 + r) * (3 * DMODEL) + c4];
        v.x = to_tf32(v.x * ATTN_SCALE); v.y = to_tf32(v.y * ATTN_SCALE);
        v.z = to_tf32(v.z * ATTN_SCALE); v.w = to_tf32(v.w * ATTN_SCALE);
        *(float4*)&sQ[r * AQPAD + c4] = v;
    }
    if (tid < 128) { sM[tid] = -1e30f; sL[tid] = 0.f; }

    // per-thread rows: wm*32 + {g, g+8, 16+g, 24+g}
    const int rows[4] = {wm * 32 + g, wm * 32 + g + 8,
                         wm * 32 + 16 + g, wm * 32 + 24 + g};

    float o[2][6][4];
    #pragma unroll
    for (int mt = 0; mt < 2; mt++)
        #pragma unroll
        for (int nt = 0; nt < 6; nt++)
            #pragma unroll
            for (int q = 0; q < 4; q++) o[mt][nt][q] = 0.f;

    for (int kt = 0; kt < NSEQ; kt += 64) {
        __syncthreads();   // prior-tile PV readers done; also covers init/Q fill
        // K fill: 64 x 24 float4 / 256 = 6 each
        #pragma unroll
        for (int i = 0; i < 6; i++) {
            const int idx = tid + i * 256;
            const int r = idx / 24, c4 = (idx % 24) * 4;
            float4 v = *(const float4*)&gK[(size_t)(kt + r) * (3 * DMODEL) + c4];
            v.x = to_tf32(v.x); v.y = to_tf32(v.y);
            v.z = to_tf32(v.z); v.w = to_tf32(v.w);
            *(float4*)&sK[r * AQPAD + c4] = v;
        }
        // V transposed fill: lanes span kv for fixed d4 -> conflict-free STS
        {
            const int kv = tid & 63;
            const int dbase = tid >> 6;           // 0..3
            #pragma unroll
            for (int j = 0; j < 6; j++) {
                const int d4 = j * 4 + dbase;
                float4 v = *(const float4*)&gV[(size_t)(kt + kv) * (3 * DMODEL) + d4 * 4];
                sVt[(d4 * 4 + 0) * AVPAD + kv] = to_tf32(v.x);
                sVt[(d4 * 4 + 1) * AVPAD + kv] = to_tf32(v.y);
                sVt[(d4 * 4 + 2) * AVPAD + kv] = to_tf32(v.z);
                sVt[(d4 * 4 + 3) * AVPAD + kv] = to_tf32(v.w);
            }
        }
        __syncthreads();

        // ---- S = Q K^T (scaled already) ----
        float sacc[2][4][4];
        #pragma unroll
        for (int mt = 0; mt < 2; mt++)
            #pragma unroll
            for (int nt = 0; nt < 4; nt++)
                #pragma unroll
                for (int q = 0; q < 4; q++) sacc[mt][nt][q] = 0.f;

        #pragma unroll
        for (int k8 = 0; k8 < 96; k8 += 8) {
            uint32_t af[2][4];
            #pragma unroll
            for (int mt = 0; mt < 2; mt++) {
                const int rb = wm * 32 + mt * 16;
                af[mt][0] = __float_as_uint(sQ[(rb + g) * AQPAD + k8 + t]);
                af[mt][1] = __float_as_uint(sQ[(rb + g + 8) * AQPAD + k8 + t]);
                af[mt][2] = __float_as_uint(sQ[(rb + g) * AQPAD + k8 + t + 4]);
                af[mt][3] = __float_as_uint(sQ[(rb + g + 8) * AQPAD + k8 + t + 4]);
            }
            uint32_t bf[4][2];
            #pragma unroll
            for (int nt = 0; nt < 4; nt++) {
                const int nb = wn * 32 + nt * 8 + g;
                bf[nt][0] = __float_as_uint(sK[nb * AQPAD + k8 + t]);
                bf[nt][1] = __float_as_uint(sK[nb * AQPAD + k8 + t + 4]);
            }
            #pragma unroll
            for (int mt = 0; mt < 2; mt++)
                #pragma unroll
                for (int nt = 0; nt < 4; nt++)
                    MMA_TF32(sacc[mt][nt], af[mt], bf[nt]);
        }

        // ---- row max: quad reduce, then 2-warp combine via smem ----
        float rmax[4];
        #pragma unroll
        for (int mt = 0; mt < 2; mt++) {
            float m0 = sacc[mt][0][0], m1 = sacc[mt][0][2];
            #pragma unroll
            for (int nt = 0; nt < 4; nt++) {
                m0 = fmaxf(m0, fmaxf(sacc[mt][nt][0], sacc[mt][nt][1]));
                m1 = fmaxf(m1, fmaxf(sacc[mt][nt][2], sacc[mt][nt][3]));
            }
            rmax[mt * 2] = m0; rmax[mt * 2 + 1] = m1;
        }
        #pragma unroll
        for (int q = 0; q < 4; q++) {
            rmax[q] = fmaxf(rmax[q], __shfl_xor_sync(0xffffffffu, rmax[q], 1));
            rmax[q] = fmaxf(rmax[q], __shfl_xor_sync(0xffffffffu, rmax[q], 2));
        }
        if (t == 0) {
            #pragma unroll
            for (int q = 0; q < 4; q++) sRmx[rows[q] * 2 + wn] = rmax[q];
        }
        __syncthreads();

        float mnew[4], corr[4];
        #pragma unroll
        for (int q = 0; q < 4; q++) {
            const float mo = sM[rows[q]];
            mnew[q] = fmaxf(mo, fmaxf(sRmx[rows[q] * 2], sRmx[rows[q] * 2 + 1]));
            corr[q] = __expf(mo - mnew[q]);
        }
        float psum[4] = {0.f, 0.f, 0.f, 0.f};
        #pragma unroll
        for (int mt = 0; mt < 2; mt++) {
            #pragma unroll
            for (int nt = 0; nt < 4; nt++) {
                const float p0 = __expf(sacc[mt][nt][0] - mnew[mt * 2]);
                const float p1 = __expf(sacc[mt][nt][1] - mnew[mt * 2]);
                const float p2 = __expf(sacc[mt][nt][2] - mnew[mt * 2 + 1]);
                const float p3 = __expf(sacc[mt][nt][3] - mnew[mt * 2 + 1]);
                psum[mt * 2] += p0 + p1;
                psum[mt * 2 + 1] += p2 + p3;
                const int col = wn * 32 + nt * 8 + 2 * t;
                float2 v0; v0.x = to_tf32(p0); v0.y = to_tf32(p1);
                float2 v1; v1.x = to_tf32(p2); v1.y = to_tf32(p3);
                *(float2*)&sP[(wm * 32 + mt * 16 + g) * APPAD + col] = v0;
                *(float2*)&sP[(wm * 32 + mt * 16 + g + 8) * APPAD + col] = v1;
            }
        }
        #pragma unroll
        for (int q = 0; q < 4; q++) {
            psum[q] += __shfl_xor_sync(0xffffffffu, psum[q], 1);
            psum[q] += __shfl_xor_sync(0xffffffffu, psum[q], 2);
        }
        if (t == 0) {
            #pragma unroll
            for (int q = 0; q < 4; q++) sRsm[rows[q] * 2 + wn] = psum[q];
        }
        __syncthreads();
        if (wn == 0 && t == 0) {
            #pragma unroll
            for (int q = 0; q < 4; q++) {
                const int r = rows[q];
                sL[r] = sL[r] * corr[q] + sRsm[r * 2] + sRsm[r * 2 + 1];
                sM[r] = mnew[q];
                sCr[r] = corr[q];
            }
        }
        __syncthreads();

        // ---- O = O*corr + P V ----
        float cr[4];
        #pragma unroll
        for (int q = 0; q < 4; q++) cr[q] = sCr[rows[q]];
        #pragma unroll
        for (int mt = 0; mt < 2; mt++)
            #pragma unroll
            for (int nt = 0; nt < 6; nt++) {
                o[mt][nt][0] *= cr[mt * 2];     o[mt][nt][1] *= cr[mt * 2];
                o[mt][nt][2] *= cr[mt * 2 + 1]; o[mt][nt][3] *= cr[mt * 2 + 1];
            }
        #pragma unroll
        for (int k8 = 0; k8 < 64; k8 += 8) {
            uint32_t af[2][4];
            #pragma unroll
            for (int mt = 0; mt < 2; mt++) {
                const int rb = wm * 32 + mt * 16;
                af[mt][0] = __float_as_uint(sP[(rb + g) * APPAD + k8 + t]);
                af[mt][1] = __float_as_uint(sP[(rb + g + 8) * APPAD + k8 + t]);
                af[mt][2] = __float_as_uint(sP[(rb + g) * APPAD + k8 + t + 4]);
                af[mt][3] = __float_as_uint(sP[(rb + g + 8) * APPAD + k8 + t + 4]);
            }
            uint32_t bf[6][2];
            #pragma unroll
            for (int nt = 0; nt < 6; nt++) {
                const int nb = wn * 48 + nt * 8 + g;
                bf[nt][0] = __float_as_uint(sVt[nb * AVPAD + k8 + t]);
                bf[nt][1] = __float_as_uint(sVt[nb * AVPAD + k8 + t + 4]);
            }
            #pragma unroll
            for (int mt = 0; mt < 2; mt++)
                #pragma unroll
                for (int nt = 0; nt < 6; nt++)
                    MMA_TF32(o[mt][nt], af[mt], bf[nt]);
        }
    }

    // ---- epilogue: normalize by 1/l, write (B,H,N,DH) contiguous ----
    float invl[4];
    #pragma unroll
    for (int q = 0; q < 4; q++) invl[q] = 1.0f / sL[rows[q]];

    float* gO = out + ((size_t)bh * NSEQ + q0) * DHEAD;
    #pragma unroll
    for (int mt = 0; mt < 2; mt++) {
        const int rlo = wm * 32 + mt * 16 + g;
        const int rhi = rlo + 8;
        #pragma unroll
        for (int nt = 0; nt < 6; nt++) {
            const int col = wn * 48 + nt * 8 + 2 * t;
            float2 v0; v0.x = o[mt][nt][0] * invl[mt * 2];
            v0.y = o[mt][nt][1] * invl[mt * 2];
            float2 v1; v1.x = o[mt][nt][2] * invl[mt * 2 + 1];
            v1.y = o[mt][nt][3] * invl[mt * 2 + 1];
            *(float2*)&gO[(size_t)rlo * DHEAD + col] = v0;
            *(float2*)&gO[(size_t)rhi * DHEAD + col] = v1;
        }
    }
}

// ---------------------------------------------------------------------------
// Launcher
// ---------------------------------------------------------------------------
extern "C" void kernel_launch(void* const* d_in, const int* in_sizes, int n_in,
                              void* d_out, int out_size)
{
    (void)in_sizes; (void)n_in; (void)out_size;
    const float* x     = (const float*)d_in[0];
    const float* w_qkv = (const float*)d_in[1];
    const float* w_o   = (const float*)d_in[2];
    const float* b_o   = (const float*)d_in[3];
    const float* w1    = (const float*)d_in[4];
    const float* b1    = (const float*)d_in[5];
    const float* w2    = (const float*)d_in[6];
    const float* b2    = (const float*)d_in[7];
    const float* g1    = (const float*)d_in[8];
    const float* be1   = (const float*)d_in[9];
    const float* gm    = (const float*)d_in[10];
    const float* bm    = (const float*)d_in[11];
    const float* g3    = (const float*)d_in[12];
    const float* be3   = (const float*)d_in[13];

    float *ln, *qkv, *att, *x1, *ffn, *x2;
    float *wqkvT, *woT, *w1T, *w2T;
    cudaGetSymbolAddress((void**)&ln,    g_ln);
    cudaGetSymbolAddress((void**)&qkv,   g_qkv);
    cudaGetSymbolAddress((void**)&att,   g_att);
    cudaGetSymbolAddress((void**)&x1,    g_x1);
    cudaGetSymbolAddress((void**)&ffn,   g_ffn);
    cudaGetSymbolAddress((void**)&x2,    g_x2);
    cudaGetSymbolAddress((void**)&wqkvT, g_wqkvT);
    cudaGetSymbolAddress((void**)&woT,   g_woT);
    cudaGetSymbolAddress((void**)&w1T,   g_w1T);
    cudaGetSymbolAddress((void**)&w2T,   g_w2T);

    cudaFuncSetAttribute(attn_mma_kernel,
        cudaFuncAttributeMaxDynamicSharedMemorySize, ATTN_SMEM_BYTES);
    cudaFuncSetAttribute(tc_gemm<0>,
        cudaFuncAttributeMaxDynamicSharedMemorySize, GEMM_SMEM_BYTES);
    cudaFuncSetAttribute(tc_gemm<1>,
        cudaFuncAttributeMaxDynamicSharedMemorySize, GEMM_SMEM_BYTES);
    cudaFuncSetAttribute(tc_gemm<2>,
        cudaFuncAttributeMaxDynamicSharedMemorySize, GEMM_SMEM_BYTES);
    cudaFuncSetAttribute(tc_gemm<3>,
        cudaFuncAttributeMaxDynamicSharedMemorySize, GEMM_SMEM_BYTES);

    // 0. transpose weights to [N][K]
    transpose_kernel<<<dim3(2304 / 32,  768 / 32), 256>>>(w_qkv, wqkvT,  768, 2304);
    transpose_kernel<<<dim3( 768 / 32,  768 / 32), 256>>>(w_o,   woT,    768,  768);
    transpose_kernel<<<dim3(3072 / 32,  768 / 32), 256>>>(w1,    w1T,    768, 3072);
    transpose_kernel<<<dim3( 768 / 32, 3072 / 32), 256>>>(w2,    w2T,   3072,  768);

    // 1. h = LN1(x)
    ln_kernel<<<TOKENS, 256>>>(x, g1, be1, ln);
    // 2. qkv = h @ w_qkv              (8192 x 2304, K=768)
    tc_gemm<0><<<dim3(2304 / 128, TOKENS / 128), 256, GEMM_SMEM_BYTES>>>(
        ln, wqkvT, qkv, TOKENS, 2304, 768, nullptr, nullptr);
    // 3. attention -> (B,H,N,DH) contiguous == (B,N,D) flat
    attn_mma_kernel<<<dim3(NSEQ / 128, 64), 256, ATTN_SMEM_BYTES>>>(qkv, att);
    // 4. x1 = att @ w_o + b_o + x     (8192 x 768, K=768)
    tc_gemm<1><<<dim3(768 / 128, TOKENS / 128), 256, GEMM_SMEM_BYTES>>>(
        att, woT, x1, TOKENS, 768, 768, b_o, x);
    // 5. h = LN2(x1)
    ln_kernel<<<TOKENS, 256>>>(x1, gm, bm, ln);
    // 6. ffn = gelu(h @ w1 + b1)      (8192 x 3072, K=768)
    tc_gemm<2><<<dim3(3072 / 128, TOKENS / 128), 256, GEMM_SMEM_BYTES>>>(
        ln, w1T, ffn, TOKENS, 3072, 768, b1, nullptr);
    // 7. x2 = gelu(ffn @ w2 + b2) + x1 (8192 x 768, K=3072)
    tc_gemm<3><<<dim3(768 / 128, TOKENS / 128), 256, GEMM_SMEM_BYTES>>>(
        ffn, w2T, x2, TOKENS, 768, 3072, b2, x1);
    // 8. out = LN3(x2)
    ln_kernel<<<TOKENS, 256>>>(x2, g3, be3, (float*)d_out);
}

// round 5
// speedup vs baseline: 3.5878x; 1.0462x over previous
#include <cuda_runtime.h>
#include <cuda_bf16.h>
#include <math.h>
#include <stdint.h>

// ---------------------------------------------------------------------------
// EncoderBlock: B=8, N=1024, D=768, H=8, DH=96
// Round 5: GEMM CTA tile 128x256 (warp tile 64x64), cp.async 3-stage pipeline,
// raw-f32 tf32 MMA (HW truncation). Attention drops CVTs in hot loops.
// ---------------------------------------------------------------------------

#define TOKENS 8192
#define DMODEL 768
#define NSEQ   1024
#define NHEAD  8
#define DHEAD  96
#define ATTN_SCALE 0.10206207261596577f   // 1/sqrt(96)

// ---------------- scratch ---------------------------------------------------
__device__ float g_ln  [TOKENS * DMODEL];
__device__ float g_qkv [TOKENS * 3 * DMODEL];
__device__ float g_att [TOKENS * DMODEL];
__device__ float g_x1  [TOKENS * DMODEL];
__device__ float g_ffn [TOKENS * 4 * DMODEL];
__device__ float g_x2  [TOKENS * DMODEL];
__device__ float g_wqkvT[3 * DMODEL * DMODEL];
__device__ float g_woT  [DMODEL * DMODEL];
__device__ float g_w1T  [4 * DMODEL * DMODEL];
__device__ float g_w2T  [DMODEL * 4 * DMODEL];

__device__ __forceinline__ uint32_t smem_u32(const void* p) {
    uint32_t a;
    asm("{ .reg .u64 t; cvta.to.shared.u64 t, %1; cvt.u32.u64 %0, t; }"
        : "=r"(a) : "l"(p));
    return a;
}
__device__ __forceinline__ float gelu_f(float x) {
    return 0.5f * x * (1.0f + erff(x * 0.70710678118654752f));
}

#define MMA_TF32(d, a, b) \
    asm volatile("mma.sync.aligned.m16n8k8.row.col.f32.tf32.tf32.f32 " \
      "{%0,%1,%2,%3}, {%4,%5,%6,%7}, {%8,%9}, {%0,%1,%2,%3};" \
      : "+f"((d)[0]), "+f"((d)[1]), "+f"((d)[2]), "+f"((d)[3]) \
      : "r"((a)[0]), "r"((a)[1]), "r"((a)[2]), "r"((a)[3]), \
        "r"((b)[0]), "r"((b)[1]))

#define CP_ASYNC16(dst, src) \
    asm volatile("cp.async.cg.shared.global [%0], [%1], 16;" \
                 :: "r"(dst), "l"(src))
#define CP_COMMIT() asm volatile("cp.async.commit_group;" ::: "memory")
#define CP_WAIT1()  asm volatile("cp.async.wait_group 1;" ::: "memory")

// ---------------------------------------------------------------------------
// Weight transpose: out[N][K] = in[K][N]
// ---------------------------------------------------------------------------
__global__ __launch_bounds__(256) void transpose_kernel(
    const float* __restrict__ in, float* __restrict__ out, int R, int C)
{
    __shared__ float t[32][33];
    const int bx = blockIdx.x * 32;
    const int by = blockIdx.y * 32;
    const int tx = threadIdx.x & 31, ty4 = (threadIdx.x >> 5) * 4;
    #pragma unroll
    for (int i = 0; i < 4; i++)
        t[ty4 + i][tx] = in[(size_t)(by + ty4 + i) * C + bx + tx];
    __syncthreads();
    #pragma unroll
    for (int i = 0; i < 4; i++)
        out[(size_t)(bx + ty4 + i) * R + by + tx] = t[tx][ty4 + i];
}

// ---------------------------------------------------------------------------
// LayerNorm: one block per row of 768
// ---------------------------------------------------------------------------
__global__ __launch_bounds__(256) void ln_kernel(
    const float* __restrict__ x, const float* __restrict__ g,
    const float* __restrict__ b, float* __restrict__ o)
{
    __shared__ float red[32];
    const int t = threadIdx.x;
    const float* xr = x + (size_t)blockIdx.x * DMODEL;

    float v0 = xr[t], v1 = xr[t + 256], v2 = xr[t + 512];
    float s  = v0 + v1 + v2;
    float ss = v0 * v0 + v1 * v1 + v2 * v2;
    #pragma unroll
    for (int o2 = 16; o2 > 0; o2 >>= 1) {
        s  += __shfl_xor_sync(0xffffffffu, s,  o2);
        ss += __shfl_xor_sync(0xffffffffu, ss, o2);
    }
    const int w = t >> 5;
    if ((t & 31) == 0) { red[w] = s; red[16 + w] = ss; }
    __syncthreads();
    if (t == 0) {
        float S = 0.f, SS = 0.f;
        #pragma unroll
        for (int i = 0; i < 8; i++) { S += red[i]; SS += red[16 + i]; }
        red[0] = S; red[16] = SS;
    }
    __syncthreads();
    const float mean = red[0] * (1.0f / DMODEL);
    const float var  = red[16] * (1.0f / DMODEL) - mean * mean;
    const float inv  = rsqrtf(var + 1e-5f);

    float* orow = o + (size_t)blockIdx.x * DMODEL;
    orow[t]       = (v0 - mean) * inv * g[t]       + b[t];
    orow[t + 256] = (v1 - mean) * inv * g[t + 256] + b[t + 256];
    orow[t + 512] = (v2 - mean) * inv * g[t + 512] + b[t + 512];
}

// ---------------------------------------------------------------------------
// tf32 mma.sync GEMM, cp.async 3-stage: C(MxN) = A(MxK) @ Bt(NxK)^T + epi
// CTA tile 128x256, 256 threads = 8 warps (2m x 4n), warp tile 64x64.
// A/B fed raw f32 to HMMA (hardware tf32 truncation).
// MODE 0: C = AB ; 1: +bias+res ; 2: gelu(+bias) ; 3: gelu(+bias)+res
// Requires M%128==0, N%256==0, K%32==0, K>=96. True for all calls.
// ---------------------------------------------------------------------------
#define GBK 32
#define APAD 36
#define STG_A (128 * APAD)
#define STG_B (256 * APAD)
#define STG_FL (STG_A + STG_B)                 // 13824 floats / stage
#define GEMM_SMEM_BYTES (3 * STG_FL * 4)       // 165888 B

template <int MODE>
__global__ __launch_bounds__(256, 1) void tc_gemm(
    const float* __restrict__ A, const float* __restrict__ Bt,
    float* __restrict__ C, int M, int N, int K,
    const float* __restrict__ bias, const float* __restrict__ res)
{
    extern __shared__ float gsm[];
    const uint32_t sb = smem_u32(gsm);

    const int tid = threadIdx.x;
    const int wid = tid >> 5, lane = tid & 31;
    const int g = lane >> 2, t = lane & 3;
    const int wm = wid >> 2, wn = wid & 3;
    const int bn = blockIdx.x, bm = blockIdx.y;

    const float* Ab = A  + (size_t)bm * 128 * K;
    const float* Bb = Bt + (size_t)bn * 256 * K;

    const int fr = tid >> 3, fc16 = (tid & 7) * 4;   // fill row/col4

    float acc[4][8][4];
    #pragma unroll
    for (int mt = 0; mt < 4; mt++)
        #pragma unroll
        for (int nt = 0; nt < 8; nt++)
            #pragma unroll
            for (int q = 0; q < 4; q++) acc[mt][nt][q] = 0.f;

    const int nch = K / GBK;

    // fill stage s with chunk c (A: 4 granules/thread, B: 8)
    auto fill = [&](int s, int c) {
        const uint32_t base = sb + (uint32_t)s * (STG_FL * 4);
        const int k0 = c * GBK;
        #pragma unroll
        for (int i = 0; i < 4; i++) {
            const int r = fr + i * 32;
            const uint32_t dst = base + (uint32_t)(r * APAD + fc16) * 4;
            CP_ASYNC16(dst, Ab + (size_t)r * K + k0 + fc16);
        }
        #pragma unroll
        for (int i = 0; i < 8; i++) {
            const int r = fr + i * 32;
            const uint32_t dst = base + (uint32_t)(STG_A + r * APAD + fc16) * 4;
            CP_ASYNC16(dst, Bb + (size_t)r * K + k0 + fc16);
        }
        CP_COMMIT();
    };

    fill(0, 0);
    fill(1, 1);

    int st = 0;
    for (int ch = 0; ch < nch; ch++) {
        CP_WAIT1();
        __syncthreads();
        if (ch + 2 < nch) {
            const int s2 = (st + 2 >= 3) ? st - 1 : st + 2;
            fill(s2, ch + 2);
        }
        const float* As = gsm + st * STG_FL;
        const float* Bs = As + STG_A;

        #pragma unroll
        for (int kk = 0; kk < GBK; kk += 8) {
            uint32_t af[4][4];
            #pragma unroll
            for (int mt = 0; mt < 4; mt++) {
                const int rb = wm * 64 + mt * 16 + g;
                af[mt][0] = __float_as_uint(As[rb * APAD + kk + t]);
                af[mt][1] = __float_as_uint(As[(rb + 8) * APAD + kk + t]);
                af[mt][2] = __float_as_uint(As[rb * APAD + kk + t + 4]);
                af[mt][3] = __float_as_uint(As[(rb + 8) * APAD + kk + t + 4]);
            }
            uint32_t bf[8][2];
            #pragma unroll
            for (int nt = 0; nt < 8; nt++) {
                const int nb = wn * 64 + nt * 8 + g;
                bf[nt][0] = __float_as_uint(Bs[nb * APAD + kk + t]);
                bf[nt][1] = __float_as_uint(Bs[nb * APAD + kk + t + 4]);
            }
            #pragma unroll
            for (int mt = 0; mt < 4; mt++)
                #pragma unroll
                for (int nt = 0; nt < 8; nt++)
                    MMA_TF32(acc[mt][nt], af[mt], bf[nt]);
        }
        st = (st == 2) ? 0 : st + 1;
    }

    // ---- epilogue ----
    #pragma unroll
    for (int mt = 0; mt < 4; mt++) {
        const int row = bm * 128 + wm * 64 + mt * 16 + g;
        #pragma unroll
        for (int nt = 0; nt < 8; nt++) {
            const int col = bn * 256 + wn * 64 + nt * 8 + 2 * t;
            float v0 = acc[mt][nt][0], v1 = acc[mt][nt][1];
            float v2 = acc[mt][nt][2], v3 = acc[mt][nt][3];
            if (MODE >= 1) {
                const float2 bb = *(const float2*)&bias[col];
                v0 += bb.x; v1 += bb.y; v2 += bb.x; v3 += bb.y;
            }
            if (MODE >= 2) {
                v0 = gelu_f(v0); v1 = gelu_f(v1);
                v2 = gelu_f(v2); v3 = gelu_f(v3);
            }
            const size_t r0 = (size_t)row * N + col;
            const size_t r1 = (size_t)(row + 8) * N + col;
            if (MODE == 1 || MODE == 3) {
                const float2 ra = *(const float2*)&res[r0];
                const float2 rb2 = *(const float2*)&res[r1];
                v0 += ra.x; v1 += ra.y; v2 += rb2.x; v3 += rb2.y;
            }
            float2 o0; o0.x = v0; o0.y = v1;
            float2 o1; o1.x = v2; o1.y = v3;
            *(float2*)&C[r0] = o0;
            *(float2*)&C[r1] = o1;
        }
    }
}

// ---------------------------------------------------------------------------
// Attention on mma.sync tf32 (raw f32 operands). CTA: 128 q x 64 kv, 256 thr.
// Warps 4m x 2n. S: warp 32x32; PV: warp 32x48 (V transposed in smem).
// Output contiguous (B,H,N,DH) == faithful reshape (B,N,D).
// ---------------------------------------------------------------------------
#define AQPAD 100
#define AVPAD 68
#define APPAD 68
#define SQ_OFF   0
#define SK_OFF   (128 * AQPAD)
#define SVT_OFF  (SK_OFF + 64 * AQPAD)
#define SP_OFF   (SVT_OFF + 96 * AVPAD)
#define SM_OFF   (SP_OFF + 128 * APPAD)
#define SL_OFF   (SM_OFF + 128)
#define SCR_OFF  (SL_OFF + 128)
#define RMX_OFF  (SCR_OFF + 128)
#define RSM_OFF  (RMX_OFF + 256)
#define ATTN_SMEM_BYTES ((RSM_OFF + 256) * 4)

__global__ __launch_bounds__(256) void attn_mma_kernel(
    const float* __restrict__ qkv, float* __restrict__ out)
{
    extern __shared__ float sm[];
    float* sQ   = sm + SQ_OFF;
    float* sK   = sm + SK_OFF;
    float* sVt  = sm + SVT_OFF;
    float* sP   = sm + SP_OFF;
    float* sM   = sm + SM_OFF;
    float* sL   = sm + SL_OFF;
    float* sCr  = sm + SCR_OFF;
    float* sRmx = sm + RMX_OFF;
    float* sRsm = sm + RSM_OFF;

    const int tid = threadIdx.x, lane = tid & 31, wid = tid >> 5;
    const int g = lane >> 2, t = lane & 3;
    const int wm = wid & 3, wn = wid >> 2;
    const int bh = blockIdx.y, b = bh >> 3, h = bh & 7;
    const int q0 = blockIdx.x * 128;

    const float* gQ = qkv + (size_t)b * NSEQ * (3 * DMODEL) + h * DHEAD;
    const float* gK = gQ + DMODEL;
    const float* gV = gQ + 2 * DMODEL;

    #pragma unroll
    for (int i = 0; i < 12; i++) {
        const int idx = tid + i * 256;
        const int r = idx / 24, c4 = (idx % 24) * 4;
        float4 v = *(const float4*)&gQ[(size_t)(q0 + r) * (3 * DMODEL) + c4];
        v.x *= ATTN_SCALE; v.y *= ATTN_SCALE;
        v.z *= ATTN_SCALE; v.w *= ATTN_SCALE;
        *(float4*)&sQ[r * AQPAD + c4] = v;
    }
    if (tid < 128) { sM[tid] = -1e30f; sL[tid] = 0.f; }

    const int rows[4] = {wm * 32 + g, wm * 32 + g + 8,
                         wm * 32 + 16 + g, wm * 32 + 24 + g};

    float o[2][6][4];
    #pragma unroll
    for (int mt = 0; mt < 2; mt++)
        #pragma unroll
        for (int nt = 0; nt < 6; nt++)
            #pragma unroll
            for (int q = 0; q < 4; q++) o[mt][nt][q] = 0.f;

    for (int kt = 0; kt < NSEQ; kt += 64) {
        __syncthreads();
        #pragma unroll
        for (int i = 0; i < 6; i++) {
            const int idx = tid + i * 256;
            const int r = idx / 24, c4 = (idx % 24) * 4;
            *(float4*)&sK[r * AQPAD + c4] =
                *(const float4*)&gK[(size_t)(kt + r) * (3 * DMODEL) + c4];
        }
        {
            const int kv = tid & 63;
            const int dbase = tid >> 6;
            #pragma unroll
            for (int j = 0; j < 6; j++) {
                const int d4 = j * 4 + dbase;
                float4 v = *(const float4*)&gV[(size_t)(kt + kv) * (3 * DMODEL) + d4 * 4];
                sVt[(d4 * 4 + 0) * AVPAD + kv] = v.x;
                sVt[(d4 * 4 + 1) * AVPAD + kv] = v.y;
                sVt[(d4 * 4 + 2) * AVPAD + kv] = v.z;
                sVt[(d4 * 4 + 3) * AVPAD + kv] = v.w;
            }
        }
        __syncthreads();

        float sacc[2][4][4];
        #pragma unroll
        for (int mt = 0; mt < 2; mt++)
            #pragma unroll
            for (int nt = 0; nt < 4; nt++)
                #pragma unroll
                for (int q = 0; q < 4; q++) sacc[mt][nt][q] = 0.f;

        #pragma unroll
        for (int k8 = 0; k8 < 96; k8 += 8) {
            uint32_t af[2][4];
            #pragma unroll
            for (int mt = 0; mt < 2; mt++) {
                const int rb = wm * 32 + mt * 16;
                af[mt][0] = __float_as_uint(sQ[(rb + g) * AQPAD + k8 + t]);
                af[mt][1] = __float_as_uint(sQ[(rb + g + 8) * AQPAD + k8 + t]);
                af[mt][2] = __float_as_uint(sQ[(rb + g) * AQPAD + k8 + t + 4]);
                af[mt][3] = __float_as_uint(sQ[(rb + g + 8) * AQPAD + k8 + t + 4]);
            }
            uint32_t bf[4][2];
            #pragma unroll
            for (int nt = 0; nt < 4; nt++) {
                const int nb = wn * 32 + nt * 8 + g;
                bf[nt][0] = __float_as_uint(sK[nb * AQPAD + k8 + t]);
                bf[nt][1] = __float_as_uint(sK[nb * AQPAD + k8 + t + 4]);
            }
            #pragma unroll
            for (int mt = 0; mt < 2; mt++)
                #pragma unroll
                for (int nt = 0; nt < 4; nt++)
                    MMA_TF32(sacc[mt][nt], af[mt], bf[nt]);
        }

        float rmax[4];
        #pragma unroll
        for (int mt = 0; mt < 2; mt++) {
            float m0 = sacc[mt][0][0], m1 = sacc[mt][0][2];
            #pragma unroll
            for (int nt = 0; nt < 4; nt++) {
                m0 = fmaxf(m0, fmaxf(sacc[mt][nt][0], sacc[mt][nt][1]));
                m1 = fmaxf(m1, fmaxf(sacc[mt][nt][2], sacc[mt][nt][3]));
            }
            rmax[mt * 2] = m0; rmax[mt * 2 + 1] = m1;
        }
        #pragma unroll
        for (int q = 0; q < 4; q++) {
            rmax[q] = fmaxf(rmax[q], __shfl_xor_sync(0xffffffffu, rmax[q], 1));
            rmax[q] = fmaxf(rmax[q], __shfl_xor_sync(0xffffffffu, rmax[q], 2));
        }
        if (t == 0) {
            #pragma unroll
            for (int q = 0; q < 4; q++) sRmx[rows[q] * 2 + wn] = rmax[q];
        }
        __syncthreads();

        float mnew[4], corr[4];
        #pragma unroll
        for (int q = 0; q < 4; q++) {
            const float mo = sM[rows[q]];
            mnew[q] = fmaxf(mo, fmaxf(sRmx[rows[q] * 2], sRmx[rows[q] * 2 + 1]));
            corr[q] = __expf(mo - mnew[q]);
        }
        float psum[4] = {0.f, 0.f, 0.f, 0.f};
        #pragma unroll
        for (int mt = 0; mt < 2; mt++) {
            #pragma unroll
            for (int nt = 0; nt < 4; nt++) {
                const float p0 = __expf(sacc[mt][nt][0] - mnew[mt * 2]);
                const float p1 = __expf(sacc[mt][nt][1] - mnew[mt * 2]);
                const float p2 = __expf(sacc[mt][nt][2] - mnew[mt * 2 + 1]);
                const float p3 = __expf(sacc[mt][nt][3] - mnew[mt * 2 + 1]);
                psum[mt * 2] += p0 + p1;
                psum[mt * 2 + 1] += p2 + p3;
                const int col = wn * 32 + nt * 8 + 2 * t;
                float2 v0; v0.x = p0; v0.y = p1;
                float2 v1; v1.x = p2; v1.y = p3;
                *(float2*)&sP[(wm * 32 + mt * 16 + g) * APPAD + col] = v0;
                *(float2*)&sP[(wm * 32 + mt * 16 + g + 8) * APPAD + col] = v1;
            }
        }
        #pragma unroll
        for (int q = 0; q < 4; q++) {
            psum[q] += __shfl_xor_sync(0xffffffffu, psum[q], 1);
            psum[q] += __shfl_xor_sync(0xffffffffu, psum[q], 2);
        }
        if (t == 0) {
            #pragma unroll
            for (int q = 0; q < 4; q++) sRsm[rows[q] * 2 + wn] = psum[q];
        }
        __syncthreads();
        if (wn == 0 && t == 0) {
            #pragma unroll
            for (int q = 0; q < 4; q++) {
                const int r = rows[q];
                sL[r] = sL[r] * corr[q] + sRsm[r * 2] + sRsm[r * 2 + 1];
                sM[r] = mnew[q];
                sCr[r] = corr[q];
            }
        }
        __syncthreads();

        float cr[4];
        #pragma unroll
        for (int q = 0; q < 4; q++) cr[q] = sCr[rows[q]];
        #pragma unroll
        for (int mt = 0; mt < 2; mt++)
            #pragma unroll
            for (int nt = 0; nt < 6; nt++) {
                o[mt][nt][0] *= cr[mt * 2];     o[mt][nt][1] *= cr[mt * 2];
                o[mt][nt][2] *= cr[mt * 2 + 1]; o[mt][nt][3] *= cr[mt * 2 + 1];
            }
        #pragma unroll
        for (int k8 = 0; k8 < 64; k8 += 8) {
            uint32_t af[2][4];
            #pragma unroll
            for (int mt = 0; mt < 2; mt++) {
                const int rb = wm * 32 + mt * 16;
                af[mt][0] = __float_as_uint(sP[(rb + g) * APPAD + k8 + t]);
                af[mt][1] = __float_as_uint(sP[(rb + g + 8) * APPAD + k8 + t]);
                af[mt][2] = __float_as_uint(sP[(rb + g) * APPAD + k8 + t + 4]);
                af[mt][3] = __float_as_uint(sP[(rb + g + 8) * APPAD + k8 + t + 4]);
            }
            uint32_t bf[6][2];
            #pragma unroll
            for (int nt = 0; nt < 6; nt++) {
                const int nb = wn * 48 + nt * 8 + g;
                bf[nt][0] = __float_as_uint(sVt[nb * AVPAD + k8 + t]);
                bf[nt][1] = __float_as_uint(sVt[nb * AVPAD + k8 + t + 4]);
            }
            #pragma unroll
            for (int mt = 0; mt < 2; mt++)
                #pragma unroll
                for (int nt = 0; nt < 6; nt++)
                    MMA_TF32(o[mt][nt], af[mt], bf[nt]);
        }
    }

    float invl[4];
    #pragma unroll
    for (int q = 0; q < 4; q++) invl[q] = 1.0f / sL[rows[q]];

    float* gO = out + ((size_t)bh * NSEQ + q0) * DHEAD;
    #pragma unroll
    for (int mt = 0; mt < 2; mt++) {
        const int rlo = wm * 32 + mt * 16 + g;
        const int rhi = rlo + 8;
        #pragma unroll
        for (int nt = 0; nt < 6; nt++) {
            const int col = wn * 48 + nt * 8 + 2 * t;
            float2 v0; v0.x = o[mt][nt][0] * invl[mt * 2];
            v0.y = o[mt][nt][1] * invl[mt * 2];
            float2 v1; v1.x = o[mt][nt][2] * invl[mt * 2 + 1];
            v1.y = o[mt][nt][3] * invl[mt * 2 + 1];
            *(float2*)&gO[(size_t)rlo * DHEAD + col] = v0;
            *(float2*)&gO[(size_t)rhi * DHEAD + col] = v1;
        }
    }
}

// ---------------------------------------------------------------------------
// Launcher
// ---------------------------------------------------------------------------
extern "C" void kernel_launch(void* const* d_in, const int* in_sizes, int n_in,
                              void* d_out, int out_size)
{
    (void)in_sizes; (void)n_in; (void)out_size;
    const float* x     = (const float*)d_in[0];
    const float* w_qkv = (const float*)d_in[1];
    const float* w_o   = (const float*)d_in[2];
    const float* b_o   = (const float*)d_in[3];
    const float* w1    = (const float*)d_in[4];
    const float* b1    = (const float*)d_in[5];
    const float* w2    = (const float*)d_in[6];
    const float* b2    = (const float*)d_in[7];
    const float* g1    = (const float*)d_in[8];
    const float* be1   = (const float*)d_in[9];
    const float* gm    = (const float*)d_in[10];
    const float* bm    = (const float*)d_in[11];
    const float* g3    = (const float*)d_in[12];
    const float* be3   = (const float*)d_in[13];

    float *ln, *qkv, *att, *x1, *ffn, *x2;
    float *wqkvT, *woT, *w1T, *w2T;
    cudaGetSymbolAddress((void**)&ln,    g_ln);
    cudaGetSymbolAddress((void**)&qkv,   g_qkv);
    cudaGetSymbolAddress((void**)&att,   g_att);
    cudaGetSymbolAddress((void**)&x1,    g_x1);
    cudaGetSymbolAddress((void**)&ffn,   g_ffn);
    cudaGetSymbolAddress((void**)&x2,    g_x2);
    cudaGetSymbolAddress((void**)&wqkvT, g_wqkvT);
    cudaGetSymbolAddress((void**)&woT,   g_woT);
    cudaGetSymbolAddress((void**)&w1T,   g_w1T);
    cudaGetSymbolAddress((void**)&w2T,   g_w2T);

    cudaFuncSetAttribute(attn_mma_kernel,
        cudaFuncAttributeMaxDynamicSharedMemorySize, ATTN_SMEM_BYTES);
    cudaFuncSetAttribute(tc_gemm<0>,
        cudaFuncAttributeMaxDynamicSharedMemorySize, GEMM_SMEM_BYTES);
    cudaFuncSetAttribute(tc_gemm<1>,
        cudaFuncAttributeMaxDynamicSharedMemorySize, GEMM_SMEM_BYTES);
    cudaFuncSetAttribute(tc_gemm<2>,
        cudaFuncAttributeMaxDynamicSharedMemorySize, GEMM_SMEM_BYTES);
    cudaFuncSetAttribute(tc_gemm<3>,
        cudaFuncAttributeMaxDynamicSharedMemorySize, GEMM_SMEM_BYTES);

    // 0. transpose weights to [N][K]
    transpose_kernel<<<dim3(2304 / 32,  768 / 32), 256>>>(w_qkv, wqkvT,  768, 2304);
    transpose_kernel<<<dim3( 768 / 32,  768 / 32), 256>>>(w_o,   woT,    768,  768);
    transpose_kernel<<<dim3(3072 / 32,  768 / 32), 256>>>(w1,    w1T,    768, 3072);
    transpose_kernel<<<dim3( 768 / 32, 3072 / 32), 256>>>(w2,    w2T,   3072,  768);

    // 1. h = LN1(x)
    ln_kernel<<<TOKENS, 256>>>(x, g1, be1, ln);
    // 2. qkv = h @ w_qkv              (8192 x 2304, K=768)
    tc_gemm<0><<<dim3(2304 / 256, TOKENS / 128), 256, GEMM_SMEM_BYTES>>>(
        ln, wqkvT, qkv, TOKENS, 2304, 768, nullptr, nullptr);
    // 3. attention -> (B,H,N,DH) contiguous == (B,N,D) flat
    attn_mma_kernel<<<dim3(NSEQ / 128, 64), 256, ATTN_SMEM_BYTES>>>(qkv, att);
    // 4. x1 = att @ w_o + b_o + x     (8192 x 768, K=768)
    tc_gemm<1><<<dim3(768 / 256, TOKENS / 128), 256, GEMM_SMEM_BYTES>>>(
        att, woT, x1, TOKENS, 768, 768, b_o, x);
    // 5. h = LN2(x1)
    ln_kernel<<<TOKENS, 256>>>(x1, gm, bm, ln);
    // 6. ffn = gelu(h @ w1 + b1)      (8192 x 3072, K=768)
    tc_gemm<2><<<dim3(3072 / 256, TOKENS / 128), 256, GEMM_SMEM_BYTES>>>(
        ln, w1T, ffn, TOKENS, 3072, 768, b1, nullptr);
    // 7. x2 = gelu(ffn @ w2 + b2) + x1 (8192 x 768, K=3072)
    tc_gemm<3><<<dim3(768 / 256, TOKENS / 128), 256, GEMM_SMEM_BYTES>>>(
        ffn, w2T, x2, TOKENS, 768, 3072, b2, x1);
    // 8. out = LN3(x2)
    ln_kernel<<<TOKENS, 256>>>(x2, g3, be3, (float*)d_out);
}

// round 6
// speedup vs baseline: 3.8019x; 1.0597x over previous
#include <cuda_runtime.h>
#include <cuda_bf16.h>
#include <math.h>
#include <stdint.h>

// ---------------------------------------------------------------------------
// EncoderBlock: B=8, N=1024, D=768, H=8, DH=96
// Round 6: per-GEMM tile config (BN=256 deep-wave / BN=128 2-CTA-per-SM),
// RNA tf32 rounding moved to producers (exact operands, HW trunc = no-op),
// pipeline tail race fixed. Attention: R4 numerics (rounded Q*scale, P, out).
// ---------------------------------------------------------------------------

#define TOKENS 8192
#define DMODEL 768
#define NSEQ   1024
#define NHEAD  8
#define DHEAD  96
#define ATTN_SCALE 0.10206207261596577f   // 1/sqrt(96)

// ---------------- scratch ---------------------------------------------------
__device__ float g_ln  [TOKENS * DMODEL];
__device__ float g_qkv [TOKENS * 3 * DMODEL];
__device__ float g_att [TOKENS * DMODEL];
__device__ float g_x1  [TOKENS * DMODEL];
__device__ float g_ffn [TOKENS * 4 * DMODEL];
__device__ float g_x2  [TOKENS * DMODEL];
__device__ float g_wqkvT[3 * DMODEL * DMODEL];
__device__ float g_woT  [DMODEL * DMODEL];
__device__ float g_w1T  [4 * DMODEL * DMODEL];
__device__ float g_w2T  [DMODEL * 4 * DMODEL];

__device__ __forceinline__ uint32_t smem_u32(const void* p) {
    uint32_t a;
    asm("{ .reg .u64 t; cvta.to.shared.u64 t, %1; cvt.u32.u64 %0, t; }"
        : "=r"(a) : "l"(p));
    return a;
}
__device__ __forceinline__ float to_tf32(float x) {
    float y; asm("cvt.rna.tf32.f32 %0, %1;" : "=f"(y) : "f"(x)); return y;
}
__device__ __forceinline__ float gelu_f(float x) {
    return 0.5f * x * (1.0f + erff(x * 0.70710678118654752f));
}

#define MMA_TF32(d, a, b) \
    asm volatile("mma.sync.aligned.m16n8k8.row.col.f32.tf32.tf32.f32 " \
      "{%0,%1,%2,%3}, {%4,%5,%6,%7}, {%8,%9}, {%0,%1,%2,%3};" \
      : "+f"((d)[0]), "+f"((d)[1]), "+f"((d)[2]), "+f"((d)[3]) \
      : "r"((a)[0]), "r"((a)[1]), "r"((a)[2]), "r"((a)[3]), \
        "r"((b)[0]), "r"((b)[1]))

#define CP_ASYNC16(dst, src) \
    asm volatile("cp.async.cg.shared.global [%0], [%1], 16;" \
                 :: "r"(dst), "l"(src))
#define CP_COMMIT() asm volatile("cp.async.commit_group;" ::: "memory")
#define CP_WAIT1()  asm volatile("cp.async.wait_group 1;" ::: "memory")
#define CP_WAIT0()  asm volatile("cp.async.wait_group 0;" ::: "memory")

// ---------------------------------------------------------------------------
// Weight transpose + RNA tf32 round: out[N][K] = tf32(in[K][N])
// ---------------------------------------------------------------------------
__global__ __launch_bounds__(256) void transpose_kernel(
    const float* __restrict__ in, float* __restrict__ out, int R, int C)
{
    __shared__ float t[32][33];
    const int bx = blockIdx.x * 32;
    const int by = blockIdx.y * 32;
    const int tx = threadIdx.x & 31, ty4 = (threadIdx.x >> 5) * 4;
    #pragma unroll
    for (int i = 0; i < 4; i++)
        t[ty4 + i][tx] = in[(size_t)(by + ty4 + i) * C + bx + tx];
    __syncthreads();
    #pragma unroll
    for (int i = 0; i < 4; i++)
        out[(size_t)(bx + ty4 + i) * R + by + tx] = to_tf32(t[tx][ty4 + i]);
}

// ---------------------------------------------------------------------------
// LayerNorm: one block per row of 768. ROUND=true -> output RNA tf32-exact
// (used when the output feeds a GEMM A operand).
// ---------------------------------------------------------------------------
template <bool ROUND>
__global__ __launch_bounds__(256) void ln_kernel(
    const float* __restrict__ x, const float* __restrict__ g,
    const float* __restrict__ b, float* __restrict__ o)
{
    __shared__ float red[32];
    const int t = threadIdx.x;
    const float* xr = x + (size_t)blockIdx.x * DMODEL;

    float v0 = xr[t], v1 = xr[t + 256], v2 = xr[t + 512];
    float s  = v0 + v1 + v2;
    float ss = v0 * v0 + v1 * v1 + v2 * v2;
    #pragma unroll
    for (int o2 = 16; o2 > 0; o2 >>= 1) {
        s  += __shfl_xor_sync(0xffffffffu, s,  o2);
        ss += __shfl_xor_sync(0xffffffffu, ss, o2);
    }
    const int w = t >> 5;
    if ((t & 31) == 0) { red[w] = s; red[16 + w] = ss; }
    __syncthreads();
    if (t == 0) {
        float S = 0.f, SS = 0.f;
        #pragma unroll
        for (int i = 0; i < 8; i++) { S += red[i]; SS += red[16 + i]; }
        red[0] = S; red[16] = SS;
    }
    __syncthreads();
    const float mean = red[0] * (1.0f / DMODEL);
    const float var  = red[16] * (1.0f / DMODEL) - mean * mean;
    const float inv  = rsqrtf(var + 1e-5f);

    float* orow = o + (size_t)blockIdx.x * DMODEL;
    float r0 = (v0 - mean) * inv * g[t]       + b[t];
    float r1 = (v1 - mean) * inv * g[t + 256] + b[t + 256];
    float r2 = (v2 - mean) * inv * g[t + 512] + b[t + 512];
    if (ROUND) { r0 = to_tf32(r0); r1 = to_tf32(r1); r2 = to_tf32(r2); }
    orow[t] = r0; orow[t + 256] = r1; orow[t + 512] = r2;
}

// ---------------------------------------------------------------------------
// tf32 mma.sync GEMM, cp.async pipelined: C(MxN) = A(MxK) @ Bt(NxK)^T + epi
// BM=128, 256 threads = 8 warps (2m x 4n).
//   BN=256: warp tile 64x64, 3-stage, 1 CTA/SM (deep-wave GEMMs)
//   BN=128: warp tile 64x32, 2-stage, 2 CTAs/SM (shallow-wave GEMMs)
// Operands are tf32-exact in memory (producers RNA-round) -> HW trunc no-op.
// MODE 0: tf32(AB) ; 1: +bias+res ; 2: tf32(gelu(+bias)) ; 3: gelu(+bias)+res
// ---------------------------------------------------------------------------
#define GBK 32
#define APAD 36

template <int MODE, int BN>
__global__ __launch_bounds__(256, (BN == 128) ? 2 : 1) void tc_gemm(
    const float* __restrict__ A, const float* __restrict__ Bt,
    float* __restrict__ C, int M, int N, int K,
    const float* __restrict__ bias, const float* __restrict__ res)
{
    constexpr int NT    = BN / 32;            // n-tiles per warp
    constexpr int NB    = BN / 32;            // B fill granules per thread
    constexpr int WNW   = BN / 4;             // warp n-width
    constexpr int NSTG  = (BN == 128) ? 2 : 3;
    constexpr int STG_A = 128 * APAD;
    constexpr int STG_B = BN * APAD;
    constexpr int STG_FL = STG_A + STG_B;

    extern __shared__ float gsm[];
    const uint32_t sb = smem_u32(gsm);

    const int tid = threadIdx.x;
    const int wid = tid >> 5, lane = tid & 31;
    const int g = lane >> 2, t = lane & 3;
    const int wm = wid >> 2, wn = wid & 3;
    const int bn = blockIdx.x, bm = blockIdx.y;

    const float* Ab = A  + (size_t)bm * 128 * K;
    const float* Bb = Bt + (size_t)bn * BN * K;

    const int fr = tid >> 3, fc16 = (tid & 7) * 4;

    float acc[4][NT][4];
    #pragma unroll
    for (int mt = 0; mt < 4; mt++)
        #pragma unroll
        for (int nt = 0; nt < NT; nt++)
            #pragma unroll
            for (int q = 0; q < 4; q++) acc[mt][nt][q] = 0.f;

    const int nch = K / GBK;

    auto fill = [&](int s, int c) {
        const uint32_t base = sb + (uint32_t)s * (STG_FL * 4);
        const int k0 = c * GBK;
        #pragma unroll
        for (int i = 0; i < 4; i++) {
            const int r = fr + i * 32;
            CP_ASYNC16(base + (uint32_t)(r * APAD + fc16) * 4,
                       Ab + (size_t)r * K + k0 + fc16);
        }
        #pragma unroll
        for (int i = 0; i < NB; i++) {
            const int r = fr + i * 32;
            CP_ASYNC16(base + (uint32_t)(STG_A + r * APAD + fc16) * 4,
                       Bb + (size_t)r * K + k0 + fc16);
        }
        CP_COMMIT();
    };

    fill(0, 0);
    fill(1, 1);

    int st = 0;
    for (int ch = 0; ch < nch; ch++) {
        if (ch >= nch - 1) { CP_WAIT0(); } else { CP_WAIT1(); }
        __syncthreads();
        if (NSTG == 3 && ch + 2 < nch)
            fill((st + 2 >= 3) ? st - 1 : st + 2, ch + 2);

        const float* As = gsm + st * STG_FL;
        const float* Bs = As + STG_A;

        #pragma unroll
        for (int kk = 0; kk < GBK; kk += 8) {
            uint32_t af[4][4];
            #pragma unroll
            for (int mt = 0; mt < 4; mt++) {
                const int rb = wm * 64 + mt * 16 + g;
                af[mt][0] = __float_as_uint(As[rb * APAD + kk + t]);
                af[mt][1] = __float_as_uint(As[(rb + 8) * APAD + kk + t]);
                af[mt][2] = __float_as_uint(As[rb * APAD + kk + t + 4]);
                af[mt][3] = __float_as_uint(As[(rb + 8) * APAD + kk + t + 4]);
            }
            uint32_t bf[NT][2];
            #pragma unroll
            for (int nt = 0; nt < NT; nt++) {
                const int nb = wn * WNW + nt * 8 + g;
                bf[nt][0] = __float_as_uint(Bs[nb * APAD + kk + t]);
                bf[nt][1] = __float_as_uint(Bs[nb * APAD + kk + t + 4]);
            }
            #pragma unroll
            for (int mt = 0; mt < 4; mt++)
                #pragma unroll
                for (int nt = 0; nt < NT; nt++)
                    MMA_TF32(acc[mt][nt], af[mt], bf[nt]);
        }

        if (NSTG == 2) {
            __syncthreads();
            if (ch + 2 < nch) fill(st, ch + 2);
        }
        st = (st + 1 == NSTG) ? 0 : st + 1;
    }

    // ---- epilogue ----
    #pragma unroll
    for (int mt = 0; mt < 4; mt++) {
        const int row = bm * 128 + wm * 64 + mt * 16 + g;
        #pragma unroll
        for (int nt = 0; nt < NT; nt++) {
            const int col = bn * BN + wn * WNW + nt * 8 + 2 * t;
            float v0 = acc[mt][nt][0], v1 = acc[mt][nt][1];
            float v2 = acc[mt][nt][2], v3 = acc[mt][nt][3];
            if (MODE >= 1) {
                const float2 bb = *(const float2*)&bias[col];
                v0 += bb.x; v1 += bb.y; v2 += bb.x; v3 += bb.y;
            }
            if (MODE >= 2) {
                v0 = gelu_f(v0); v1 = gelu_f(v1);
                v2 = gelu_f(v2); v3 = gelu_f(v3);
            }
            if (MODE == 0 || MODE == 2) {   // output feeds a GEMM/attention A|B
                v0 = to_tf32(v0); v1 = to_tf32(v1);
                v2 = to_tf32(v2); v3 = to_tf32(v3);
            }
            const size_t r0 = (size_t)row * N + col;
            const size_t r1 = (size_t)(row + 8) * N + col;
            if (MODE == 1 || MODE == 3) {
                const float2 ra = *(const float2*)&res[r0];
                const float2 rb2 = *(const float2*)&res[r1];
                v0 += ra.x; v1 += ra.y; v2 += rb2.x; v3 += rb2.y;
            }
            float2 o0; o0.x = v0; o0.y = v1;
            float2 o1; o1.x = v2; o1.y = v3;
            *(float2*)&C[r0] = o0;
            *(float2*)&C[r1] = o1;
        }
    }
}

// ---------------------------------------------------------------------------
// Attention on mma.sync tf32. CTA: 128 q x 64 kv, 256 thr. Warps 4m x 2n.
// qkv is tf32-exact (producer rounded). Q*scale and P are RNA-rounded.
// Output rounded (feeds o-proj GEMM). (B,H,N,DH) contiguous == (B,N,D) flat.
// ---------------------------------------------------------------------------
#define AQPAD 100
#define AVPAD 68
#define APPAD 68
#define SQ_OFF   0
#define SK_OFF   (128 * AQPAD)
#define SVT_OFF  (SK_OFF + 64 * AQPAD)
#define SP_OFF   (SVT_OFF + 96 * AVPAD)
#define SM_OFF   (SP_OFF + 128 * APPAD)
#define SL_OFF   (SM_OFF + 128)
#define SCR_OFF  (SL_OFF + 128)
#define RMX_OFF  (SCR_OFF + 128)
#define RSM_OFF  (RMX_OFF + 256)
#define ATTN_SMEM_BYTES ((RSM_OFF + 256) * 4)

__global__ __launch_bounds__(256) void attn_mma_kernel(
    const float* __restrict__ qkv, float* __restrict__ out)
{
    extern __shared__ float sm[];
    float* sQ   = sm + SQ_OFF;
    float* sK   = sm + SK_OFF;
    float* sVt  = sm + SVT_OFF;
    float* sP   = sm + SP_OFF;
    float* sM   = sm + SM_OFF;
    float* sL   = sm + SL_OFF;
    float* sCr  = sm + SCR_OFF;
    float* sRmx = sm + RMX_OFF;
    float* sRsm = sm + RSM_OFF;

    const int tid = threadIdx.x, lane = tid & 31, wid = tid >> 5;
    const int g = lane >> 2, t = lane & 3;
    const int wm = wid & 3, wn = wid >> 2;
    const int bh = blockIdx.y, b = bh >> 3, h = bh & 7;
    const int q0 = blockIdx.x * 128;

    const float* gQ = qkv + (size_t)b * NSEQ * (3 * DMODEL) + h * DHEAD;
    const float* gK = gQ + DMODEL;
    const float* gV = gQ + 2 * DMODEL;

    #pragma unroll
    for (int i = 0; i < 12; i++) {
        const int idx = tid + i * 256;
        const int r = idx / 24, c4 = (idx % 24) * 4;
        float4 v = *(const float4*)&gQ[(size_t)(q0 + r) * (3 * DMODEL) + c4];
        v.x = to_tf32(v.x * ATTN_SCALE); v.y = to_tf32(v.y * ATTN_SCALE);
        v.z = to_tf32(v.z * ATTN_SCALE); v.w = to_tf32(v.w * ATTN_SCALE);
        *(float4*)&sQ[r * AQPAD + c4] = v;
    }
    if (tid < 128) { sM[tid] = -1e30f; sL[tid] = 0.f; }

    const int rows[4] = {wm * 32 + g, wm * 32 + g + 8,
                         wm * 32 + 16 + g, wm * 32 + 24 + g};

    float o[2][6][4];
    #pragma unroll
    for (int mt = 0; mt < 2; mt++)
        #pragma unroll
        for (int nt = 0; nt < 6; nt++)
            #pragma unroll
            for (int q = 0; q < 4; q++) o[mt][nt][q] = 0.f;

    for (int kt = 0; kt < NSEQ; kt += 64) {
        __syncthreads();
        #pragma unroll
        for (int i = 0; i < 6; i++) {
            const int idx = tid + i * 256;
            const int r = idx / 24, c4 = (idx % 24) * 4;
            *(float4*)&sK[r * AQPAD + c4] =
                *(const float4*)&gK[(size_t)(kt + r) * (3 * DMODEL) + c4];
        }
        {
            const int kv = tid & 63;
            const int dbase = tid >> 6;
            #pragma unroll
            for (int j = 0; j < 6; j++) {
                const int d4 = j * 4 + dbase;
                float4 v = *(const float4*)&gV[(size_t)(kt + kv) * (3 * DMODEL) + d4 * 4];
                sVt[(d4 * 4 + 0) * AVPAD + kv] = v.x;
                sVt[(d4 * 4 + 1) * AVPAD + kv] = v.y;
                sVt[(d4 * 4 + 2) * AVPAD + kv] = v.z;
                sVt[(d4 * 4 + 3) * AVPAD + kv] = v.w;
            }
        }
        __syncthreads();

        float sacc[2][4][4];
        #pragma unroll
        for (int mt = 0; mt < 2; mt++)
            #pragma unroll
            for (int nt = 0; nt < 4; nt++)
                #pragma unroll
                for (int q = 0; q < 4; q++) sacc[mt][nt][q] = 0.f;

        #pragma unroll
        for (int k8 = 0; k8 < 96; k8 += 8) {
            uint32_t af[2][4];
            #pragma unroll
            for (int mt = 0; mt < 2; mt++) {
                const int rb = wm * 32 + mt * 16;
                af[mt][0] = __float_as_uint(sQ[(rb + g) * AQPAD + k8 + t]);
                af[mt][1] = __float_as_uint(sQ[(rb + g + 8) * AQPAD + k8 + t]);
                af[mt][2] = __float_as_uint(sQ[(rb + g) * AQPAD + k8 + t + 4]);
                af[mt][3] = __float_as_uint(sQ[(rb + g + 8) * AQPAD + k8 + t + 4]);
            }
            uint32_t bf[4][2];
            #pragma unroll
            for (int nt = 0; nt < 4; nt++) {
                const int nb = wn * 32 + nt * 8 + g;
                bf[nt][0] = __float_as_uint(sK[nb * AQPAD + k8 + t]);
                bf[nt][1] = __float_as_uint(sK[nb * AQPAD + k8 + t + 4]);
            }
            #pragma unroll
            for (int mt = 0; mt < 2; mt++)
                #pragma unroll
                for (int nt = 0; nt < 4; nt++)
                    MMA_TF32(sacc[mt][nt], af[mt], bf[nt]);
        }

        float rmax[4];
        #pragma unroll
        for (int mt = 0; mt < 2; mt++) {
            float m0 = sacc[mt][0][0], m1 = sacc[mt][0][2];
            #pragma unroll
            for (int nt = 0; nt < 4; nt++) {
                m0 = fmaxf(m0, fmaxf(sacc[mt][nt][0], sacc[mt][nt][1]));
                m1 = fmaxf(m1, fmaxf(sacc[mt][nt][2], sacc[mt][nt][3]));
            }
            rmax[mt * 2] = m0; rmax[mt * 2 + 1] = m1;
        }
        #pragma unroll
        for (int q = 0; q < 4; q++) {
            rmax[q] = fmaxf(rmax[q], __shfl_xor_sync(0xffffffffu, rmax[q], 1));
            rmax[q] = fmaxf(rmax[q], __shfl_xor_sync(0xffffffffu, rmax[q], 2));
        }
        if (t == 0) {
            #pragma unroll
            for (int q = 0; q < 4; q++) sRmx[rows[q] * 2 + wn] = rmax[q];
        }
        __syncthreads();

        float mnew[4], corr[4];
        #pragma unroll
        for (int q = 0; q < 4; q++) {
            const float mo = sM[rows[q]];
            mnew[q] = fmaxf(mo, fmaxf(sRmx[rows[q] * 2], sRmx[rows[q] * 2 + 1]));
            corr[q] = __expf(mo - mnew[q]);
        }
        float psum[4] = {0.f, 0.f, 0.f, 0.f};
        #pragma unroll
        for (int mt = 0; mt < 2; mt++) {
            #pragma unroll
            for (int nt = 0; nt < 4; nt++) {
                const float p0 = __expf(sacc[mt][nt][0] - mnew[mt * 2]);
                const float p1 = __expf(sacc[mt][nt][1] - mnew[mt * 2]);
                const float p2 = __expf(sacc[mt][nt][2] - mnew[mt * 2 + 1]);
                const float p3 = __expf(sacc[mt][nt][3] - mnew[mt * 2 + 1]);
                psum[mt * 2] += p0 + p1;
                psum[mt * 2 + 1] += p2 + p3;
                const int col = wn * 32 + nt * 8 + 2 * t;
                float2 v0; v0.x = to_tf32(p0); v0.y = to_tf32(p1);
                float2 v1; v1.x = to_tf32(p2); v1.y = to_tf32(p3);
                *(float2*)&sP[(wm * 32 + mt * 16 + g) * APPAD + col] = v0;
                *(float2*)&sP[(wm * 32 + mt * 16 + g + 8) * APPAD + col] = v1;
            }
        }
        #pragma unroll
        for (int q = 0; q < 4; q++) {
            psum[q] += __shfl_xor_sync(0xffffffffu, psum[q], 1);
            psum[q] += __shfl_xor_sync(0xffffffffu, psum[q], 2);
        }
        if (t == 0) {
            #pragma unroll
            for (int q = 0; q < 4; q++) sRsm[rows[q] * 2 + wn] = psum[q];
        }
        __syncthreads();
        if (wn == 0 && t == 0) {
            #pragma unroll
            for (int q = 0; q < 4; q++) {
                const int r = rows[q];
                sL[r] = sL[r] * corr[q] + sRsm[r * 2] + sRsm[r * 2 + 1];
                sM[r] = mnew[q];
                sCr[r] = corr[q];
            }
        }
        __syncthreads();

        float cr[4];
        #pragma unroll
        for (int q = 0; q < 4; q++) cr[q] = sCr[rows[q]];
        #pragma unroll
        for (int mt = 0; mt < 2; mt++)
            #pragma unroll
            for (int nt = 0; nt < 6; nt++) {
                o[mt][nt][0] *= cr[mt * 2];     o[mt][nt][1] *= cr[mt * 2];
                o[mt][nt][2] *= cr[mt * 2 + 1]; o[mt][nt][3] *= cr[mt * 2 + 1];
            }
        #pragma unroll
        for (int k8 = 0; k8 < 64; k8 += 8) {
            uint32_t af[2][4];
            #pragma unroll
            for (int mt = 0; mt < 2; mt++) {
                const int rb = wm * 32 + mt * 16;
                af[mt][0] = __float_as_uint(sP[(rb + g) * APPAD + k8 + t]);
                af[mt][1] = __float_as_uint(sP[(rb + g + 8) * APPAD + k8 + t]);
                af[mt][2] = __float_as_uint(sP[(rb + g) * APPAD + k8 + t + 4]);
                af[mt][3] = __float_as_uint(sP[(rb + g + 8) * APPAD + k8 + t + 4]);
            }
            uint32_t bf[6][2];
            #pragma unroll
            for (int nt = 0; nt < 6; nt++) {
                const int nb = wn * 48 + nt * 8 + g;
                bf[nt][0] = __float_as_uint(sVt[nb * AVPAD + k8 + t]);
                bf[nt][1] = __float_as_uint(sVt[nb * AVPAD + k8 + t + 4]);
            }
            #pragma unroll
            for (int mt = 0; mt < 2; mt++)
                #pragma unroll
                for (int nt = 0; nt < 6; nt++)
                    MMA_TF32(o[mt][nt], af[mt], bf[nt]);
        }
    }

    float invl[4];
    #pragma unroll
    for (int q = 0; q < 4; q++) invl[q] = 1.0f / sL[rows[q]];

    float* gO = out + ((size_t)bh * NSEQ + q0) * DHEAD;
    #pragma unroll
    for (int mt = 0; mt < 2; mt++) {
        const int rlo = wm * 32 + mt * 16 + g;
        const int rhi = rlo + 8;
        #pragma unroll
        for (int nt = 0; nt < 6; nt++) {
            const int col = wn * 48 + nt * 8 + 2 * t;
            float2 v0; v0.x = to_tf32(o[mt][nt][0] * invl[mt * 2]);
            v0.y = to_tf32(o[mt][nt][1] * invl[mt * 2]);
            float2 v1; v1.x = to_tf32(o[mt][nt][2] * invl[mt * 2 + 1]);
            v1.y = to_tf32(o[mt][nt][3] * invl[mt * 2 + 1]);
            *(float2*)&gO[(size_t)rlo * DHEAD + col] = v0;
            *(float2*)&gO[(size_t)rhi * DHEAD + col] = v1;
        }
    }
}

// ---------------------------------------------------------------------------
// Launcher
// ---------------------------------------------------------------------------
#define SMEM_G256 (3 * (128 + 256) * APAD * 4)   // 165888
#define SMEM_G128 (2 * (128 + 128) * APAD * 4)   // 73728

extern "C" void kernel_launch(void* const* d_in, const int* in_sizes, int n_in,
                              void* d_out, int out_size)
{
    (void)in_sizes; (void)n_in; (void)out_size;
    const float* x     = (const float*)d_in[0];
    const float* w_qkv = (const float*)d_in[1];
    const float* w_o   = (const float*)d_in[2];
    const float* b_o   = (const float*)d_in[3];
    const float* w1    = (const float*)d_in[4];
    const float* b1    = (const float*)d_in[5];
    const float* w2    = (const float*)d_in[6];
    const float* b2    = (const float*)d_in[7];
    const float* g1    = (const float*)d_in[8];
    const float* be1   = (const float*)d_in[9];
    const float* gm    = (const float*)d_in[10];
    const float* bm    = (const float*)d_in[11];
    const float* g3    = (const float*)d_in[12];
    const float* be3   = (const float*)d_in[13];

    float *ln, *qkv, *att, *x1, *ffn, *x2;
    float *wqkvT, *woT, *w1T, *w2T;
    cudaGetSymbolAddress((void**)&ln,    g_ln);
    cudaGetSymbolAddress((void**)&qkv,   g_qkv);
    cudaGetSymbolAddress((void**)&att,   g_att);
    cudaGetSymbolAddress((void**)&x1,    g_x1);
    cudaGetSymbolAddress((void**)&ffn,   g_ffn);
    cudaGetSymbolAddress((void**)&x2,    g_x2);
    cudaGetSymbolAddress((void**)&wqkvT, g_wqkvT);
    cudaGetSymbolAddress((void**)&woT,   g_woT);
    cudaGetSymbolAddress((void**)&w1T,   g_w1T);
    cudaGetSymbolAddress((void**)&w2T,   g_w2T);

    cudaFuncSetAttribute(attn_mma_kernel,
        cudaFuncAttributeMaxDynamicSharedMemorySize, ATTN_SMEM_BYTES);
    cudaFuncSetAttribute(tc_gemm<0, 256>,
        cudaFuncAttributeMaxDynamicSharedMemorySize, SMEM_G256);
    cudaFuncSetAttribute(tc_gemm<2, 256>,
        cudaFuncAttributeMaxDynamicSharedMemorySize, SMEM_G256);
    cudaFuncSetAttribute(tc_gemm<1, 128>,
        cudaFuncAttributeMaxDynamicSharedMemorySize, SMEM_G128);
    cudaFuncSetAttribute(tc_gemm<3, 128>,
        cudaFuncAttributeMaxDynamicSharedMemorySize, SMEM_G128);

    // 0. transpose + tf32-round weights to [N][K]
    transpose_kernel<<<dim3(2304 / 32,  768 / 32), 256>>>(w_qkv, wqkvT,  768, 2304);
    transpose_kernel<<<dim3( 768 / 32,  768 / 32), 256>>>(w_o,   woT,    768,  768);
    transpose_kernel<<<dim3(3072 / 32,  768 / 32), 256>>>(w1,    w1T,    768, 3072);
    transpose_kernel<<<dim3( 768 / 32, 3072 / 32), 256>>>(w2,    w2T,   3072,  768);

    // 1. h = tf32(LN1(x))
    ln_kernel<true><<<TOKENS, 256>>>(x, g1, be1, ln);
    // 2. qkv = tf32(h @ w_qkv)        (8192 x 2304, K=768)
    tc_gemm<0, 256><<<dim3(2304 / 256, TOKENS / 128), 256, SMEM_G256>>>(
        ln, wqkvT, qkv, TOKENS, 2304, 768, nullptr, nullptr);
    // 3. attention -> tf32, (B,H,N,DH) contiguous == (B,N,D) flat
    attn_mma_kernel<<<dim3(NSEQ / 128, 64), 256, ATTN_SMEM_BYTES>>>(qkv, att);
    // 4. x1 = att @ w_o + b_o + x     (8192 x 768, K=768)
    tc_gemm<1, 128><<<dim3(768 / 128, TOKENS / 128), 256, SMEM_G128>>>(
        att, woT, x1, TOKENS, 768, 768, b_o, x);
    // 5. h = tf32(LN2(x1))
    ln_kernel<true><<<TOKENS, 256>>>(x1, gm, bm, ln);
    // 6. ffn = tf32(gelu(h @ w1 + b1)) (8192 x 3072, K=768)
    tc_gemm<2, 256><<<dim3(3072 / 256, TOKENS / 128), 256, SMEM_G256>>>(
        ln, w1T, ffn, TOKENS, 3072, 768, b1, nullptr);
    // 7. x2 = gelu(ffn @ w2 + b2) + x1 (8192 x 768, K=3072)
    tc_gemm<3, 128><<<dim3(768 / 128, TOKENS / 128), 256, SMEM_G128>>>(
        ffn, w2T, x2, TOKENS, 768, 3072, b2, x1);
    // 8. out = LN3(x2)
    ln_kernel<false><<<TOKENS, 256>>>(x2, g3, be3, (float*)d_out);
}

// round 7
// speedup vs baseline: 3.8197x; 1.0047x over previous
#include <cuda_runtime.h>
#include <cuda_bf16.h>
#include <math.h>
#include <stdint.h>

// ---------------------------------------------------------------------------
// EncoderBlock: B=8, N=1024, D=768, H=8, DH=96
// Round 7: attention with pair-scoped named barriers (1 full sync/tile),
// double-buffered K (cp.async) + V (register prefetch); GEMMs 4-stage (BN=256)
// and 3-stage (BN=128, 2 CTAs/SM). Producer-side RNA tf32 rounding kept.
// ---------------------------------------------------------------------------

#define TOKENS 8192
#define DMODEL 768
#define NSEQ   1024
#define NHEAD  8
#define DHEAD  96
#define ATTN_SCALE 0.10206207261596577f   // 1/sqrt(96)

// ---------------- scratch ---------------------------------------------------
__device__ float g_ln  [TOKENS * DMODEL];
__device__ float g_qkv [TOKENS * 3 * DMODEL];
__device__ float g_att [TOKENS * DMODEL];
__device__ float g_x1  [TOKENS * DMODEL];
__device__ float g_ffn [TOKENS * 4 * DMODEL];
__device__ float g_x2  [TOKENS * DMODEL];
__device__ float g_wqkvT[3 * DMODEL * DMODEL];
__device__ float g_woT  [DMODEL * DMODEL];
__device__ float g_w1T  [4 * DMODEL * DMODEL];
__device__ float g_w2T  [DMODEL * 4 * DMODEL];

__device__ __forceinline__ uint32_t smem_u32(const void* p) {
    uint32_t a;
    asm("{ .reg .u64 t; cvta.to.shared.u64 t, %1; cvt.u32.u64 %0, t; }"
        : "=r"(a) : "l"(p));
    return a;
}
__device__ __forceinline__ float to_tf32(float x) {
    float y; asm("cvt.rna.tf32.f32 %0, %1;" : "=f"(y) : "f"(x)); return y;
}
__device__ __forceinline__ float gelu_f(float x) {
    return 0.5f * x * (1.0f + erff(x * 0.70710678118654752f));
}

#define MMA_TF32(d, a, b) \
    asm volatile("mma.sync.aligned.m16n8k8.row.col.f32.tf32.tf32.f32 " \
      "{%0,%1,%2,%3}, {%4,%5,%6,%7}, {%8,%9}, {%0,%1,%2,%3};" \
      : "+f"((d)[0]), "+f"((d)[1]), "+f"((d)[2]), "+f"((d)[3]) \
      : "r"((a)[0]), "r"((a)[1]), "r"((a)[2]), "r"((a)[3]), \
        "r"((b)[0]), "r"((b)[1]))

#define CP_ASYNC16(dst, src) \
    asm volatile("cp.async.cg.shared.global [%0], [%1], 16;" \
                 :: "r"(dst), "l"(src))
#define CP_COMMIT() asm volatile("cp.async.commit_group;" ::: "memory")
#define CP_WAIT0()  asm volatile("cp.async.wait_group 0;" ::: "memory")
#define CP_WAIT1()  asm volatile("cp.async.wait_group 1;" ::: "memory")
#define CP_WAIT2()  asm volatile("cp.async.wait_group 2;" ::: "memory")

#define PAIR_BAR(id) \
    asm volatile("bar.sync %0, 64;" :: "r"(id) : "memory")

// ---------------------------------------------------------------------------
// Weight transpose + RNA tf32 round: out[N][K] = tf32(in[K][N])
// ---------------------------------------------------------------------------
__global__ __launch_bounds__(256) void transpose_kernel(
    const float* __restrict__ in, float* __restrict__ out, int R, int C)
{
    __shared__ float t[32][33];
    const int bx = blockIdx.x * 32;
    const int by = blockIdx.y * 32;
    const int tx = threadIdx.x & 31, ty4 = (threadIdx.x >> 5) * 4;
    #pragma unroll
    for (int i = 0; i < 4; i++)
        t[ty4 + i][tx] = in[(size_t)(by + ty4 + i) * C + bx + tx];
    __syncthreads();
    #pragma unroll
    for (int i = 0; i < 4; i++)
        out[(size_t)(bx + ty4 + i) * R + by + tx] = to_tf32(t[tx][ty4 + i]);
}

// ---------------------------------------------------------------------------
// LayerNorm: one block per row of 768. ROUND -> tf32-exact output.
// ---------------------------------------------------------------------------
template <bool ROUND>
__global__ __launch_bounds__(256) void ln_kernel(
    const float* __restrict__ x, const float* __restrict__ g,
    const float* __restrict__ b, float* __restrict__ o)
{
    __shared__ float red[32];
    const int t = threadIdx.x;
    const float* xr = x + (size_t)blockIdx.x * DMODEL;

    float v0 = xr[t], v1 = xr[t + 256], v2 = xr[t + 512];
    float s  = v0 + v1 + v2;
    float ss = v0 * v0 + v1 * v1 + v2 * v2;
    #pragma unroll
    for (int o2 = 16; o2 > 0; o2 >>= 1) {
        s  += __shfl_xor_sync(0xffffffffu, s,  o2);
        ss += __shfl_xor_sync(0xffffffffu, ss, o2);
    }
    const int w = t >> 5;
    if ((t & 31) == 0) { red[w] = s; red[16 + w] = ss; }
    __syncthreads();
    if (t == 0) {
        float S = 0.f, SS = 0.f;
        #pragma unroll
        for (int i = 0; i < 8; i++) { S += red[i]; SS += red[16 + i]; }
        red[0] = S; red[16] = SS;
    }
    __syncthreads();
    const float mean = red[0] * (1.0f / DMODEL);
    const float var  = red[16] * (1.0f / DMODEL) - mean * mean;
    const float inv  = rsqrtf(var + 1e-5f);

    float* orow = o + (size_t)blockIdx.x * DMODEL;
    float r0 = (v0 - mean) * inv * g[t]       + b[t];
    float r1 = (v1 - mean) * inv * g[t + 256] + b[t + 256];
    float r2 = (v2 - mean) * inv * g[t + 512] + b[t + 512];
    if (ROUND) { r0 = to_tf32(r0); r1 = to_tf32(r1); r2 = to_tf32(r2); }
    orow[t] = r0; orow[t + 256] = r1; orow[t + 512] = r2;
}

// ---------------------------------------------------------------------------
// tf32 mma.sync GEMM, cp.async pipelined: C(MxN) = A(MxK) @ Bt(NxK)^T + epi
// BM=128, 256 threads = 8 warps (2m x 4n).
//   BN=256: warp 64x64, 4-stage, 1 CTA/SM
//   BN=128: warp 64x32, 3-stage, 2 CTAs/SM
// MODE 0: tf32(AB) ; 1: +bias+res ; 2: tf32(gelu(+bias)) ; 3: gelu(+bias)+res
// ---------------------------------------------------------------------------
#define GBK 32
#define APAD 36

template <int MODE, int BN>
__global__ __launch_bounds__(256, (BN == 128) ? 2 : 1) void tc_gemm(
    const float* __restrict__ A, const float* __restrict__ Bt,
    float* __restrict__ C, int M, int N, int K,
    const float* __restrict__ bias, const float* __restrict__ res)
{
    constexpr int NT    = BN / 32;
    constexpr int NB    = BN / 32;
    constexpr int WNW   = BN / 4;
    constexpr int NSTG  = (BN == 128) ? 3 : 4;
    constexpr int STG_A = 128 * APAD;
    constexpr int STG_B = BN * APAD;
    constexpr int STG_FL = STG_A + STG_B;

    extern __shared__ float gsm[];
    const uint32_t sb = smem_u32(gsm);

    const int tid = threadIdx.x;
    const int wid = tid >> 5, lane = tid & 31;
    const int g = lane >> 2, t = lane & 3;
    const int wm = wid >> 2, wn = wid & 3;
    const int bn = blockIdx.x, bm = blockIdx.y;

    const float* Ab = A  + (size_t)bm * 128 * K;
    const float* Bb = Bt + (size_t)bn * BN * K;

    const int fr = tid >> 3, fc16 = (tid & 7) * 4;

    float acc[4][NT][4];
    #pragma unroll
    for (int mt = 0; mt < 4; mt++)
        #pragma unroll
        for (int nt = 0; nt < NT; nt++)
            #pragma unroll
            for (int q = 0; q < 4; q++) acc[mt][nt][q] = 0.f;

    const int nch = K / GBK;

    auto fill = [&](int s, int c) {
        const uint32_t base = sb + (uint32_t)s * (STG_FL * 4);
        const int k0 = c * GBK;
        #pragma unroll
        for (int i = 0; i < 4; i++) {
            const int r = fr + i * 32;
            CP_ASYNC16(base + (uint32_t)(r * APAD + fc16) * 4,
                       Ab + (size_t)r * K + k0 + fc16);
        }
        #pragma unroll
        for (int i = 0; i < NB; i++) {
            const int r = fr + i * 32;
            CP_ASYNC16(base + (uint32_t)(STG_A + r * APAD + fc16) * 4,
                       Bb + (size_t)r * K + k0 + fc16);
        }
        CP_COMMIT();
    };

    #pragma unroll
    for (int i = 0; i < NSTG - 1; i++) fill(i, i);

    int st = 0;
    for (int ch = 0; ch < nch; ch++) {
        const int pend = (ch + NSTG - 1 < nch) ? (NSTG - 2) : (nch - 1 - ch);
        if (pend <= 0) { CP_WAIT0(); }
        else if (pend == 1) { CP_WAIT1(); }
        else { CP_WAIT2(); }
        __syncthreads();
        if (ch + NSTG - 1 < nch)
            fill((st + NSTG - 1) % NSTG, ch + NSTG - 1);

        const float* As = gsm + st * STG_FL;
        const float* Bs = As + STG_A;

        #pragma unroll
        for (int kk = 0; kk < GBK; kk += 8) {
            uint32_t af[4][4];
            #pragma unroll
            for (int mt = 0; mt < 4; mt++) {
                const int rb = wm * 64 + mt * 16 + g;
                af[mt][0] = __float_as_uint(As[rb * APAD + kk + t]);
                af[mt][1] = __float_as_uint(As[(rb + 8) * APAD + kk + t]);
                af[mt][2] = __float_as_uint(As[rb * APAD + kk + t + 4]);
                af[mt][3] = __float_as_uint(As[(rb + 8) * APAD + kk + t + 4]);
            }
            uint32_t bf[NT][2];
            #pragma unroll
            for (int nt = 0; nt < NT; nt++) {
                const int nb = wn * WNW + nt * 8 + g;
                bf[nt][0] = __float_as_uint(Bs[nb * APAD + kk + t]);
                bf[nt][1] = __float_as_uint(Bs[nb * APAD + kk + t + 4]);
            }
            #pragma unroll
            for (int mt = 0; mt < 4; mt++)
                #pragma unroll
                for (int nt = 0; nt < NT; nt++)
                    MMA_TF32(acc[mt][nt], af[mt], bf[nt]);
        }
        st = (st + 1 == NSTG) ? 0 : st + 1;
    }

    // ---- epilogue ----
    #pragma unroll
    for (int mt = 0; mt < 4; mt++) {
        const int row = bm * 128 + wm * 64 + mt * 16 + g;
        #pragma unroll
        for (int nt = 0; nt < NT; nt++) {
            const int col = bn * BN + wn * WNW + nt * 8 + 2 * t;
            float v0 = acc[mt][nt][0], v1 = acc[mt][nt][1];
            float v2 = acc[mt][nt][2], v3 = acc[mt][nt][3];
            if (MODE >= 1) {
                const float2 bb = *(const float2*)&bias[col];
                v0 += bb.x; v1 += bb.y; v2 += bb.x; v3 += bb.y;
            }
            if (MODE >= 2) {
                v0 = gelu_f(v0); v1 = gelu_f(v1);
                v2 = gelu_f(v2); v3 = gelu_f(v3);
            }
            if (MODE == 0 || MODE == 2) {
                v0 = to_tf32(v0); v1 = to_tf32(v1);
                v2 = to_tf32(v2); v3 = to_tf32(v3);
            }
            const size_t r0 = (size_t)row * N + col;
            const size_t r1 = (size_t)(row + 8) * N + col;
            if (MODE == 1 || MODE == 3) {
                const float2 ra = *(const float2*)&res[r0];
                const float2 rb2 = *(const float2*)&res[r1];
                v0 += ra.x; v1 += ra.y; v2 += rb2.x; v3 += rb2.y;
            }
            float2 o0; o0.x = v0; o0.y = v1;
            float2 o1; o1.x = v2; o1.y = v3;
            *(float2*)&C[r0] = o0;
            *(float2*)&C[r1] = o1;
        }
    }
}

// ---------------------------------------------------------------------------
// Attention, mma.sync tf32. CTA: 128 q x 64 kv, 256 thr, warps 4m x 2n.
// Double-buffered K (cp.async) + Vt (register prefetch). Row stats (m,l) in
// registers replicated across the 8 owning threads; cross-warp-pair combine
// via sRmx/sRsm + named pair barriers. One full __syncthreads per tile.
// ---------------------------------------------------------------------------
#define AQPAD 100
#define AVPAD 68
#define APPAD 68
#define SKT   (64 * AQPAD)     // 6400 floats / K buffer
#define SVTT  (96 * AVPAD)     // 6528 floats / Vt buffer
#define SQ_OFF   0
#define SK_OFF   (128 * AQPAD)                 // 12800
#define SVT_OFF  (SK_OFF + 2 * SKT)            // 25600
#define SP_OFF   (SVT_OFF + 2 * SVTT)          // 38656
#define RMX_OFF  (SP_OFF + 128 * APPAD)        // 47360
#define RSM_OFF  (RMX_OFF + 256)
#define ATTN_SMEM_BYTES ((RSM_OFF + 256) * 4)  // 191488 B

__global__ __launch_bounds__(256, 1) void attn_mma_kernel(
    const float* __restrict__ qkv, float* __restrict__ out)
{
    extern __shared__ float sm[];
    float* sQ   = sm + SQ_OFF;
    float* sK   = sm + SK_OFF;
    float* sVt  = sm + SVT_OFF;
    float* sP   = sm + SP_OFF;
    float* sRmx = sm + RMX_OFF;
    float* sRsm = sm + RSM_OFF;
    const uint32_t sb = smem_u32(sm);

    const int tid = threadIdx.x, lane = tid & 31, wid = tid >> 5;
    const int g = lane >> 2, t = lane & 3;
    const int wm = wid & 3, wn = wid >> 2;
    const int barid = 1 + wm;
    const int bh = blockIdx.y, b = bh >> 3, h = bh & 7;
    const int q0 = blockIdx.x * 128;

    const float* gQ = qkv + (size_t)b * NSEQ * (3 * DMODEL) + h * DHEAD;
    const float* gK = gQ + DMODEL;
    const float* gV = gQ + 2 * DMODEL;

    // K fill indices (cp.async): 64 rows x 24 granules = 1536 / 256 thr = 6
    const int kvv = tid & 63, dbase = tid >> 6;

    auto fillK = [&](int buf, int kt) {
        const uint32_t base = sb + (uint32_t)(SK_OFF + buf * SKT) * 4;
        #pragma unroll
        for (int i = 0; i < 6; i++) {
            const int idx = tid + i * 256;
            const int r = idx / 24, c4 = (idx % 24) * 4;
            CP_ASYNC16(base + (uint32_t)(r * AQPAD + c4) * 4,
                       gK + (size_t)(kt + r) * (3 * DMODEL) + c4);
        }
        CP_COMMIT();
    };

    // ---- prologue: Q (scaled, rounded), K0 (async), Vt0 ----
    fillK(0, 0);
    #pragma unroll
    for (int j = 0; j < 6; j++) {
        const int d4 = j * 4 + dbase;
        float4 v = *(const float4*)&gV[(size_t)kvv * (3 * DMODEL) + d4 * 4];
        sVt[(d4 * 4 + 0) * AVPAD + kvv] = v.x;
        sVt[(d4 * 4 + 1) * AVPAD + kvv] = v.y;
        sVt[(d4 * 4 + 2) * AVPAD + kvv] = v.z;
        sVt[(d4 * 4 + 3) * AVPAD + kvv] = v.w;
    }
    #pragma unroll
    for (int i = 0; i < 12; i++) {
        const int idx = tid + i * 256;
        const int r = idx / 24, c4 = (idx % 24) * 4;
        float4 v = *(const float4*)&gQ[(size_t)(q0 + r) * (3 * DMODEL) + c4];
        v.x = to_tf32(v.x * ATTN_SCALE); v.y = to_tf32(v.y * ATTN_SCALE);
        v.z = to_tf32(v.z * ATTN_SCALE); v.w = to_tf32(v.w * ATTN_SCALE);
        *(float4*)&sQ[r * AQPAD + c4] = v;
    }
    CP_WAIT0();
    __syncthreads();

    const int rows[4] = {wm * 32 + g, wm * 32 + g + 8,
                         wm * 32 + 16 + g, wm * 32 + 24 + g};

    float m_r[4] = {-1e30f, -1e30f, -1e30f, -1e30f};
    float l_r[4] = {0.f, 0.f, 0.f, 0.f};

    float o[2][6][4];
    #pragma unroll
    for (int mt = 0; mt < 2; mt++)
        #pragma unroll
        for (int nt = 0; nt < 6; nt++)
            #pragma unroll
            for (int q = 0; q < 4; q++) o[mt][nt][q] = 0.f;

    const int NTILE = NSEQ / 64;
    for (int it = 0; it < NTILE; it++) {
        const int cur = it & 1, alt = cur ^ 1;
        const bool pre = (it + 1 < NTILE);

        // prefetch next tile: K via cp.async, V into registers
        float4 vreg[6];
        if (pre) {
            const int ktn = (it + 1) * 64;
            fillK(alt, ktn);
            #pragma unroll
            for (int j = 0; j < 6; j++) {
                const int d4 = j * 4 + dbase;
                vreg[j] = *(const float4*)
                    &gV[(size_t)(ktn + kvv) * (3 * DMODEL) + d4 * 4];
            }
        }

        // ---- S = Q K^T ----
        const float* Kb = sK + cur * SKT;
        float sacc[2][4][4];
        #pragma unroll
        for (int mt = 0; mt < 2; mt++)
            #pragma unroll
            for (int nt = 0; nt < 4; nt++)
                #pragma unroll
                for (int q = 0; q < 4; q++) sacc[mt][nt][q] = 0.f;

        #pragma unroll
        for (int k8 = 0; k8 < 96; k8 += 8) {
            uint32_t af[2][4];
            #pragma unroll
            for (int mt = 0; mt < 2; mt++) {
                const int rb = wm * 32 + mt * 16;
                af[mt][0] = __float_as_uint(sQ[(rb + g) * AQPAD + k8 + t]);
                af[mt][1] = __float_as_uint(sQ[(rb + g + 8) * AQPAD + k8 + t]);
                af[mt][2] = __float_as_uint(sQ[(rb + g) * AQPAD + k8 + t + 4]);
                af[mt][3] = __float_as_uint(sQ[(rb + g + 8) * AQPAD + k8 + t + 4]);
            }
            uint32_t bf[4][2];
            #pragma unroll
            for (int nt = 0; nt < 4; nt++) {
                const int nb = wn * 32 + nt * 8 + g;
                bf[nt][0] = __float_as_uint(Kb[nb * AQPAD + k8 + t]);
                bf[nt][1] = __float_as_uint(Kb[nb * AQPAD + k8 + t + 4]);
            }
            #pragma unroll
            for (int mt = 0; mt < 2; mt++)
                #pragma unroll
                for (int nt = 0; nt < 4; nt++)
                    MMA_TF32(sacc[mt][nt], af[mt], bf[nt]);
        }

        // ---- softmax: pair-scoped combine ----
        float rmax[4];
        #pragma unroll
        for (int mt = 0; mt < 2; mt++) {
            float m0 = sacc[mt][0][0], m1 = sacc[mt][0][2];
            #pragma unroll
            for (int nt = 0; nt < 4; nt++) {
                m0 = fmaxf(m0, fmaxf(sacc[mt][nt][0], sacc[mt][nt][1]));
                m1 = fmaxf(m1, fmaxf(sacc[mt][nt][2], sacc[mt][nt][3]));
            }
            rmax[mt * 2] = m0; rmax[mt * 2 + 1] = m1;
        }
        #pragma unroll
        for (int q = 0; q < 4; q++) {
            rmax[q] = fmaxf(rmax[q], __shfl_xor_sync(0xffffffffu, rmax[q], 1));
            rmax[q] = fmaxf(rmax[q], __shfl_xor_sync(0xffffffffu, rmax[q], 2));
        }
        if (t == 0) {
            #pragma unroll
            for (int q = 0; q < 4; q++) sRmx[rows[q] * 2 + wn] = rmax[q];
        }
        PAIR_BAR(barid);

        float mnew[4], corr[4];
        #pragma unroll
        for (int q = 0; q < 4; q++) {
            const float tmx = fmaxf(sRmx[rows[q] * 2], sRmx[rows[q] * 2 + 1]);
            mnew[q] = fmaxf(m_r[q], tmx);
            corr[q] = __expf(m_r[q] - mnew[q]);
        }
        float psum[4] = {0.f, 0.f, 0.f, 0.f};
        #pragma unroll
        for (int mt = 0; mt < 2; mt++) {
            #pragma unroll
            for (int nt = 0; nt < 4; nt++) {
                const float p0 = __expf(sacc[mt][nt][0] - mnew[mt * 2]);
                const float p1 = __expf(sacc[mt][nt][1] - mnew[mt * 2]);
                const float p2 = __expf(sacc[mt][nt][2] - mnew[mt * 2 + 1]);
                const float p3 = __expf(sacc[mt][nt][3] - mnew[mt * 2 + 1]);
                psum[mt * 2] += p0 + p1;
                psum[mt * 2 + 1] += p2 + p3;
                const int col = wn * 32 + nt * 8 + 2 * t;
                float2 v0; v0.x = to_tf32(p0); v0.y = to_tf32(p1);
                float2 v1; v1.x = to_tf32(p2); v1.y = to_tf32(p3);
                *(float2*)&sP[(wm * 32 + mt * 16 + g) * APPAD + col] = v0;
                *(float2*)&sP[(wm * 32 + mt * 16 + g + 8) * APPAD + col] = v1;
            }
        }
        #pragma unroll
        for (int q = 0; q < 4; q++) {
            psum[q] += __shfl_xor_sync(0xffffffffu, psum[q], 1);
            psum[q] += __shfl_xor_sync(0xffffffffu, psum[q], 2);
        }
        if (t == 0) {
            #pragma unroll
            for (int q = 0; q < 4; q++) sRsm[rows[q] * 2 + wn] = psum[q];
        }
        PAIR_BAR(barid);

        #pragma unroll
        for (int q = 0; q < 4; q++) {
            l_r[q] = l_r[q] * corr[q] + sRsm[rows[q] * 2] + sRsm[rows[q] * 2 + 1];
            m_r[q] = mnew[q];
        }

        // ---- O = O*corr + P V ----
        #pragma unroll
        for (int mt = 0; mt < 2; mt++)
            #pragma unroll
            for (int nt = 0; nt < 6; nt++) {
                o[mt][nt][0] *= corr[mt * 2];     o[mt][nt][1] *= corr[mt * 2];
                o[mt][nt][2] *= corr[mt * 2 + 1]; o[mt][nt][3] *= corr[mt * 2 + 1];
            }
        const float* Vb = sVt + cur * SVTT;
        #pragma unroll
        for (int k8 = 0; k8 < 64; k8 += 8) {
            uint32_t af[2][4];
            #pragma unroll
            for (int mt = 0; mt < 2; mt++) {
                const int rb = wm * 32 + mt * 16;
                af[mt][0] = __float_as_uint(sP[(rb + g) * APPAD + k8 + t]);
                af[mt][1] = __float_as_uint(sP[(rb + g + 8) * APPAD + k8 + t]);
                af[mt][2] = __float_as_uint(sP[(rb + g) * APPAD + k8 + t + 4]);
                af[mt][3] = __float_as_uint(sP[(rb + g + 8) * APPAD + k8 + t + 4]);
            }
            uint32_t bf[6][2];
            #pragma unroll
            for (int nt = 0; nt < 6; nt++) {
                const int nb = wn * 48 + nt * 8 + g;
                bf[nt][0] = __float_as_uint(Vb[nb * AVPAD + k8 + t]);
                bf[nt][1] = __float_as_uint(Vb[nb * AVPAD + k8 + t + 4]);
            }
            #pragma unroll
            for (int mt = 0; mt < 2; mt++)
                #pragma unroll
                for (int nt = 0; nt < 6; nt++)
                    MMA_TF32(o[mt][nt], af[mt], bf[nt]);
        }

        // store prefetched V to alt buffer; wait K cp.async; full sync
        if (pre) {
            float* Va = sVt + alt * SVTT;
            #pragma unroll
            for (int j = 0; j < 6; j++) {
                const int d4 = j * 4 + dbase;
                Va[(d4 * 4 + 0) * AVPAD + kvv] = vreg[j].x;
                Va[(d4 * 4 + 1) * AVPAD + kvv] = vreg[j].y;
                Va[(d4 * 4 + 2) * AVPAD + kvv] = vreg[j].z;
                Va[(d4 * 4 + 3) * AVPAD + kvv] = vreg[j].w;
            }
            CP_WAIT0();
        }
        __syncthreads();
    }

    // ---- epilogue: normalize, round (feeds o-proj), write (B,H,N,DH) ----
    float invl[4];
    #pragma unroll
    for (int q = 0; q < 4; q++) invl[q] = 1.0f / l_r[q];

    float* gO = out + ((size_t)bh * NSEQ + q0) * DHEAD;
    #pragma unroll
    for (int mt = 0; mt < 2; mt++) {
        const int rlo = wm * 32 + mt * 16 + g;
        const int rhi = rlo + 8;
        #pragma unroll
        for (int nt = 0; nt < 6; nt++) {
            const int col = wn * 48 + nt * 8 + 2 * t;
            float2 v0; v0.x = to_tf32(o[mt][nt][0] * invl[mt * 2]);
            v0.y = to_tf32(o[mt][nt][1] * invl[mt * 2]);
            float2 v1; v1.x = to_tf32(o[mt][nt][2] * invl[mt * 2 + 1]);
            v1.y = to_tf32(o[mt][nt][3] * invl[mt * 2 + 1]);
            *(float2*)&gO[(size_t)rlo * DHEAD + col] = v0;
            *(float2*)&gO[(size_t)rhi * DHEAD + col] = v1;
        }
    }
}

// ---------------------------------------------------------------------------
// Launcher
// ---------------------------------------------------------------------------
#define SMEM_G256 (4 * (128 + 256) * APAD * 4)   // 221184
#define SMEM_G128 (3 * (128 + 128) * APAD * 4)   // 110592

extern "C" void kernel_launch(void* const* d_in, const int* in_sizes, int n_in,
                              void* d_out, int out_size)
{
    (void)in_sizes; (void)n_in; (void)out_size;
    const float* x     = (const float*)d_in[0];
    const float* w_qkv = (const float*)d_in[1];
    const float* w_o   = (const float*)d_in[2];
    const float* b_o   = (const float*)d_in[3];
    const float* w1    = (const float*)d_in[4];
    const float* b1    = (const float*)d_in[5];
    const float* w2    = (const float*)d_in[6];
    const float* b2    = (const float*)d_in[7];
    const float* g1    = (const float*)d_in[8];
    const float* be1   = (const float*)d_in[9];
    const float* gm    = (const float*)d_in[10];
    const float* bm    = (const float*)d_in[11];
    const float* g3    = (const float*)d_in[12];
    const float* be3   = (const float*)d_in[13];

    float *ln, *qkv, *att, *x1, *ffn, *x2;
    float *wqkvT, *woT, *w1T, *w2T;
    cudaGetSymbolAddress((void**)&ln,    g_ln);
    cudaGetSymbolAddress((void**)&qkv,   g_qkv);
    cudaGetSymbolAddress((void**)&att,   g_att);
    cudaGetSymbolAddress((void**)&x1,    g_x1);
    cudaGetSymbolAddress((void**)&ffn,   g_ffn);
    cudaGetSymbolAddress((void**)&x2,    g_x2);
    cudaGetSymbolAddress((void**)&wqkvT, g_wqkvT);
    cudaGetSymbolAddress((void**)&woT,   g_woT);
    cudaGetSymbolAddress((void**)&w1T,   g_w1T);
    cudaGetSymbolAddress((void**)&w2T,   g_w2T);

    cudaFuncSetAttribute(attn_mma_kernel,
        cudaFuncAttributeMaxDynamicSharedMemorySize, ATTN_SMEM_BYTES);
    cudaFuncSetAttribute(tc_gemm<0, 256>,
        cudaFuncAttributeMaxDynamicSharedMemorySize, SMEM_G256);
    cudaFuncSetAttribute(tc_gemm<2, 256>,
        cudaFuncAttributeMaxDynamicSharedMemorySize, SMEM_G256);
    cudaFuncSetAttribute(tc_gemm<1, 128>,
        cudaFuncAttributeMaxDynamicSharedMemorySize, SMEM_G128);
    cudaFuncSetAttribute(tc_gemm<3, 128>,
        cudaFuncAttributeMaxDynamicSharedMemorySize, SMEM_G128);

    // 0. transpose + tf32-round weights to [N][K]
    transpose_kernel<<<dim3(2304 / 32,  768 / 32), 256>>>(w_qkv, wqkvT,  768, 2304);
    transpose_kernel<<<dim3( 768 / 32,  768 / 32), 256>>>(w_o,   woT,    768,  768);
    transpose_kernel<<<dim3(3072 / 32,  768 / 32), 256>>>(w1,    w1T,    768, 3072);
    transpose_kernel<<<dim3( 768 / 32, 3072 / 32), 256>>>(w2,    w2T,   3072,  768);

    // 1. h = tf32(LN1(x))
    ln_kernel<true><<<TOKENS, 256>>>(x, g1, be1, ln);
    // 2. qkv = tf32(h @ w_qkv)        (8192 x 2304, K=768)
    tc_gemm<0, 256><<<dim3(2304 / 256, TOKENS / 128), 256, SMEM_G256>>>(
        ln, wqkvT, qkv, TOKENS, 2304, 768, nullptr, nullptr);
    // 3. attention -> tf32, (B,H,N,DH) contiguous == (B,N,D) flat
    attn_mma_kernel<<<dim3(NSEQ / 128, 64), 256, ATTN_SMEM_BYTES>>>(qkv, att);
    // 4. x1 = att @ w_o + b_o + x     (8192 x 768, K=768)
    tc_gemm<1, 128><<<dim3(768 / 128, TOKENS / 128), 256, SMEM_G128>>>(
        att, woT, x1, TOKENS, 768, 768, b_o, x);
    // 5. h = tf32(LN2(x1))
    ln_kernel<true><<<TOKENS, 256>>>(x1, gm, bm, ln);
    // 6. ffn = tf32(gelu(h @ w1 + b1)) (8192 x 3072, K=768)
    tc_gemm<2, 256><<<dim3(3072 / 256, TOKENS / 128), 256, SMEM_G256>>>(
        ln, w1T, ffn, TOKENS, 3072, 768, b1, nullptr);
    // 7. x2 = gelu(ffn @ w2 + b2) + x1 (8192 x 768, K=3072)
    tc_gemm<3, 128><<<dim3(768 / 128, TOKENS / 128), 256, SMEM_G128>>>(
        ffn, w2T, x2, TOKENS, 768, 3072, b2, x1);
    // 8. out = LN3(x2)
    ln_kernel<false><<<TOKENS, 256>>>(x2, g3, be3, (float*)d_out);
}

// round 8
// speedup vs baseline: 6.8254x; 1.7869x over previous
#include <cuda_runtime.h>
#include <cuda_fp16.h>
#include <math.h>
#include <stdint.h>

// ---------------------------------------------------------------------------
// EncoderBlock: B=8, N=1024, D=768, H=8, DH=96
// Round 8: all tensor math on fp16 m16n8k16 (f32 accum). fp16 mantissa ==
// tf32 mantissa, so precision matches R7; MMA instruction count halves.
// Intermediates stored half (smem + DRAM traffic halves; attention 2 CTA/SM).
// ---------------------------------------------------------------------------

#define TOKENS 8192
#define DMODEL 768
#define NSEQ   1024
#define NHEAD  8
#define DHEAD  96
#define ATTN_SCALE 0.10206207261596577f   // 1/sqrt(96)

// ---------------- scratch ---------------------------------------------------
__device__ __half g_ln  [TOKENS * DMODEL];
__device__ __half g_qkv [TOKENS * 3 * DMODEL];
__device__ __half g_att [TOKENS * DMODEL];
__device__ float  g_x1  [TOKENS * DMODEL];
__device__ __half g_ffn [TOKENS * 4 * DMODEL];
__device__ float  g_x2  [TOKENS * DMODEL];
__device__ __half g_wqkvT[3 * DMODEL * DMODEL];
__device__ __half g_woT  [DMODEL * DMODEL];
__device__ __half g_w1T  [4 * DMODEL * DMODEL];
__device__ __half g_w2T  [DMODEL * 4 * DMODEL];

__device__ __forceinline__ uint32_t smem_u32(const void* p) {
    uint32_t a;
    asm("{ .reg .u64 t; cvta.to.shared.u64 t, %1; cvt.u32.u64 %0, t; }"
        : "=r"(a) : "l"(p));
    return a;
}
__device__ __forceinline__ uint32_t f2h2(float lo, float hi) {
    __half2 h = __floats2half2_rn(lo, hi);
    return *reinterpret_cast<uint32_t*>(&h);
}
__device__ __forceinline__ float gelu_f(float x) {
    return 0.5f * x * (1.0f + erff(x * 0.70710678118654752f));
}

#define MMA_F16(d, a, b) \
    asm volatile("mma.sync.aligned.m16n8k16.row.col.f32.f16.f16.f32 " \
      "{%0,%1,%2,%3}, {%4,%5,%6,%7}, {%8,%9}, {%0,%1,%2,%3};" \
      : "+f"((d)[0]), "+f"((d)[1]), "+f"((d)[2]), "+f"((d)[3]) \
      : "r"((a)[0]), "r"((a)[1]), "r"((a)[2]), "r"((a)[3]), \
        "r"((b)[0]), "r"((b)[1]))

#define CP_ASYNC16(dst, src) \
    asm volatile("cp.async.cg.shared.global [%0], [%1], 16;" \
                 :: "r"(dst), "l"(src))
#define CP_COMMIT() asm volatile("cp.async.commit_group;" ::: "memory")
#define CP_WAIT0()  asm volatile("cp.async.wait_group 0;" ::: "memory")
#define CP_WAIT1()  asm volatile("cp.async.wait_group 1;" ::: "memory")
#define CP_WAIT2()  asm volatile("cp.async.wait_group 2;" ::: "memory")

#define PAIR_BAR(id) \
    asm volatile("bar.sync %0, 64;" :: "r"(id) : "memory")

// ---------------------------------------------------------------------------
// Weight transpose + RN half round: out[N][K] = half(in[K][N])
// ---------------------------------------------------------------------------
__global__ __launch_bounds__(256) void transpose_kernel(
    const float* __restrict__ in, __half* __restrict__ out, int R, int C)
{
    __shared__ float t[32][33];
    const int bx = blockIdx.x * 32;
    const int by = blockIdx.y * 32;
    const int tx = threadIdx.x & 31, ty4 = (threadIdx.x >> 5) * 4;
    #pragma unroll
    for (int i = 0; i < 4; i++)
        t[ty4 + i][tx] = in[(size_t)(by + ty4 + i) * C + bx + tx];
    __syncthreads();
    #pragma unroll
    for (int i = 0; i < 4; i++)
        out[(size_t)(bx + ty4 + i) * R + by + tx] = __float2half_rn(t[tx][ty4 + i]);
}

// ---------------------------------------------------------------------------
// LayerNorm: one block per row of 768. HALF_OUT -> half output (feeds GEMM).
// ---------------------------------------------------------------------------
template <bool HALF_OUT>
__global__ __launch_bounds__(256) void ln_kernel(
    const float* __restrict__ x, const float* __restrict__ g,
    const float* __restrict__ b, void* __restrict__ o)
{
    __shared__ float red[32];
    const int t = threadIdx.x;
    const float* xr = x + (size_t)blockIdx.x * DMODEL;

    float v0 = xr[t], v1 = xr[t + 256], v2 = xr[t + 512];
    float s  = v0 + v1 + v2;
    float ss = v0 * v0 + v1 * v1 + v2 * v2;
    #pragma unroll
    for (int o2 = 16; o2 > 0; o2 >>= 1) {
        s  += __shfl_xor_sync(0xffffffffu, s,  o2);
        ss += __shfl_xor_sync(0xffffffffu, ss, o2);
    }
    const int w = t >> 5;
    if ((t & 31) == 0) { red[w] = s; red[16 + w] = ss; }
    __syncthreads();
    if (t == 0) {
        float S = 0.f, SS = 0.f;
        #pragma unroll
        for (int i = 0; i < 8; i++) { S += red[i]; SS += red[16 + i]; }
        red[0] = S; red[16] = SS;
    }
    __syncthreads();
    const float mean = red[0] * (1.0f / DMODEL);
    const float var  = red[16] * (1.0f / DMODEL) - mean * mean;
    const float inv  = rsqrtf(var + 1e-5f);

    float r0 = (v0 - mean) * inv * g[t]       + b[t];
    float r1 = (v1 - mean) * inv * g[t + 256] + b[t + 256];
    float r2 = (v2 - mean) * inv * g[t + 512] + b[t + 512];
    if (HALF_OUT) {
        __half* orow = (__half*)o + (size_t)blockIdx.x * DMODEL;
        orow[t]       = __float2half_rn(r0);
        orow[t + 256] = __float2half_rn(r1);
        orow[t + 512] = __float2half_rn(r2);
    } else {
        float* orow = (float*)o + (size_t)blockIdx.x * DMODEL;
        orow[t] = r0; orow[t + 256] = r1; orow[t + 512] = r2;
    }
}

// ---------------------------------------------------------------------------
// fp16 mma.sync GEMM, cp.async pipelined: C(MxN) = A(MxK) @ Bt(NxK)^T + epi
// BM=128, 256 threads = 8 warps (2m x 4n). GBK=64 halves (4 k16-steps).
//   BN=256: warp 64x64, 4-stage, 1 CTA/SM
//   BN=128: warp 64x32, 3-stage, 2 CTAs/SM
// smem rows: 32 words data + 4 pad = 36 (bank 4g+t, conflict-free).
// MODE 0: half(AB) ; 1: f32 AB+bias+res ; 2: half(gelu(AB+bias)) ;
// MODE 3: f32 gelu(AB+bias)+res
// ---------------------------------------------------------------------------
#define GBK 64

template <int MODE, int BN>
__global__ __launch_bounds__(256, (BN == 128) ? 2 : 1) void tc_gemm(
    const __half* __restrict__ A, const __half* __restrict__ Bt,
    void* __restrict__ Cv, int M, int N, int K,
    const float* __restrict__ bias, const float* __restrict__ res)
{
    constexpr int NT     = BN / 32;
    constexpr int WNW    = BN / 4;
    constexpr int NSTG   = (BN == 128) ? 3 : 4;
    constexpr int STG_AW = 128 * 36;
    constexpr int STG_BW = BN * 36;
    constexpr int STG_W  = STG_AW + STG_BW;

    extern __shared__ uint32_t dynsm[];
    const uint32_t sb = smem_u32(dynsm);

    const int tid = threadIdx.x;
    const int wid = tid >> 5, lane = tid & 31;
    const int g = lane >> 2, t = lane & 3;
    const int wm = wid >> 2, wn = wid & 3;
    const int bn = blockIdx.x, bm = blockIdx.y;

    const __half* Ab = A  + (size_t)bm * 128 * K;
    const __half* Bb = Bt + (size_t)bn * BN * K;

    float acc[4][NT][4];
    #pragma unroll
    for (int mt = 0; mt < 4; mt++)
        #pragma unroll
        for (int nt = 0; nt < NT; nt++)
            #pragma unroll
            for (int q = 0; q < 4; q++) acc[mt][nt][q] = 0.f;

    const int nch = K / GBK;

    auto fill = [&](int s, int c) {
        const uint32_t base = sb + (uint32_t)(s * STG_W) * 4;
        const int k0 = c * GBK;
        #pragma unroll
        for (int i = 0; i < 4; i++) {
            const int idx = tid + i * 256;
            const int r = idx >> 3, gr = idx & 7;
            CP_ASYNC16(base + (uint32_t)(r * 36 + gr * 4) * 4,
                       Ab + (size_t)r * K + k0 + gr * 8);
        }
        #pragma unroll
        for (int i = 0; i < BN / 32; i++) {
            const int idx = tid + i * 256;
            const int r = idx >> 3, gr = idx & 7;
            CP_ASYNC16(base + (uint32_t)(STG_AW + r * 36 + gr * 4) * 4,
                       Bb + (size_t)r * K + k0 + gr * 8);
        }
        CP_COMMIT();
    };

    #pragma unroll
    for (int i = 0; i < NSTG - 1; i++) fill(i, i);

    int st = 0;
    for (int ch = 0; ch < nch; ch++) {
        const int pend = (ch + NSTG - 1 < nch) ? (NSTG - 2) : (nch - 1 - ch);
        if (pend <= 0) { CP_WAIT0(); }
        else if (pend == 1) { CP_WAIT1(); }
        else { CP_WAIT2(); }
        __syncthreads();
        if (ch + NSTG - 1 < nch)
            fill((st + NSTG - 1) % NSTG, ch + NSTG - 1);

        const uint32_t* As = dynsm + st * STG_W;
        const uint32_t* Bs = As + STG_AW;

        #pragma unroll
        for (int ks = 0; ks < 4; ks++) {
            const int kw = ks * 8;
            uint32_t af[4][4];
            #pragma unroll
            for (int mt = 0; mt < 4; mt++) {
                const int rb = wm * 64 + mt * 16 + g;
                af[mt][0] = As[rb * 36 + kw + t];
                af[mt][1] = As[(rb + 8) * 36 + kw + t];
                af[mt][2] = As[rb * 36 + kw + 4 + t];
                af[mt][3] = As[(rb + 8) * 36 + kw + 4 + t];
            }
            uint32_t bf[NT][2];
            #pragma unroll
            for (int nt = 0; nt < NT; nt++) {
                const int nb = wn * WNW + nt * 8 + g;
                bf[nt][0] = Bs[nb * 36 + kw + t];
                bf[nt][1] = Bs[nb * 36 + kw + 4 + t];
            }
            #pragma unroll
            for (int mt = 0; mt < 4; mt++)
                #pragma unroll
                for (int nt = 0; nt < NT; nt++)
                    MMA_F16(acc[mt][nt], af[mt], bf[nt]);
        }
        st = (st + 1 == NSTG) ? 0 : st + 1;
    }

    // ---- epilogue ----
    __half* Ch = (__half*)Cv;
    float*  Cf = (float*)Cv;
    #pragma unroll
    for (int mt = 0; mt < 4; mt++) {
        const int row = bm * 128 + wm * 64 + mt * 16 + g;
        #pragma unroll
        for (int nt = 0; nt < NT; nt++) {
            const int col = bn * BN + wn * WNW + nt * 8 + 2 * t;
            float v0 = acc[mt][nt][0], v1 = acc[mt][nt][1];
            float v2 = acc[mt][nt][2], v3 = acc[mt][nt][3];
            if (MODE >= 1) {
                const float2 bb = *(const float2*)&bias[col];
                v0 += bb.x; v1 += bb.y; v2 += bb.x; v3 += bb.y;
            }
            if (MODE >= 2) {
                v0 = gelu_f(v0); v1 = gelu_f(v1);
                v2 = gelu_f(v2); v3 = gelu_f(v3);
            }
            const size_t r0 = (size_t)row * N + col;
            const size_t r1 = (size_t)(row + 8) * N + col;
            if (MODE == 0 || MODE == 2) {
                *(uint32_t*)&Ch[r0] = f2h2(v0, v1);
                *(uint32_t*)&Ch[r1] = f2h2(v2, v3);
            } else {
                const float2 ra = *(const float2*)&res[r0];
                const float2 rb2 = *(const float2*)&res[r1];
                v0 += ra.x; v1 += ra.y; v2 += rb2.x; v3 += rb2.y;
                float2 o0; o0.x = v0; o0.y = v1;
                float2 o1; o1.x = v2; o1.y = v3;
                *(float2*)&Cf[r0] = o0;
                *(float2*)&Cf[r1] = o1;
            }
        }
    }
}

// ---------------------------------------------------------------------------
// Attention, fp16 mma. CTA: 128 q x 64 kv, 256 thr, warps 4m x 2n, 2 CTA/SM.
// Word-layout smem: sQ/sK stride 52 (bank 20g+t), sVt/sP stride 36 (4g+t).
// Double-buffered K (cp.async) + Vt (register prefetch); pair barriers.
// Output half, contiguous (B,H,N,DH) == faithful reshape (B,N,D).
// ---------------------------------------------------------------------------
#define SQW   0
#define SKW   (128 * 52)                  // 6656
#define SKT_W (64 * 52)                   // 3328 per buffer
#define SVW   (SKW + 2 * SKT_W)           // 13312
#define SVT_W (96 * 36)                   // 3456 per buffer
#define SPW   (SVW + 2 * SVT_W)           // 20224
#define RMXW  (SPW + 128 * 36)            // 24832
#define RSMW  (RMXW + 256)
#define ATTN_SMEM_BYTES ((RSMW + 256) * 4)  // 101376 B

__global__ __launch_bounds__(256, 2) void attn_mma_kernel(
    const __half* __restrict__ qkv, __half* __restrict__ out)
{
    extern __shared__ uint32_t dynsm[];
    uint32_t* sQw = dynsm + SQW;
    uint32_t* sKw = dynsm + SKW;
    uint32_t* sPw = dynsm + SPW;
    float* sRmx = (float*)(dynsm + RMXW);
    float* sRsm = (float*)(dynsm + RSMW);
    const uint32_t sb = smem_u32(dynsm);

    const int tid = threadIdx.x, lane = tid & 31, wid = tid >> 5;
    const int g = lane >> 2, t = lane & 3;
    const int wm = wid & 3, wn = wid >> 2;
    const int barid = 1 + wm;
    const int bh = blockIdx.y, b = bh >> 3, h = bh & 7;
    const int q0 = blockIdx.x * 128;

    const __half* gQ = qkv + (size_t)b * NSEQ * (3 * DMODEL) + h * DHEAD;
    const __half* gK = gQ + DMODEL;
    const __half* gV = gQ + 2 * DMODEL;

    const int kvv = tid & 63, dpart = tid >> 6;

    auto fillK = [&](int buf, int kt) {
        const uint32_t base = sb + (uint32_t)(SKW + buf * SKT_W) * 4;
        #pragma unroll
        for (int i = 0; i < 3; i++) {
            const int idx = tid + i * 256;
            const int r = idx / 12, gr = idx % 12;
            CP_ASYNC16(base + (uint32_t)(r * 52 + gr * 4) * 4,
                       gK + (size_t)(kt + r) * (3 * DMODEL) + gr * 8);
        }
        CP_COMMIT();
    };
    auto storeV = [&](int buf, const float4* raw) {
        __half* sVh = (__half*)(dynsm + SVW + buf * SVT_W);
        #pragma unroll
        for (int j = 0; j < 3; j++) {
            const int d8 = dpart * 3 + j;
            const __half* hh = (const __half*)&raw[j];
            #pragma unroll
            for (int e = 0; e < 8; e++)
                sVh[(d8 * 8 + e) * 72 + kvv] = hh[e];
        }
    };

    // ---- prologue: K0 async; V0; Q (scaled, RN-rounded) ----
    fillK(0, 0);
    {
        float4 raw[3];
        #pragma unroll
        for (int j = 0; j < 3; j++) {
            const int d8 = dpart * 3 + j;
            raw[j] = *(const float4*)&gV[(size_t)kvv * (3 * DMODEL) + d8 * 8];
        }
        storeV(0, raw);
    }
    #pragma unroll
    for (int i = 0; i < 6; i++) {
        const int idx = tid + i * 256;
        const int r = idx / 12, gr = idx % 12;
        float4 raw = *(const float4*)&gQ[(size_t)(q0 + r) * (3 * DMODEL) + gr * 8];
        const __half2* hp = (const __half2*)&raw;
        #pragma unroll
        for (int e = 0; e < 4; e++) {
            float2 f = __half22float2(hp[e]);
            sQw[r * 52 + gr * 4 + e] = f2h2(f.x * ATTN_SCALE, f.y * ATTN_SCALE);
        }
    }
    CP_WAIT0();
    __syncthreads();

    const int rows[4] = {wm * 32 + g, wm * 32 + g + 8,
                         wm * 32 + 16 + g, wm * 32 + 24 + g};

    float m_r[4] = {-1e30f, -1e30f, -1e30f, -1e30f};
    float l_r[4] = {0.f, 0.f, 0.f, 0.f};

    float o[2][6][4];
    #pragma unroll
    for (int mt = 0; mt < 2; mt++)
        #pragma unroll
        for (int nt = 0; nt < 6; nt++)
            #pragma unroll
            for (int q = 0; q < 4; q++) o[mt][nt][q] = 0.f;

    const int NTILE = NSEQ / 64;
    for (int it = 0; it < NTILE; it++) {
        const int cur = it & 1, alt = cur ^ 1;
        const bool pre = (it + 1 < NTILE);

        float4 vreg[3];
        if (pre) {
            const int ktn = (it + 1) * 64;
            fillK(alt, ktn);
            #pragma unroll
            for (int j = 0; j < 3; j++) {
                const int d8 = dpart * 3 + j;
                vreg[j] = *(const float4*)
                    &gV[(size_t)(ktn + kvv) * (3 * DMODEL) + d8 * 8];
            }
        }

        // ---- S = Q K^T (6 k16 steps over d=96) ----
        const uint32_t* Kb = sKw + cur * SKT_W;
        float sacc[2][4][4];
        #pragma unroll
        for (int mt = 0; mt < 2; mt++)
            #pragma unroll
            for (int nt = 0; nt < 4; nt++)
                #pragma unroll
                for (int q = 0; q < 4; q++) sacc[mt][nt][q] = 0.f;

        #pragma unroll
        for (int ks = 0; ks < 6; ks++) {
            const int kw = ks * 8;
            uint32_t af[2][4];
            #pragma unroll
            for (int mt = 0; mt < 2; mt++) {
                const int rb = wm * 32 + mt * 16;
                af[mt][0] = sQw[(rb + g) * 52 + kw + t];
                af[mt][1] = sQw[(rb + g + 8) * 52 + kw + t];
                af[mt][2] = sQw[(rb + g) * 52 + kw + 4 + t];
                af[mt][3] = sQw[(rb + g + 8) * 52 + kw + 4 + t];
            }
            uint32_t bf[4][2];
            #pragma unroll
            for (int nt = 0; nt < 4; nt++) {
                const int nb = wn * 32 + nt * 8 + g;
                bf[nt][0] = Kb[nb * 52 + kw + t];
                bf[nt][1] = Kb[nb * 52 + kw + 4 + t];
            }
            #pragma unroll
            for (int mt = 0; mt < 2; mt++)
                #pragma unroll
                for (int nt = 0; nt < 4; nt++)
                    MMA_F16(sacc[mt][nt], af[mt], bf[nt]);
        }

        // ---- softmax: pair-scoped combine ----
        float rmax[4];
        #pragma unroll
        for (int mt = 0; mt < 2; mt++) {
            float m0 = sacc[mt][0][0], m1 = sacc[mt][0][2];
            #pragma unroll
            for (int nt = 0; nt < 4; nt++) {
                m0 = fmaxf(m0, fmaxf(sacc[mt][nt][0], sacc[mt][nt][1]));
                m1 = fmaxf(m1, fmaxf(sacc[mt][nt][2], sacc[mt][nt][3]));
            }
            rmax[mt * 2] = m0; rmax[mt * 2 + 1] = m1;
        }
        #pragma unroll
        for (int q = 0; q < 4; q++) {
            rmax[q] = fmaxf(rmax[q], __shfl_xor_sync(0xffffffffu, rmax[q], 1));
            rmax[q] = fmaxf(rmax[q], __shfl_xor_sync(0xffffffffu, rmax[q], 2));
        }
        if (t == 0) {
            #pragma unroll
            for (int q = 0; q < 4; q++) sRmx[rows[q] * 2 + wn] = rmax[q];
        }
        PAIR_BAR(barid);

        float mnew[4], corr[4];
        #pragma unroll
        for (int q = 0; q < 4; q++) {
            const float tmx = fmaxf(sRmx[rows[q] * 2], sRmx[rows[q] * 2 + 1]);
            mnew[q] = fmaxf(m_r[q], tmx);
            corr[q] = __expf(m_r[q] - mnew[q]);
        }
        float psum[4] = {0.f, 0.f, 0.f, 0.f};
        #pragma unroll
        for (int mt = 0; mt < 2; mt++) {
            #pragma unroll
            for (int nt = 0; nt < 4; nt++) {
                const float p0 = __expf(sacc[mt][nt][0] - mnew[mt * 2]);
                const float p1 = __expf(sacc[mt][nt][1] - mnew[mt * 2]);
                const float p2 = __expf(sacc[mt][nt][2] - mnew[mt * 2 + 1]);
                const float p3 = __expf(sacc[mt][nt][3] - mnew[mt * 2 + 1]);
                psum[mt * 2] += p0 + p1;
                psum[mt * 2 + 1] += p2 + p3;
                const int cw = wn * 16 + nt * 4 + t;
                sPw[(wm * 32 + mt * 16 + g) * 36 + cw] = f2h2(p0, p1);
                sPw[(wm * 32 + mt * 16 + g + 8) * 36 + cw] = f2h2(p2, p3);
            }
        }
        #pragma unroll
        for (int q = 0; q < 4; q++) {
            psum[q] += __shfl_xor_sync(0xffffffffu, psum[q], 1);
            psum[q] += __shfl_xor_sync(0xffffffffu, psum[q], 2);
        }
        if (t == 0) {
            #pragma unroll
            for (int q = 0; q < 4; q++) sRsm[rows[q] * 2 + wn] = psum[q];
        }
        PAIR_BAR(barid);

        #pragma unroll
        for (int q = 0; q < 4; q++) {
            l_r[q] = l_r[q] * corr[q] + sRsm[rows[q] * 2] + sRsm[rows[q] * 2 + 1];
            m_r[q] = mnew[q];
        }

        // ---- O = O*corr + P V (4 k16 steps over kv=64) ----
        #pragma unroll
        for (int mt = 0; mt < 2; mt++)
            #pragma unroll
            for (int nt = 0; nt < 6; nt++) {
                o[mt][nt][0] *= corr[mt * 2];     o[mt][nt][1] *= corr[mt * 2];
                o[mt][nt][2] *= corr[mt * 2 + 1]; o[mt][nt][3] *= corr[mt * 2 + 1];
            }
        const uint32_t* Vb = dynsm + SVW + cur * SVT_W;
        #pragma unroll
        for (int ks = 0; ks < 4; ks++) {
            const int kw = ks * 8;
            uint32_t af[2][4];
            #pragma unroll
            for (int mt = 0; mt < 2; mt++) {
                const int rb = wm * 32 + mt * 16;
                af[mt][0] = sPw[(rb + g) * 36 + kw + t];
                af[mt][1] = sPw[(rb + g + 8) * 36 + kw + t];
                af[mt][2] = sPw[(rb + g) * 36 + kw + 4 + t];
                af[mt][3] = sPw[(rb + g + 8) * 36 + kw + 4 + t];
            }
            uint32_t bf[6][2];
            #pragma unroll
            for (int nt = 0; nt < 6; nt++) {
                const int nb = wn * 48 + nt * 8 + g;
                bf[nt][0] = Vb[nb * 36 + kw + t];
                bf[nt][1] = Vb[nb * 36 + kw + 4 + t];
            }
            #pragma unroll
            for (int mt = 0; mt < 2; mt++)
                #pragma unroll
                for (int nt = 0; nt < 6; nt++)
                    MMA_F16(o[mt][nt], af[mt], bf[nt]);
        }

        if (pre) {
            storeV(alt, vreg);
            CP_WAIT0();
        }
        __syncthreads();
    }

    // ---- epilogue: normalize, half output, (B,H,N,DH) contiguous ----
    float invl[4];
    #pragma unroll
    for (int q = 0; q < 4; q++) invl[q] = 1.0f / l_r[q];

    __half* gO = out + ((size_t)bh * NSEQ + q0) * DHEAD;
    #pragma unroll
    for (int mt = 0; mt < 2; mt++) {
        const int rlo = wm * 32 + mt * 16 + g;
        const int rhi = rlo + 8;
        #pragma unroll
        for (int nt = 0; nt < 6; nt++) {
            const int col = wn * 48 + nt * 8 + 2 * t;
            *(uint32_t*)&gO[(size_t)rlo * DHEAD + col] =
                f2h2(o[mt][nt][0] * invl[mt * 2], o[mt][nt][1] * invl[mt * 2]);
            *(uint32_t*)&gO[(size_t)rhi * DHEAD + col] =
                f2h2(o[mt][nt][2] * invl[mt * 2 + 1], o[mt][nt][3] * invl[mt * 2 + 1]);
        }
    }
}

// ---------------------------------------------------------------------------
// Launcher
// ---------------------------------------------------------------------------
#define SMEM_G256 (4 * (128 + 256) * 36 * 4)   // 221184
#define SMEM_G128 (3 * (128 + 128) * 36 * 4)   // 110592

extern "C" void kernel_launch(void* const* d_in, const int* in_sizes, int n_in,
                              void* d_out, int out_size)
{
    (void)in_sizes; (void)n_in; (void)out_size;
    const float* x     = (const float*)d_in[0];
    const float* w_qkv = (const float*)d_in[1];
    const float* w_o   = (const float*)d_in[2];
    const float* b_o   = (const float*)d_in[3];
    const float* w1    = (const float*)d_in[4];
    const float* b1    = (const float*)d_in[5];
    const float* w2    = (const float*)d_in[6];
    const float* b2    = (const float*)d_in[7];
    const float* g1    = (const float*)d_in[8];
    const float* be1   = (const float*)d_in[9];
    const float* gm    = (const float*)d_in[10];
    const float* bm    = (const float*)d_in[11];
    const float* g3    = (const float*)d_in[12];
    const float* be3   = (const float*)d_in[13];

    __half *ln, *qkv, *att, *ffn, *wqkvT, *woT, *w1T, *w2T;
    float *x1, *x2;
    cudaGetSymbolAddress((void**)&ln,    g_ln);
    cudaGetSymbolAddress((void**)&qkv,   g_qkv);
    cudaGetSymbolAddress((void**)&att,   g_att);
    cudaGetSymbolAddress((void**)&x1,    g_x1);
    cudaGetSymbolAddress((void**)&ffn,   g_ffn);
    cudaGetSymbolAddress((void**)&x2,    g_x2);
    cudaGetSymbolAddress((void**)&wqkvT, g_wqkvT);
    cudaGetSymbolAddress((void**)&woT,   g_woT);
    cudaGetSymbolAddress((void**)&w1T,   g_w1T);
    cudaGetSymbolAddress((void**)&w2T,   g_w2T);

    cudaFuncSetAttribute(attn_mma_kernel,
        cudaFuncAttributeMaxDynamicSharedMemorySize, ATTN_SMEM_BYTES);
    cudaFuncSetAttribute(tc_gemm<0, 256>,
        cudaFuncAttributeMaxDynamicSharedMemorySize, SMEM_G256);
    cudaFuncSetAttribute(tc_gemm<2, 256>,
        cudaFuncAttributeMaxDynamicSharedMemorySize, SMEM_G256);
    cudaFuncSetAttribute(tc_gemm<1, 128>,
        cudaFuncAttributeMaxDynamicSharedMemorySize, SMEM_G128);
    cudaFuncSetAttribute(tc_gemm<3, 128>,
        cudaFuncAttributeMaxDynamicSharedMemorySize, SMEM_G128);

    // 0. transpose + half-round weights to [N][K]
    transpose_kernel<<<dim3(2304 / 32,  768 / 32), 256>>>(w_qkv, wqkvT,  768, 2304);
    transpose_kernel<<<dim3( 768 / 32,  768 / 32), 256>>>(w_o,   woT,    768,  768);
    transpose_kernel<<<dim3(3072 / 32,  768 / 32), 256>>>(w1,    w1T,    768, 3072);
    transpose_kernel<<<dim3( 768 / 32, 3072 / 32), 256>>>(w2,    w2T,   3072,  768);

    // 1. h = half(LN1(x))
    ln_kernel<true><<<TOKENS, 256>>>(x, g1, be1, ln);
    // 2. qkv = half(h @ w_qkv)        (8192 x 2304, K=768)
    tc_gemm<0, 256><<<dim3(2304 / 256, TOKENS / 128), 256, SMEM_G256>>>(
        ln, wqkvT, qkv, TOKENS, 2304, 768, nullptr, nullptr);
    // 3. attention -> half, (B,H,N,DH) contiguous == (B,N,D) flat
    attn_mma_kernel<<<dim3(NSEQ / 128, 64), 256, ATTN_SMEM_BYTES>>>(qkv, att);
    // 4. x1 = att @ w_o + b_o + x     (8192 x 768, K=768), f32
    tc_gemm<1, 128><<<dim3(768 / 128, TOKENS / 128), 256, SMEM_G128>>>(
        att, woT, x1, TOKENS, 768, 768, b_o, x);
    // 5. h = half(LN2(x1))
    ln_kernel<true><<<TOKENS, 256>>>(x1, gm, bm, ln);
    // 6. ffn = half(gelu(h @ w1 + b1)) (8192 x 3072, K=768)
    tc_gemm<2, 256><<<dim3(3072 / 256, TOKENS / 128), 256, SMEM_G256>>>(
        ln, w1T, ffn, TOKENS, 3072, 768, b1, nullptr);
    // 7. x2 = gelu(ffn @ w2 + b2) + x1 (8192 x 768, K=3072), f32
    tc_gemm<3, 128><<<dim3(768 / 128, TOKENS / 128), 256, SMEM_G128>>>(
        ffn, w2T, x2, TOKENS, 768, 3072, b2, x1);
    // 8. out = LN3(x2)
    ln_kernel<false><<<TOKENS, 256>>>(x2, g3, be3, (float*)d_out);
}

// round 9
// speedup vs baseline: 7.3782x; 1.0810x over previous
#include <cuda_runtime.h>
#include <cuda_fp16.h>
#include <math.h>
#include <stdint.h>

// ---------------------------------------------------------------------------
// EncoderBlock: B=8, N=1024, D=768, H=8, DH=96
// Round 9: ldmatrix.x4 fragment loads everywhere (LDS instr / 4);
// transposes+LN1 fused into one launch; warp-per-row LN. fp16 MMA kept.
// ---------------------------------------------------------------------------

#define TOKENS 8192
#define DMODEL 768
#define NSEQ   1024
#define NHEAD  8
#define DHEAD  96
#define ATTN_SCALE 0.10206207261596577f   // 1/sqrt(96)

// ---------------- scratch ---------------------------------------------------
__device__ __half g_ln  [TOKENS * DMODEL];
__device__ __half g_qkv [TOKENS * 3 * DMODEL];
__device__ __half g_att [TOKENS * DMODEL];
__device__ float  g_x1  [TOKENS * DMODEL];
__device__ __half g_ffn [TOKENS * 4 * DMODEL];
__device__ float  g_x2  [TOKENS * DMODEL];
__device__ __half g_wqkvT[3 * DMODEL * DMODEL];
__device__ __half g_woT  [DMODEL * DMODEL];
__device__ __half g_w1T  [4 * DMODEL * DMODEL];
__device__ __half g_w2T  [DMODEL * 4 * DMODEL];

__device__ __forceinline__ uint32_t smem_u32(const void* p) {
    uint32_t a;
    asm("{ .reg .u64 t; cvta.to.shared.u64 t, %1; cvt.u32.u64 %0, t; }"
        : "=r"(a) : "l"(p));
    return a;
}
__device__ __forceinline__ uint32_t f2h2(float lo, float hi) {
    __half2 h = __floats2half2_rn(lo, hi);
    return *reinterpret_cast<uint32_t*>(&h);
}
__device__ __forceinline__ float gelu_f(float x) {
    return 0.5f * x * (1.0f + erff(x * 0.70710678118654752f));
}

#define MMA_F16(d, a, b) \
    asm volatile("mma.sync.aligned.m16n8k16.row.col.f32.f16.f16.f32 " \
      "{%0,%1,%2,%3}, {%4,%5,%6,%7}, {%8,%9}, {%0,%1,%2,%3};" \
      : "+f"((d)[0]), "+f"((d)[1]), "+f"((d)[2]), "+f"((d)[3]) \
      : "r"((a)[0]), "r"((a)[1]), "r"((a)[2]), "r"((a)[3]), \
        "r"((b)[0]), "r"((b)[1]))

#define LDSM_X4(r0, r1, r2, r3, addr) \
    asm volatile("ldmatrix.sync.aligned.m8n8.x4.shared.b16 {%0,%1,%2,%3}, [%4];" \
      : "=r"(r0), "=r"(r1), "=r"(r2), "=r"(r3) : "r"(addr))

#define CP_ASYNC16(dst, src) \
    asm volatile("cp.async.cg.shared.global [%0], [%1], 16;" \
                 :: "r"(dst), "l"(src))
#define CP_COMMIT() asm volatile("cp.async.commit_group;" ::: "memory")
#define CP_WAIT0()  asm volatile("cp.async.wait_group 0;" ::: "memory")
#define CP_WAIT1()  asm volatile("cp.async.wait_group 1;" ::: "memory")
#define CP_WAIT2()  asm volatile("cp.async.wait_group 2;" ::: "memory")

#define PAIR_BAR(id) \
    asm volatile("bar.sync %0, 64;" :: "r"(id) : "memory")

// ---------------------------------------------------------------------------
// Warp-per-row LayerNorm body (8 rows per 256-thread block, shfl-only)
// ---------------------------------------------------------------------------
template <bool HALF_OUT>
__device__ __forceinline__ void ln_row8(
    const float* __restrict__ x, const float* __restrict__ g,
    const float* __restrict__ b, void* __restrict__ o, int blk)
{
    const int wid = threadIdx.x >> 5, lane = threadIdx.x & 31;
    const int row = blk * 8 + wid;
    const float* xr = x + (size_t)row * DMODEL;

    float4 v[6];
    float s = 0.f, ss = 0.f;
    #pragma unroll
    for (int i = 0; i < 6; i++) {
        v[i] = *(const float4*)&xr[lane * 4 + i * 128];
        s  += v[i].x + v[i].y + v[i].z + v[i].w;
        ss += v[i].x * v[i].x + v[i].y * v[i].y
            + v[i].z * v[i].z + v[i].w * v[i].w;
    }
    #pragma unroll
    for (int o2 = 16; o2 > 0; o2 >>= 1) {
        s  += __shfl_xor_sync(0xffffffffu, s,  o2);
        ss += __shfl_xor_sync(0xffffffffu, ss, o2);
    }
    const float mean = s * (1.0f / DMODEL);
    const float var  = ss * (1.0f / DMODEL) - mean * mean;
    const float inv  = rsqrtf(var + 1e-5f);

    #pragma unroll
    for (int i = 0; i < 6; i++) {
        const int c = lane * 4 + i * 128;
        const float4 gg = *(const float4*)&g[c];
        const float4 bb = *(const float4*)&b[c];
        const float r0 = (v[i].x - mean) * inv * gg.x + bb.x;
        const float r1 = (v[i].y - mean) * inv * gg.y + bb.y;
        const float r2 = (v[i].z - mean) * inv * gg.z + bb.z;
        const float r3 = (v[i].w - mean) * inv * gg.w + bb.w;
        if (HALF_OUT) {
            uint2 u; u.x = f2h2(r0, r1); u.y = f2h2(r2, r3);
            *(uint2*)((__half*)o + (size_t)row * DMODEL + c) = u;
        } else {
            float4 ov; ov.x = r0; ov.y = r1; ov.z = r2; ov.w = r3;
            *(float4*)((float*)o + (size_t)row * DMODEL + c) = ov;
        }
    }
}

template <bool HALF_OUT>
__global__ __launch_bounds__(256) void ln_warp_kernel(
    const float* __restrict__ x, const float* __restrict__ g,
    const float* __restrict__ b, void* __restrict__ o)
{
    ln_row8<HALF_OUT>(x, g, b, o, blockIdx.x);
}

// ---------------------------------------------------------------------------
// prep_kernel: blocks [0,6912) transpose+round weights; [6912,7936) = LN1.
// Transposed weight layout: out[N][K] = half(in[K][N]).
// ---------------------------------------------------------------------------
__device__ __forceinline__ void transpose_tile(
    float (*t)[33], const float* __restrict__ in, __half* __restrict__ out,
    int R, int C, int bx, int by)
{
    const int tx = threadIdx.x & 31, ty4 = (threadIdx.x >> 5) * 4;
    #pragma unroll
    for (int i = 0; i < 4; i++)
        t[ty4 + i][tx] = in[(size_t)(by + ty4 + i) * C + bx + tx];
    __syncthreads();
    #pragma unroll
    for (int i = 0; i < 4; i++)
        out[(size_t)(bx + ty4 + i) * R + by + tx] = __float2half_rn(t[tx][ty4 + i]);
}

__global__ __launch_bounds__(256) void prep_kernel(
    const float* __restrict__ x, const float* __restrict__ g1,
    const float* __restrict__ be1, __half* __restrict__ ln,
    const float* __restrict__ w_qkv, const float* __restrict__ w_o,
    const float* __restrict__ w1, const float* __restrict__ w2,
    __half* __restrict__ wqkvT, __half* __restrict__ woT,
    __half* __restrict__ w1T, __half* __restrict__ w2T)
{
    __shared__ float t[32][33];
    const int bid = blockIdx.x;
    if (bid < 1728) {
        transpose_tile(t, w_qkv, wqkvT, 768, 2304, (bid % 72) * 32, (bid / 72) * 32);
    } else if (bid < 2304) {
        const int b2 = bid - 1728;
        transpose_tile(t, w_o, woT, 768, 768, (b2 % 24) * 32, (b2 / 24) * 32);
    } else if (bid < 4608) {
        const int b2 = bid - 2304;
        transpose_tile(t, w1, w1T, 768, 3072, (b2 % 96) * 32, (b2 / 96) * 32);
    } else if (bid < 6912) {
        const int b2 = bid - 4608;
        transpose_tile(t, w2, w2T, 3072, 768, (b2 % 24) * 32, (b2 / 24) * 32);
    } else {
        ln_row8<true>(x, g1, be1, ln, bid - 6912);
    }
}

// ---------------------------------------------------------------------------
// fp16 mma GEMM, cp.async pipelined, ldmatrix frags:
// C(MxN) = A(MxK) @ Bt(NxK)^T + epi. BM=128, 8 warps (2m x 4n), GBK=64.
//   BN=256: warp 64x64, 4-stage, 1 CTA/SM
//   BN=128: warp 64x32, 3-stage, 2 CTAs/SM
// MODE 0: half(AB) ; 1: f32 AB+bias+res ; 2: half(gelu(AB+bias)) ;
// MODE 3: f32 gelu(AB+bias)+res
// ---------------------------------------------------------------------------
#define GBK 64

template <int MODE, int BN>
__global__ __launch_bounds__(256, (BN == 128) ? 2 : 1) void tc_gemm(
    const __half* __restrict__ A, const __half* __restrict__ Bt,
    void* __restrict__ Cv, int M, int N, int K,
    const float* __restrict__ bias, const float* __restrict__ res)
{
    constexpr int NT     = BN / 32;
    constexpr int WNW    = BN / 4;
    constexpr int NSTG   = (BN == 128) ? 3 : 4;
    constexpr int STG_AW = 128 * 36;
    constexpr int STG_BW = BN * 36;
    constexpr int STG_W  = STG_AW + STG_BW;

    extern __shared__ uint32_t dynsm[];
    const uint32_t sb = smem_u32(dynsm);

    const int tid = threadIdx.x;
    const int wid = tid >> 5, lane = tid & 31;
    const int g = lane >> 2, t = lane & 3;
    const int wm = wid >> 2, wn = wid & 3;
    const int bn = blockIdx.x, bm = blockIdx.y;

    const __half* Ab = A  + (size_t)bm * 128 * K;
    const __half* Bb = Bt + (size_t)bn * BN * K;

    // ldmatrix per-lane base addresses (bytes)
    const uint32_t aBase = sb +
        (uint32_t)(((wm * 64 + (lane & 15)) * 36 + 4 * (lane >> 4)) * 4);
    const uint32_t bBase = sb + (uint32_t)(STG_AW * 4) +
        (uint32_t)(((wn * WNW + (lane & 7) + 8 * (lane >> 4)) * 36
                    + 4 * ((lane >> 3) & 1)) * 4);

    float acc[4][NT][4];
    #pragma unroll
    for (int mt = 0; mt < 4; mt++)
        #pragma unroll
        for (int nt = 0; nt < NT; nt++)
            #pragma unroll
            for (int q = 0; q < 4; q++) acc[mt][nt][q] = 0.f;

    const int nch = K / GBK;

    auto fill = [&](int s, int c) {
        const uint32_t base = sb + (uint32_t)(s * STG_W) * 4;
        const int k0 = c * GBK;
        #pragma unroll
        for (int i = 0; i < 4; i++) {
            const int idx = tid + i * 256;
            const int r = idx >> 3, gr = idx & 7;
            CP_ASYNC16(base + (uint32_t)(r * 36 + gr * 4) * 4,
                       Ab + (size_t)r * K + k0 + gr * 8);
        }
        #pragma unroll
        for (int i = 0; i < BN / 32; i++) {
            const int idx = tid + i * 256;
            const int r = idx >> 3, gr = idx & 7;
            CP_ASYNC16(base + (uint32_t)(STG_AW + r * 36 + gr * 4) * 4,
                       Bb + (size_t)r * K + k0 + gr * 8);
        }
        CP_COMMIT();
    };

    #pragma unroll
    for (int i = 0; i < NSTG - 1; i++) fill(i, i);

    int st = 0;
    for (int ch = 0; ch < nch; ch++) {
        const int pend = (ch + NSTG - 1 < nch) ? (NSTG - 2) : (nch - 1 - ch);
        if (pend <= 0) { CP_WAIT0(); }
        else if (pend == 1) { CP_WAIT1(); }
        else { CP_WAIT2(); }
        __syncthreads();
        if (ch + NSTG - 1 < nch)
            fill((st + NSTG - 1) % NSTG, ch + NSTG - 1);

        const uint32_t stOff = (uint32_t)(st * STG_W) * 4;

        #pragma unroll
        for (int ks = 0; ks < 4; ks++) {
            uint32_t af[4][4];
            #pragma unroll
            for (int mt = 0; mt < 4; mt++)
                LDSM_X4(af[mt][0], af[mt][1], af[mt][2], af[mt][3],
                        aBase + stOff + (uint32_t)(mt * 2304 + ks * 32));
            uint32_t bf[NT][2];
            #pragma unroll
            for (int p = 0; p < NT / 2; p++)
                LDSM_X4(bf[2 * p][0], bf[2 * p][1], bf[2 * p + 1][0], bf[2 * p + 1][1],
                        bBase + stOff + (uint32_t)(p * 2304 + ks * 32));
            #pragma unroll
            for (int mt = 0; mt < 4; mt++)
                #pragma unroll
                for (int nt = 0; nt < NT; nt++)
                    MMA_F16(acc[mt][nt], af[mt], bf[nt]);
        }
        st = (st + 1 == NSTG) ? 0 : st + 1;
    }

    // ---- epilogue ----
    __half* Ch = (__half*)Cv;
    float*  Cf = (float*)Cv;
    #pragma unroll
    for (int mt = 0; mt < 4; mt++) {
        const int row = bm * 128 + wm * 64 + mt * 16 + g;
        #pragma unroll
        for (int nt = 0; nt < NT; nt++) {
            const int col = bn * BN + wn * WNW + nt * 8 + 2 * t;
            float v0 = acc[mt][nt][0], v1 = acc[mt][nt][1];
            float v2 = acc[mt][nt][2], v3 = acc[mt][nt][3];
            if (MODE >= 1) {
                const float2 bb = *(const float2*)&bias[col];
                v0 += bb.x; v1 += bb.y; v2 += bb.x; v3 += bb.y;
            }
            if (MODE >= 2) {
                v0 = gelu_f(v0); v1 = gelu_f(v1);
                v2 = gelu_f(v2); v3 = gelu_f(v3);
            }
            const size_t r0 = (size_t)row * N + col;
            const size_t r1 = (size_t)(row + 8) * N + col;
            if (MODE == 0 || MODE == 2) {
                *(uint32_t*)&Ch[r0] = f2h2(v0, v1);
                *(uint32_t*)&Ch[r1] = f2h2(v2, v3);
            } else {
                const float2 ra = *(const float2*)&res[r0];
                const float2 rb2 = *(const float2*)&res[r1];
                v0 += ra.x; v1 += ra.y; v2 += rb2.x; v3 += rb2.y;
                float2 o0; o0.x = v0; o0.y = v1;
                float2 o1; o1.x = v2; o1.y = v3;
                *(float2*)&Cf[r0] = o0;
                *(float2*)&Cf[r1] = o1;
            }
        }
    }
}

// ---------------------------------------------------------------------------
// Attention, fp16 mma + ldmatrix. CTA: 128 q x 64 kv, 256 thr, 4m x 2n,
// 2 CTAs/SM. sQ/sK stride 52 words, sVt/sP stride 36 words (conflict-free).
// Double-buffered K (cp.async) + Vt (register prefetch); pair barriers.
// Output half, contiguous (B,H,N,DH) == faithful reshape (B,N,D).
// ---------------------------------------------------------------------------
#define SQW   0
#define SKW   (128 * 52)
#define SKT_W (64 * 52)
#define SVW   (SKW + 2 * SKT_W)
#define SVT_W (96 * 36)
#define SPW   (SVW + 2 * SVT_W)
#define RMXW  (SPW + 128 * 36)
#define RSMW  (RMXW + 256)
#define ATTN_SMEM_BYTES ((RSMW + 256) * 4)   // 101376 B

__global__ __launch_bounds__(256, 2) void attn_mma_kernel(
    const __half* __restrict__ qkv, __half* __restrict__ out)
{
    extern __shared__ uint32_t dynsm[];
    uint32_t* sQw = dynsm + SQW;
    uint32_t* sPw = dynsm + SPW;
    float* sRmx = (float*)(dynsm + RMXW);
    float* sRsm = (float*)(dynsm + RSMW);
    const uint32_t sb = smem_u32(dynsm);

    const int tid = threadIdx.x, lane = tid & 31, wid = tid >> 5;
    const int g = lane >> 2, t = lane & 3;
    const int wm = wid & 3, wn = wid >> 2;
    const int barid = 1 + wm;
    const int bh = blockIdx.y, b = bh >> 3, h = bh & 7;
    const int q0 = blockIdx.x * 128;

    const __half* gQ = qkv + (size_t)b * NSEQ * (3 * DMODEL) + h * DHEAD;
    const __half* gK = gQ + DMODEL;
    const __half* gV = gQ + 2 * DMODEL;

    const int kvv = tid & 63, dpart = tid >> 6;

    // ldmatrix per-lane bases (bytes)
    const uint32_t qBase = sb +
        (uint32_t)(((wm * 32 + (lane & 15)) * 52 + 4 * (lane >> 4)) * 4);
    const uint32_t kBase0 = sb + (uint32_t)(SKW * 4) +
        (uint32_t)(((wn * 32 + (lane & 7) + 8 * (lane >> 4)) * 52
                    + 4 * ((lane >> 3) & 1)) * 4);
    const uint32_t pBase = sb + (uint32_t)(SPW * 4) +
        (uint32_t)(((wm * 32 + (lane & 15)) * 36 + 4 * (lane >> 4)) * 4);
    const uint32_t vBase0 = sb + (uint32_t)(SVW * 4) +
        (uint32_t)(((wn * 48 + (lane & 7) + 8 * (lane >> 4)) * 36
                    + 4 * ((lane >> 3) & 1)) * 4);

    auto fillK = [&](int buf, int kt) {
        const uint32_t base = sb + (uint32_t)(SKW + buf * SKT_W) * 4;
        #pragma unroll
        for (int i = 0; i < 3; i++) {
            const int idx = tid + i * 256;
            const int r = idx / 12, gr = idx % 12;
            CP_ASYNC16(base + (uint32_t)(r * 52 + gr * 4) * 4,
                       gK + (size_t)(kt + r) * (3 * DMODEL) + gr * 8);
        }
        CP_COMMIT();
    };
    auto storeV = [&](int buf, const float4* raw) {
        __half* sVh = (__half*)(dynsm + SVW + buf * SVT_W);
        #pragma unroll
        for (int j = 0; j < 3; j++) {
            const int d8 = dpart * 3 + j;
            const __half* hh = (const __half*)&raw[j];
            #pragma unroll
            for (int e = 0; e < 8; e++)
                sVh[(d8 * 8 + e) * 72 + kvv] = hh[e];
        }
    };

    // ---- prologue ----
    fillK(0, 0);
    {
        float4 raw[3];
        #pragma unroll
        for (int j = 0; j < 3; j++) {
            const int d8 = dpart * 3 + j;
            raw[j] = *(const float4*)&gV[(size_t)kvv * (3 * DMODEL) + d8 * 8];
        }
        storeV(0, raw);
    }
    #pragma unroll
    for (int i = 0; i < 6; i++) {
        const int idx = tid + i * 256;
        const int r = idx / 12, gr = idx % 12;
        float4 raw = *(const float4*)&gQ[(size_t)(q0 + r) * (3 * DMODEL) + gr * 8];
        const __half2* hp = (const __half2*)&raw;
        #pragma unroll
        for (int e = 0; e < 4; e++) {
            float2 f = __half22float2(hp[e]);
            sQw[r * 52 + gr * 4 + e] = f2h2(f.x * ATTN_SCALE, f.y * ATTN_SCALE);
        }
    }
    CP_WAIT0();
    __syncthreads();

    const int rows[4] = {wm * 32 + g, wm * 32 + g + 8,
                         wm * 32 + 16 + g, wm * 32 + 24 + g};

    float m_r[4] = {-1e30f, -1e30f, -1e30f, -1e30f};
    float l_r[4] = {0.f, 0.f, 0.f, 0.f};

    float o[2][6][4];
    #pragma unroll
    for (int mt = 0; mt < 2; mt++)
        #pragma unroll
        for (int nt = 0; nt < 6; nt++)
            #pragma unroll
            for (int q = 0; q < 4; q++) o[mt][nt][q] = 0.f;

    const int NTILE = NSEQ / 64;
    for (int it = 0; it < NTILE; it++) {
        const int cur = it & 1, alt = cur ^ 1;
        const bool pre = (it + 1 < NTILE);

        float4 vreg[3];
        if (pre) {
            const int ktn = (it + 1) * 64;
            fillK(alt, ktn);
            #pragma unroll
            for (int j = 0; j < 3; j++) {
                const int d8 = dpart * 3 + j;
                vreg[j] = *(const float4*)
                    &gV[(size_t)(ktn + kvv) * (3 * DMODEL) + d8 * 8];
            }
        }

        // ---- S = Q K^T (6 k16 steps) ----
        const uint32_t kB = kBase0 + (uint32_t)(cur * SKT_W) * 4;
        float sacc[2][4][4];
        #pragma unroll
        for (int mt = 0; mt < 2; mt++)
            #pragma unroll
            for (int nt = 0; nt < 4; nt++)
                #pragma unroll
                for (int q = 0; q < 4; q++) sacc[mt][nt][q] = 0.f;

        #pragma unroll
        for (int ks = 0; ks < 6; ks++) {
            uint32_t af[2][4];
            #pragma unroll
            for (int mt = 0; mt < 2; mt++)
                LDSM_X4(af[mt][0], af[mt][1], af[mt][2], af[mt][3],
                        qBase + (uint32_t)(mt * 3328 + ks * 32));
            uint32_t bf[4][2];
            #pragma unroll
            for (int p = 0; p < 2; p++)
                LDSM_X4(bf[2 * p][0], bf[2 * p][1], bf[2 * p + 1][0], bf[2 * p + 1][1],
                        kB + (uint32_t)(p * 3328 + ks * 32));
            #pragma unroll
            for (int mt = 0; mt < 2; mt++)
                #pragma unroll
                for (int nt = 0; nt < 4; nt++)
                    MMA_F16(sacc[mt][nt], af[mt], bf[nt]);
        }

        // ---- softmax: pair-scoped combine ----
        float rmax[4];
        #pragma unroll
        for (int mt = 0; mt < 2; mt++) {
            float m0 = sacc[mt][0][0], m1 = sacc[mt][0][2];
            #pragma unroll
            for (int nt = 0; nt < 4; nt++) {
                m0 = fmaxf(m0, fmaxf(sacc[mt][nt][0], sacc[mt][nt][1]));
                m1 = fmaxf(m1, fmaxf(sacc[mt][nt][2], sacc[mt][nt][3]));
            }
            rmax[mt * 2] = m0; rmax[mt * 2 + 1] = m1;
        }
        #pragma unroll
        for (int q = 0; q < 4; q++) {
            rmax[q] = fmaxf(rmax[q], __shfl_xor_sync(0xffffffffu, rmax[q], 1));
            rmax[q] = fmaxf(rmax[q], __shfl_xor_sync(0xffffffffu, rmax[q], 2));
        }
        if (t == 0) {
            #pragma unroll
            for (int q = 0; q < 4; q++) sRmx[rows[q] * 2 + wn] = rmax[q];
        }
        PAIR_BAR(barid);

        float mnew[4], corr[4];
        #pragma unroll
        for (int q = 0; q < 4; q++) {
            const float tmx = fmaxf(sRmx[rows[q] * 2], sRmx[rows[q] * 2 + 1]);
            mnew[q] = fmaxf(m_r[q], tmx);
            corr[q] = __expf(m_r[q] - mnew[q]);
        }
        float psum[4] = {0.f, 0.f, 0.f, 0.f};
        #pragma unroll
        for (int mt = 0; mt < 2; mt++) {
            #pragma unroll
            for (int nt = 0; nt < 4; nt++) {
                const float p0 = __expf(sacc[mt][nt][0] - mnew[mt * 2]);
                const float p1 = __expf(sacc[mt][nt][1] - mnew[mt * 2]);
                const float p2 = __expf(sacc[mt][nt][2] - mnew[mt * 2 + 1]);
                const float p3 = __expf(sacc[mt][nt][3] - mnew[mt * 2 + 1]);
                psum[mt * 2] += p0 + p1;
                psum[mt * 2 + 1] += p2 + p3;
                const int cw = wn * 16 + nt * 4 + t;
                sPw[(wm * 32 + mt * 16 + g) * 36 + cw] = f2h2(p0, p1);
                sPw[(wm * 32 + mt * 16 + g + 8) * 36 + cw] = f2h2(p2, p3);
            }
        }
        #pragma unroll
        for (int q = 0; q < 4; q++) {
            psum[q] += __shfl_xor_sync(0xffffffffu, psum[q], 1);
            psum[q] += __shfl_xor_sync(0xffffffffu, psum[q], 2);
        }
        if (t == 0) {
            #pragma unroll
            for (int q = 0; q < 4; q++) sRsm[rows[q] * 2 + wn] = psum[q];
        }
        PAIR_BAR(barid);

        #pragma unroll
        for (int q = 0; q < 4; q++) {
            l_r[q] = l_r[q] * corr[q] + sRsm[rows[q] * 2] + sRsm[rows[q] * 2 + 1];
            m_r[q] = mnew[q];
        }

        // ---- O = O*corr + P V (4 k16 steps) ----
        #pragma unroll
        for (int mt = 0; mt < 2; mt++)
            #pragma unroll
            for (int nt = 0; nt < 6; nt++) {
                o[mt][nt][0] *= corr[mt * 2];     o[mt][nt][1] *= corr[mt * 2];
                o[mt][nt][2] *= corr[mt * 2 + 1]; o[mt][nt][3] *= corr[mt * 2 + 1];
            }
        const uint32_t vB = vBase0 + (uint32_t)(cur * SVT_W) * 4;
        #pragma unroll
        for (int ks = 0; ks < 4; ks++) {
            uint32_t af[2][4];
            #pragma unroll
            for (int mt = 0; mt < 2; mt++)
                LDSM_X4(af[mt][0], af[mt][1], af[mt][2], af[mt][3],
                        pBase + (uint32_t)(mt * 2304 + ks * 32));
            uint32_t bf[6][2];
            #pragma unroll
            for (int p = 0; p < 3; p++)
                LDSM_X4(bf[2 * p][0], bf[2 * p][1], bf[2 * p + 1][0], bf[2 * p + 1][1],
                        vB + (uint32_t)(p * 2304 + ks * 32));
            #pragma unroll
            for (int mt = 0; mt < 2; mt++)
                #pragma unroll
                for (int nt = 0; nt < 6; nt++)
                    MMA_F16(o[mt][nt], af[mt], bf[nt]);
        }

        if (pre) {
            storeV(alt, vreg);
            CP_WAIT0();
        }
        __syncthreads();
    }

    // ---- epilogue ----
    float invl[4];
    #pragma unroll
    for (int q = 0; q < 4; q++) invl[q] = 1.0f / l_r[q];

    __half* gO = out + ((size_t)bh * NSEQ + q0) * DHEAD;
    #pragma unroll
    for (int mt = 0; mt < 2; mt++) {
        const int rlo = wm * 32 + mt * 16 + g;
        const int rhi = rlo + 8;
        #pragma unroll
        for (int nt = 0; nt < 6; nt++) {
            const int col = wn * 48 + nt * 8 + 2 * t;
            *(uint32_t*)&gO[(size_t)rlo * DHEAD + col] =
                f2h2(o[mt][nt][0] * invl[mt * 2], o[mt][nt][1] * invl[mt * 2]);
            *(uint32_t*)&gO[(size_t)rhi * DHEAD + col] =
                f2h2(o[mt][nt][2] * invl[mt * 2 + 1], o[mt][nt][3] * invl[mt * 2 + 1]);
        }
    }
}

// ---------------------------------------------------------------------------
// Launcher
// ---------------------------------------------------------------------------
#define SMEM_G256 (4 * (128 + 256) * 36 * 4)   // 221184
#define SMEM_G128 (3 * (128 + 128) * 36 * 4)   // 110592

extern "C" void kernel_launch(void* const* d_in, const int* in_sizes, int n_in,
                              void* d_out, int out_size)
{
    (void)in_sizes; (void)n_in; (void)out_size;
    const float* x     = (const float*)d_in[0];
    const float* w_qkv = (const float*)d_in[1];
    const float* w_o   = (const float*)d_in[2];
    const float* b_o   = (const float*)d_in[3];
    const float* w1    = (const float*)d_in[4];
    const float* b1    = (const float*)d_in[5];
    const float* w2    = (const float*)d_in[6];
    const float* b2    = (const float*)d_in[7];
    const float* g1    = (const float*)d_in[8];
    const float* be1   = (const float*)d_in[9];
    const float* gm    = (const float*)d_in[10];
    const float* bm    = (const float*)d_in[11];
    const float* g3    = (const float*)d_in[12];
    const float* be3   = (const float*)d_in[13];

    __half *ln, *qkv, *att, *ffn, *wqkvT, *woT, *w1T, *w2T;
    float *x1, *x2;
    cudaGetSymbolAddress((void**)&ln,    g_ln);
    cudaGetSymbolAddress((void**)&qkv,   g_qkv);
    cudaGetSymbolAddress((void**)&att,   g_att);
    cudaGetSymbolAddress((void**)&x1,    g_x1);
    cudaGetSymbolAddress((void**)&ffn,   g_ffn);
    cudaGetSymbolAddress((void**)&x2,    g_x2);
    cudaGetSymbolAddress((void**)&wqkvT, g_wqkvT);
    cudaGetSymbolAddress((void**)&woT,   g_woT);
    cudaGetSymbolAddress((void**)&w1T,   g_w1T);
    cudaGetSymbolAddress((void**)&w2T,   g_w2T);

    cudaFuncSetAttribute(attn_mma_kernel,
        cudaFuncAttributeMaxDynamicSharedMemorySize, ATTN_SMEM_BYTES);
    cudaFuncSetAttribute(tc_gemm<0, 256>,
        cudaFuncAttributeMaxDynamicSharedMemorySize, SMEM_G256);
    cudaFuncSetAttribute(tc_gemm<2, 256>,
        cudaFuncAttributeMaxDynamicSharedMemorySize, SMEM_G256);
    cudaFuncSetAttribute(tc_gemm<1, 128>,
        cudaFuncAttributeMaxDynamicSharedMemorySize, SMEM_G128);
    cudaFuncSetAttribute(tc_gemm<3, 128>,
        cudaFuncAttributeMaxDynamicSharedMemorySize, SMEM_G128);

    // 0+1. transposes + LN1 fused (independent work, one launch)
    prep_kernel<<<6912 + 1024, 256>>>(x, g1, be1, ln,
                                      w_qkv, w_o, w1, w2,
                                      wqkvT, woT, w1T, w2T);
    // 2. qkv = half(h @ w_qkv)        (8192 x 2304, K=768)
    tc_gemm<0, 256><<<dim3(2304 / 256, TOKENS / 128), 256, SMEM_G256>>>(
        ln, wqkvT, qkv, TOKENS, 2304, 768, nullptr, nullptr);
    // 3. attention -> half, (B,H,N,DH) contiguous == (B,N,D) flat
    attn_mma_kernel<<<dim3(NSEQ / 128, 64), 256, ATTN_SMEM_BYTES>>>(qkv, att);
    // 4. x1 = att @ w_o + b_o + x     (8192 x 768, K=768), f32
    tc_gemm<1, 128><<<dim3(768 / 128, TOKENS / 128), 256, SMEM_G128>>>(
        att, woT, x1, TOKENS, 768, 768, b_o, x);
    // 5. h = half(LN2(x1))
    ln_warp_kernel<true><<<TOKENS / 8, 256>>>(x1, gm, bm, ln);
    // 6. ffn = half(gelu(h @ w1 + b1)) (8192 x 3072, K=768)
    tc_gemm<2, 256><<<dim3(3072 / 256, TOKENS / 128), 256, SMEM_G256>>>(
        ln, w1T, ffn, TOKENS, 3072, 768, b1, nullptr);
    // 7. x2 = gelu(ffn @ w2 + b2) + x1 (8192 x 768, K=3072), f32
    tc_gemm<3, 128><<<dim3(768 / 128, TOKENS / 128), 256, SMEM_G128>>>(
        ffn, w2T, x2, TOKENS, 768, 3072, b2, x1);
    // 8. out = LN3(x2)
    ln_warp_kernel<false><<<TOKENS / 8, 256>>>(x2, g3, be3, (float*)d_out);
}